// round 6
// baseline (speedup 1.0000x reference)
#include <cuda_runtime.h>
#include <cuda_bf16.h>
#include <math.h>

#define BB   64
#define TL   383
#define SL   384
#define DL   896
#define HG   400
#define HEH  256
#define TAGL 128
#define MST  20
#define MR   (BB*SL)    // 24576
#define NPRE 896        // padded 2*HG

// ---------------- scratch (device globals) ----------------
__device__ float g_X[(size_t)MR*DL];
__device__ float g_Mf[MR];
__device__ float g_Pre[(size_t)MR*NPRE];
__device__ float g_GS[(size_t)MR*2*HG];
__device__ float g_H[2*2*BB*HG];
__device__ float g_Ap[MR*MST];
__device__ float g_WihFBT[NPRE*NPRE];
__device__ float g_Wg2eT[2*HG*HEH];
__device__ float g_WhheT[HEH*HEH];
__device__ float g_WtagT[2*HG*2*TAGL];
__device__ float g_biasFB[NPRE];
__device__ float g_biasE[HEH];
__device__ float g_biasTag[2*TAGL];

#define CLUSTER_SYNC_() do { \
    asm volatile("barrier.cluster.arrive.aligned;" ::: "memory"); \
    asm volatile("barrier.cluster.wait.aligned;" ::: "memory"); \
} while (0)

// ---------------- fused setup: weight prep + input build in ONE kernel ----------------
#define T1 (NPRE*NPRE)
#define T2 (2*HG*HEH)
#define T3 (HEH*HEH)
#define T4 (2*HG*2*TAGL)
#define T5 (NPRE)
#define T6 (HEH)
#define T7 (2*TAGL)
#define TPREP (T1+T2+T3+T4+T5+T6+T7)
#define TBUILD ((size_t)MR*DL + MR)
#define TSETUP (TPREP + TBUILD)

__global__ void k_setup(const float* __restrict__ Wih_f, const float* __restrict__ Wih_b,
                        const float* __restrict__ Wg2e, const float* __restrict__ Whh_e,
                        const float* __restrict__ Wht,  const float* __restrict__ Wdt,
                        const float* __restrict__ bih_f, const float* __restrict__ bhh_f,
                        const float* __restrict__ bih_b, const float* __restrict__ bhh_b,
                        const float* __restrict__ bih_e, const float* __restrict__ bhh_e,
                        const float* __restrict__ bht,   const float* __restrict__ bdt,
                        const float* __restrict__ inp, const float* __restrict__ tag,
                        const float* __restrict__ sent, const int* __restrict__ mask) {
    size_t gidx = (size_t)blockIdx.x * blockDim.x + threadIdx.x;
    if (gidx < TPREP) {
        int idx = (int)gidx;
        if (idx < T1) {
            int k = idx / NPRE, n = idx % NPRE;
            float v = 0.f;
            if (k < DL) {
                if (n < HG)          v = Wih_f[(size_t)n * DL + k];
                else if (n < 2*HG)   v = Wih_b[(size_t)(n - HG) * DL + k];
            }
            g_WihFBT[idx] = v; return;
        }
        idx -= T1;
        if (idx < T2) { int k = idx / HEH, n = idx % HEH; g_Wg2eT[idx] = Wg2e[(size_t)n * (2*HG) + k]; return; }
        idx -= T2;
        if (idx < T3) { int k = idx / HEH, n = idx % HEH; g_WhheT[idx] = Whh_e[(size_t)n * HEH + k]; return; }
        idx -= T3;
        if (idx < T4) {
            int k = idx / (2*TAGL), n = idx % (2*TAGL);
            g_WtagT[idx] = (n < TAGL) ? Wht[(size_t)n * (2*HG) + k] : Wdt[(size_t)(n - TAGL) * (2*HG) + k];
            return;
        }
        idx -= T4;
        if (idx < T5) {
            float v = 0.f;
            if (idx < HG) v = bih_f[idx] + bhh_f[idx];
            else if (idx < 2*HG) v = bih_b[idx-HG] + bhh_b[idx-HG];
            g_biasFB[idx] = v; return;
        }
        idx -= T5;
        if (idx < T6) { g_biasE[idx] = bih_e[idx] + bhh_e[idx]; return; }
        idx -= T6;
        g_biasTag[idx] = (idx < TAGL) ? bht[idx] : bdt[idx - TAGL];
        return;
    }
    gidx -= TPREP;
    size_t nx = (size_t)MR * DL;
    if (gidx < nx) {
        int d = (int)(gidx % DL);
        int m = (int)(gidx / DL);
        int b = m / SL, s = m % SL;
        float v;
        if (s == 0) v = sent[d];
        else {
            int t = s - 1;
            v = (d < 768) ? inp[(size_t)(b * TL + t) * 768 + d]
                          : tag[(size_t)(b * TL + t) * TAGL + (d - 768)];
        }
        g_X[gidx] = v;
        return;
    }
    gidx -= nx;
    if (gidx < MR) {
        int b = (int)(gidx / SL), s = (int)(gidx % SL);
        g_Mf[gidx] = (s == 0) ? 1.0f : (float)mask[b * TL + s - 1];
    }
}

// ---------------- 128x128 double-buffered SGEMM (Pre + tags) ----------------
template <int ACT>
__global__ __launch_bounds__(256) void k_gemm128(const float* __restrict__ A,
                                                 const float* __restrict__ Bt,
                                                 const float* __restrict__ bias,
                                                 float* __restrict__ C,
                                                 float* __restrict__ C2,
                                                 int N, int K) {
    __shared__ __align__(16) float As[2][8][132];
    __shared__ __align__(16) float Bs[2][8][132];
    int m0 = blockIdx.y * 128, n0 = blockIdx.x * 128;
    int tid = threadIdx.x;
    int tx = tid & 15, ty = tid >> 4;

    int arow = tid >> 1, akq = (tid & 1) * 4;
    const float* Ap = A + (size_t)(m0 + arow) * K + akq;
    int bkr = tid >> 5, bnq = (tid & 31) * 4;
    const float* Bp = Bt + (size_t)bkr * N + n0 + bnq;

    float acc[8][8];
#pragma unroll
    for (int i = 0; i < 8; i++)
#pragma unroll
        for (int j = 0; j < 8; j++) acc[i][j] = 0.f;

    float4 av = *(const float4*)Ap;
    float4 bv = *(const float4*)Bp;
    As[0][akq + 0][arow] = av.x;
    As[0][akq + 1][arow] = av.y;
    As[0][akq + 2][arow] = av.z;
    As[0][akq + 3][arow] = av.w;
    *(float4*)&Bs[0][bkr][bnq] = bv;
    __syncthreads();

    int nk = K >> 3;
    for (int kt = 0; kt < nk; kt++) {
        int buf = kt & 1;
        if (kt + 1 < nk) {
            av = *(const float4*)(Ap + (kt + 1) * 8);
            bv = *(const float4*)(Bp + (size_t)(kt + 1) * 8 * N);
        }
#pragma unroll
        for (int kk = 0; kk < 8; kk++) {
            float a[8], b[8];
            *(float4*)(a)     = *(const float4*)&As[buf][kk][ty * 8];
            *(float4*)(a + 4) = *(const float4*)&As[buf][kk][ty * 8 + 4];
            *(float4*)(b)     = *(const float4*)&Bs[buf][kk][tx * 8];
            *(float4*)(b + 4) = *(const float4*)&Bs[buf][kk][tx * 8 + 4];
#pragma unroll
            for (int i = 0; i < 8; i++)
#pragma unroll
                for (int j = 0; j < 8; j++) acc[i][j] += a[i] * b[j];
        }
        if (kt + 1 < nk) {
            int nb = buf ^ 1;
            As[nb][akq + 0][arow] = av.x;
            As[nb][akq + 1][arow] = av.y;
            As[nb][akq + 2][arow] = av.z;
            As[nb][akq + 3][arow] = av.w;
            *(float4*)&Bs[nb][bkr][bnq] = bv;
        }
        __syncthreads();
    }

    float bj[8];
#pragma unroll
    for (int j = 0; j < 8; j++) bj[j] = bias[n0 + tx * 8 + j];

    if (ACT == 0) {
#pragma unroll
        for (int i = 0; i < 8; i++) {
            int row = m0 + ty * 8 + i;
            float v[8];
#pragma unroll
            for (int j = 0; j < 8; j++) v[j] = acc[i][j] + bj[j];
            *(float4*)(C + (size_t)row * N + n0 + tx * 8)     = *(float4*)(v);
            *(float4*)(C + (size_t)row * N + n0 + tx * 8 + 4) = *(float4*)(v + 4);
        }
    } else {
        float* dst = (blockIdx.x == 0) ? C : C2;
#pragma unroll
        for (int i = 0; i < 8; i++) {
            int row = m0 + ty * 8 + i;
            float v[8];
#pragma unroll
            for (int j = 0; j < 8; j++) {
                float x = acc[i][j] + bj[j];
                v[j] = (x > 0.f) ? x : expm1f(x);
            }
            *(float4*)(dst + (size_t)row * TAGL + tx * 8)     = *(float4*)(v);
            *(float4*)(dst + (size_t)row * TAGL + tx * 8 + 4) = *(float4*)(v + 4);
        }
    }
}

// ---------------- persistent bidirectional masked RNN (cluster-synced) ----------------
__global__ void __cluster_dims__(8, 1, 1) __launch_bounds__(256, 1)
k_rnn(const float* __restrict__ WhhF, const float* __restrict__ WhhB) {
    int bx = blockIdx.x;
    int dir = bx >> 6;
    int bid = bx & 63;
    int bg = bid >> 3;
    int jg = bid & 7;
    const float* Whh = dir ? WhhB : WhhF;
    int jbase = jg * 50, b0 = bg * 8;
    int tid = threadIdx.x;
    int jl = tid >> 3, kp = tid & 7;
    bool jact = (jl < 25);
    int j0 = jbase + jl * 2;
    int preoff = dir * HG;

    float w0[50], w1[50];
    if (jact) {
#pragma unroll
        for (int i = 0; i < 50; i++) {
            w0[i] = Whh[(size_t)j0 * HG + kp * 50 + i];
            w1[i] = Whh[(size_t)(j0 + 1) * HG + kp * 50 + i];
        }
    }
    float* Hp0 = g_H + dir * 2 * BB * HG;
    float* Hp1 = Hp0 + BB * HG;
    for (int idx = tid; idx < 400; idx += 256) {
        int bl = idx / 50, jj = idx % 50;
        __stcg(&Hp0[(b0 + bl) * HG + jbase + jj], 0.f);
        __stcg(&Hp1[(b0 + bl) * HG + jbase + jj], 0.f);
    }
    CLUSTER_SYNC_();

    __shared__ __align__(16) float Hs[8 * HG];

    for (int tv = 0; tv < SL; tv++) {
        int t = dir ? (SL - 1 - tv) : tv;
        float* Hcur = (tv & 1) ? Hp1 : Hp0;
        float* Hnxt = (tv & 1) ? Hp0 : Hp1;
        for (int idx = tid; idx < 8 * HG; idx += 256)
            Hs[idx] = __ldcg(&Hcur[(b0 + (idx / HG)) * HG + (idx % HG)]);
        __syncthreads();

        float s0v[8], s1v[8];
        if (jact) {
#pragma unroll
            for (int bl = 0; bl < 8; bl++) {
                const float2* hv = (const float2*)(Hs + bl * HG + kp * 50);
                float a0 = 0.f, a1 = 0.f, c0 = 0.f, c1 = 0.f;
#pragma unroll
                for (int i = 0; i < 25; i++) {
                    float2 h = hv[i];
                    a0 += w0[2 * i] * h.x;  c0 += w0[2 * i + 1] * h.y;
                    a1 += w1[2 * i] * h.x;  c1 += w1[2 * i + 1] * h.y;
                }
                s0v[bl] = a0 + c0;
                s1v[bl] = a1 + c1;
            }
        } else {
#pragma unroll
            for (int bl = 0; bl < 8; bl++) { s0v[bl] = 0.f; s1v[bl] = 0.f; }
        }
#pragma unroll
        for (int bl = 0; bl < 8; bl++) {
            float s0 = s0v[bl], s1 = s1v[bl];
            s0 += __shfl_xor_sync(0xffffffffu, s0, 1);
            s0 += __shfl_xor_sync(0xffffffffu, s0, 2);
            s0 += __shfl_xor_sync(0xffffffffu, s0, 4);
            s1 += __shfl_xor_sync(0xffffffffu, s1, 1);
            s1 += __shfl_xor_sync(0xffffffffu, s1, 2);
            s1 += __shfl_xor_sync(0xffffffffu, s1, 4);
            if (jact && kp == 0) {
                int b = b0 + bl;
                int mrow = b * SL + t;
                float mt = g_Mf[mrow];
                float om = 1.f - mt;
                size_t pbase = (size_t)mrow * NPRE + preoff;
                float h00 = Hs[bl * HG + j0];
                float h01 = Hs[bl * HG + j0 + 1];
                float hn0 = tanhf(g_Pre[pbase + j0] + s0);
                float hn1 = tanhf(g_Pre[pbase + j0 + 1] + s1);
                float u0 = mt * hn0 + om * h00;
                float u1 = mt * hn1 + om * h01;
                __stcg(&Hnxt[b * HG + j0], u0);
                __stcg(&Hnxt[b * HG + j0 + 1], u1);
                size_t gbase = (size_t)mrow * (2 * HG) + dir * HG;
                g_GS[gbase + j0] = u0 * mt;
                g_GS[gbase + j0 + 1] = u1 * mt;
            }
        }
        CLUSTER_SYNC_();
    }
}

// ---------------- persistent proj + 20-step estep loop ----------------
// One CTA owns 64 rows for the WHOLE chain. Phase 1: As = GS@Wg2eT + bg2e.
// Phase 2: 20x { acc = As@WhheT; hn = tanh(acc + be + xe*wie) -> As; logit -> Ap }.
// xe chains through warp registers (each warp owns 8 whole rows).
// smem: As[64][260] + Bs[8][260] + Ast[8][68]  (77,056 B) -> 2 CTAs/SM.
#define ELOOP_SMEM ((64*260 + 8*260 + 8*68) * 4)

__global__ __launch_bounds__(256, 2) void k_eloop(const float* __restrict__ wie,
                                                  const float* __restrict__ wcls,
                                                  const float* __restrict__ bcls,
                                                  const float* __restrict__ bos,
                                                  const float* __restrict__ bg2e) {
    extern __shared__ __align__(16) float sm_[];
    float* As  = sm_;                        // [64][260] row-major, pad 260
    float* Bs  = sm_ + 64 * 260;             // [8][260]
    float* Ast = sm_ + 64 * 260 + 8 * 260;   // [8][68]  (k-major A staging)
    int m0 = blockIdx.x * 64;
    int tid = threadIdx.x;
    int tx = tid & 31, ty = tid >> 5;
    int row0 = ty * 8;

    float be[8], wi[8], wc[8];
#pragma unroll
    for (int j = 0; j < 8; j++) {
        int col = tx * 8 + j;
        be[j] = g_biasE[col];
        wi[j] = wie[col];
        wc[j] = wcls[col];
    }
    float bcl = bcls[0], bos0 = bos[0];

    float acc[8][8];
#pragma unroll
    for (int i = 0; i < 8; i++)
#pragma unroll
        for (int j = 0; j < 8; j++) acc[i][j] = 0.f;

    int bkk = tid >> 5, bnq = (tid & 31) * 8;

    // ---- phase 1: proj (K = 800, 100 k-tiles) ----
    {
        int ar = tid >> 2, akq = (tid & 3) * 2;
        for (int kt = 0; kt < 100; kt++) {
            __syncthreads();
            float2 av = *(const float2*)(g_GS + (size_t)(m0 + ar) * (2*HG) + kt * 8 + akq);
            Ast[(akq + 0) * 68 + ar] = av.x;
            Ast[(akq + 1) * 68 + ar] = av.y;
            const float* bp = g_Wg2eT + (size_t)(kt * 8 + bkk) * HEH + bnq;
            *(float4*)&Bs[bkk * 260 + bnq]     = *(const float4*)(bp);
            *(float4*)&Bs[bkk * 260 + bnq + 4] = *(const float4*)(bp + 4);
            __syncthreads();
#pragma unroll
            for (int kk = 0; kk < 8; kk++) {
                float a[8], b[8];
#pragma unroll
                for (int i = 0; i < 8; i++) a[i] = Ast[kk * 68 + row0 + i];
                *(float4*)(b)     = *(const float4*)&Bs[kk * 260 + tx * 8];
                *(float4*)(b + 4) = *(const float4*)&Bs[kk * 260 + tx * 8 + 4];
#pragma unroll
                for (int i = 0; i < 8; i++)
#pragma unroll
                    for (int j = 0; j < 8; j++) acc[i][j] += a[i] * b[j];
            }
        }
        __syncthreads();
        float bg[8];
#pragma unroll
        for (int j = 0; j < 8; j++) bg[j] = bg2e[tx * 8 + j];
#pragma unroll
        for (int i = 0; i < 8; i++) {
            float v[8];
#pragma unroll
            for (int j = 0; j < 8; j++) v[j] = acc[i][j] + bg[j];
            *(float4*)&As[(row0 + i) * 260 + tx * 8]     = *(float4*)(v);
            *(float4*)&As[(row0 + i) * 260 + tx * 8 + 4] = *(float4*)(v + 4);
        }
    }

    // ---- phase 2: 20 estep iterations ----
    float xen[8];
    for (int st = 0; st < MST; st++) {
#pragma unroll
        for (int i = 0; i < 8; i++)
#pragma unroll
            for (int j = 0; j < 8; j++) acc[i][j] = 0.f;
        for (int kt = 0; kt < 32; kt++) {
            __syncthreads();
            const float* bp = g_WhheT + (size_t)(kt * 8 + bkk) * HEH + bnq;
            *(float4*)&Bs[bkk * 260 + bnq]     = *(const float4*)(bp);
            *(float4*)&Bs[bkk * 260 + bnq + 4] = *(const float4*)(bp + 4);
            __syncthreads();
#pragma unroll
            for (int kk = 0; kk < 8; kk++) {
                float a[8], b[8];
#pragma unroll
                for (int i = 0; i < 8; i++) a[i] = As[(row0 + i) * 260 + kt * 8 + kk];
                *(float4*)(b)     = *(const float4*)&Bs[kk * 260 + tx * 8];
                *(float4*)(b + 4) = *(const float4*)&Bs[kk * 260 + tx * 8 + 4];
#pragma unroll
                for (int i = 0; i < 8; i++)
#pragma unroll
                    for (int j = 0; j < 8; j++) acc[i][j] += a[i] * b[j];
            }
        }
        __syncthreads();   // all As reads complete before overwrite
#pragma unroll
        for (int i = 0; i < 8; i++) {
            int row = m0 + row0 + i;
            float xe = (st == 0) ? bos0 : xen[i];
            float part = 0.f, hn[8];
#pragma unroll
            for (int j = 0; j < 8; j++) {
                float v = tanhf(acc[i][j] + be[j] + xe * wi[j]);
                hn[j] = v;
                part += v * wc[j];
            }
            *(float4*)&As[(row0 + i) * 260 + tx * 8]     = *(float4*)(hn);
            *(float4*)&As[(row0 + i) * 260 + tx * 8 + 4] = *(float4*)(hn + 4);
#pragma unroll
            for (int off = 16; off > 0; off >>= 1)
                part += __shfl_xor_sync(0xffffffffu, part, off);
            float total = part + bcl;
            xen[i] = __shfl_sync(0xffffffffu, total, 0);
            if (tx == 0) g_Ap[row * MST + st] = total;
        }
    }
}

// ---------------- arc band gather ----------------
__global__ void k_arc(float* __restrict__ out) {
    size_t idx = (size_t)blockIdx.x * blockDim.x + threadIdx.x;
    size_t total = (size_t)BB * SL * SL;
    if (idx >= total) return;
    int c = (int)(idx % SL);
    int r = (int)((idx / SL) % SL);
    int b = (int)(idx / ((size_t)SL * SL));
    int start = r - MST; if (start < 0) start = 0;
    float v = 0.f;
    if (c >= start && c < r) v = g_Ap[(size_t)(b * SL + r) * MST + (c - start)];
    out[idx] = v;
}

// ---------------- host launcher ----------------
extern "C" void kernel_launch(void* const* d_in, const int* in_sizes, int n_in,
                              void* d_out, int out_size) {
    const float* input  = (const float*)d_in[0];
    const float* tagemb = (const float*)d_in[1];
    const int*   mask   = (const int*)d_in[2];
    const float* sent   = (const float*)d_in[3];
    const float* Wih_f  = (const float*)d_in[4];
    const float* Whh_f  = (const float*)d_in[5];
    const float* bih_f  = (const float*)d_in[6];
    const float* bhh_f  = (const float*)d_in[7];
    const float* Wih_b  = (const float*)d_in[8];
    const float* Whh_b  = (const float*)d_in[9];
    const float* bih_b  = (const float*)d_in[10];
    const float* bhh_b  = (const float*)d_in[11];
    const float* Wg2e   = (const float*)d_in[12];
    const float* bg2e   = (const float*)d_in[13];
    const float* Wih_e  = (const float*)d_in[14];
    const float* Whh_e  = (const float*)d_in[15];
    const float* bih_e  = (const float*)d_in[16];
    const float* bhh_e  = (const float*)d_in[17];
    const float* Wcls   = (const float*)d_in[18];
    const float* bcls   = (const float*)d_in[19];
    const float* bos    = (const float*)d_in[20];
    const float* Wht    = (const float*)d_in[21];
    const float* bht    = (const float*)d_in[22];
    const float* Wdt    = (const float*)d_in[23];
    const float* bdt    = (const float*)d_in[24];
    float* out = (float*)d_out;

    float *pX, *pPre, *pGS;
    float *pWihFBT, *pWtagT, *pbFB, *pbTag;
    cudaGetSymbolAddress((void**)&pX, g_X);
    cudaGetSymbolAddress((void**)&pPre, g_Pre);
    cudaGetSymbolAddress((void**)&pGS, g_GS);
    cudaGetSymbolAddress((void**)&pWihFBT, g_WihFBT);
    cudaGetSymbolAddress((void**)&pWtagT, g_WtagT);
    cudaGetSymbolAddress((void**)&pbFB, g_biasFB);
    cudaGetSymbolAddress((void**)&pbTag, g_biasTag);

    static int smem_set = 0;
    if (!smem_set) {
        cudaFuncSetAttribute(k_eloop, cudaFuncAttributeMaxDynamicSharedMemorySize, ELOOP_SMEM);
        smem_set = 1;
    }

    // 1. fused setup (weights + inputs)
    {
        size_t n = TSETUP;
        k_setup<<<(unsigned)((n + 255) / 256), 256>>>(Wih_f, Wih_b, Wg2e, Whh_e, Wht, Wdt,
                                                      bih_f, bhh_f, bih_b, bhh_b,
                                                      bih_e, bhh_e, bht, bdt,
                                                      input, tagemb, sent, mask);
    }
    // 2. fused Pre GEMM (N=896 padded)
    {
        dim3 grid(NPRE / 128, MR / 128);
        k_gemm128<0><<<grid, 256>>>(pX, pWihFBT, pbFB, pPre, nullptr, NPRE, DL);
    }
    // 3. bidirectional recurrence
    k_rnn<<<128, 256>>>(Whh_f, Whh_b);
    // 4. persistent proj + estep chain (single launch)
    k_eloop<<<MR / 64, 256, ELOOP_SMEM>>>(Wih_e, Wcls, bcls, bos, bg2e);
    // 5. head_tag / dep_tag fused GEMM -> d_out
    {
        dim3 grid(2, MR / 128);
        k_gemm128<2><<<grid, 256>>>(pGS, pWtagT, pbTag, out, out + (size_t)MR * TAGL,
                                    2 * TAGL, 2 * HG);
    }
    // 6. arc logits
    {
        size_t total = (size_t)BB * SL * SL;
        k_arc<<<(unsigned)((total + 255) / 256), 256>>>(out + 2 * (size_t)MR * TAGL);
    }
    (void)in_sizes; (void)n_in; (void)out_size;
}

// round 7
// speedup vs baseline: 1.1729x; 1.1729x over previous
#include <cuda_runtime.h>
#include <cuda_bf16.h>
#include <math.h>

#define BB   64
#define TL   383
#define SL   384
#define DL   896
#define HG   400
#define HEH  256
#define TAGL 128
#define MST  20
#define MR   (BB*SL)    // 24576
#define NPRE 896        // padded 2*HG

// ---------------- scratch (device globals) ----------------
__device__ float g_X[(size_t)MR*DL];
__device__ float g_Mf[MR];
__device__ float g_Pre[(size_t)MR*NPRE];
__device__ float g_GS[(size_t)MR*2*HG];
__device__ float g_H[2*2*BB*HG];
__device__ float g_Ap[MR*MST];
__device__ float g_WihFBT[NPRE*NPRE];
__device__ float g_WtagT[2*HG*2*TAGL];
__device__ float g_biasFB[NPRE];
__device__ float g_biasE[HEH];
__device__ float g_biasTag[2*TAGL];
// pre-split bf16 B-fragment arrays: [kt][split][n][slot] (slot=2*c4+half), words of bf16x2
__device__ unsigned g_Be[16*2*2048];    // Whh_e^T  (K=256 -> 16 ktiles)
__device__ unsigned g_Bp[50*2*2048];    // Wg2e^T   (K=800 -> 50 ktiles)

#define CLUSTER_SYNC_() do { \
    asm volatile("barrier.cluster.arrive.aligned;" ::: "memory"); \
    asm volatile("barrier.cluster.wait.aligned;" ::: "memory"); \
} while (0)

// ---------------- helpers ----------------
__device__ __forceinline__ void splitpack(float x0, float x1, unsigned& hi, unsigned& lo) {
    __nv_bfloat16 b0 = __float2bfloat16_rn(x0);
    __nv_bfloat16 b1 = __float2bfloat16_rn(x1);
    float r0 = x0 - __bfloat162float(b0);
    float r1 = x1 - __bfloat162float(b1);
    __nv_bfloat16 c0 = __float2bfloat16_rn(r0);
    __nv_bfloat16 c1 = __float2bfloat16_rn(r1);
    hi = (unsigned)__bfloat16_as_ushort(b0) | ((unsigned)__bfloat16_as_ushort(b1) << 16);
    lo = (unsigned)__bfloat16_as_ushort(c0) | ((unsigned)__bfloat16_as_ushort(c1) << 16);
}

__device__ __forceinline__ void mma16816(float* d, unsigned a0, unsigned a1, unsigned a2,
                                         unsigned a3, unsigned b0, unsigned b1) {
    asm volatile(
        "mma.sync.aligned.m16n8k16.row.col.f32.bf16.bf16.f32 "
        "{%0,%1,%2,%3},{%4,%5,%6,%7},{%8,%9},{%0,%1,%2,%3};"
        : "+f"(d[0]), "+f"(d[1]), "+f"(d[2]), "+f"(d[3])
        : "r"(a0), "r"(a1), "r"(a2), "r"(a3), "r"(b0), "r"(b1));
}

__device__ __forceinline__ float tanhfast(float x) {
    float e = __expf(2.f * x);
    return 1.f - __fdividef(2.f, e + 1.f);
}

// ---------------- fused setup ----------------
#define T1 (NPRE*NPRE)
#define T2 (50*2*2048)
#define T3 (16*2*2048)
#define T4 (2*HG*2*TAGL)
#define T5 (NPRE)
#define T6 (HEH)
#define T7 (2*TAGL)
#define TPREP (T1+T2+T3+T4+T5+T6+T7)
#define TBUILD ((size_t)MR*DL + MR)
#define TSETUP (TPREP + TBUILD)

__global__ void k_setup(const float* __restrict__ Wih_f, const float* __restrict__ Wih_b,
                        const float* __restrict__ Wg2e, const float* __restrict__ Whh_e,
                        const float* __restrict__ Wht,  const float* __restrict__ Wdt,
                        const float* __restrict__ bih_f, const float* __restrict__ bhh_f,
                        const float* __restrict__ bih_b, const float* __restrict__ bhh_b,
                        const float* __restrict__ bih_e, const float* __restrict__ bhh_e,
                        const float* __restrict__ bht,   const float* __restrict__ bdt,
                        const float* __restrict__ inp, const float* __restrict__ tag,
                        const float* __restrict__ sent, const int* __restrict__ mask) {
    size_t gidx = (size_t)blockIdx.x * blockDim.x + threadIdx.x;
    if (gidx < TPREP) {
        int idx = (int)gidx;
        if (idx < T1) {
            int k = idx / NPRE, n = idx % NPRE;
            float v = 0.f;
            if (k < DL) {
                if (n < HG)          v = Wih_f[(size_t)n * DL + k];
                else if (n < 2*HG)   v = Wih_b[(size_t)(n - HG) * DL + k];
            }
            g_WihFBT[idx] = v; return;
        }
        idx -= T1;
        if (idx < T2) {   // g_Bp from Wg2e (B[k][n] = Wg2e[n][k]), K=800
            int kt = idx >> 12, rest = idx & 4095;
            int split = rest >> 11, w = rest & 2047;
            int n = w >> 3, slot = w & 7;
            int k = kt * 16 + 2 * (slot >> 1) + 8 * (slot & 1);
            float x0 = Wg2e[(size_t)n * (2*HG) + k];
            float x1 = Wg2e[(size_t)n * (2*HG) + k + 1];
            unsigned hi, lo; splitpack(x0, x1, hi, lo);
            g_Bp[idx] = split ? lo : hi; return;
        }
        idx -= T2;
        if (idx < T3) {   // g_Be from Whh_e, K=256
            int kt = idx >> 12, rest = idx & 4095;
            int split = rest >> 11, w = rest & 2047;
            int n = w >> 3, slot = w & 7;
            int k = kt * 16 + 2 * (slot >> 1) + 8 * (slot & 1);
            float x0 = Whh_e[(size_t)n * HEH + k];
            float x1 = Whh_e[(size_t)n * HEH + k + 1];
            unsigned hi, lo; splitpack(x0, x1, hi, lo);
            g_Be[idx] = split ? lo : hi; return;
        }
        idx -= T3;
        if (idx < T4) {
            int k = idx / (2*TAGL), n = idx % (2*TAGL);
            g_WtagT[idx] = (n < TAGL) ? Wht[(size_t)n * (2*HG) + k] : Wdt[(size_t)(n - TAGL) * (2*HG) + k];
            return;
        }
        idx -= T4;
        if (idx < T5) {
            float v = 0.f;
            if (idx < HG) v = bih_f[idx] + bhh_f[idx];
            else if (idx < 2*HG) v = bih_b[idx-HG] + bhh_b[idx-HG];
            g_biasFB[idx] = v; return;
        }
        idx -= T5;
        if (idx < T6) { g_biasE[idx] = bih_e[idx] + bhh_e[idx]; return; }
        idx -= T6;
        g_biasTag[idx] = (idx < TAGL) ? bht[idx] : bdt[idx - TAGL];
        return;
    }
    gidx -= TPREP;
    size_t nx = (size_t)MR * DL;
    if (gidx < nx) {
        int d = (int)(gidx % DL);
        int m = (int)(gidx / DL);
        int b = m / SL, s = m % SL;
        float v;
        if (s == 0) v = sent[d];
        else {
            int t = s - 1;
            v = (d < 768) ? inp[(size_t)(b * TL + t) * 768 + d]
                          : tag[(size_t)(b * TL + t) * TAGL + (d - 768)];
        }
        g_X[gidx] = v;
        return;
    }
    gidx -= nx;
    if (gidx < MR) {
        int b = (int)(gidx / SL), s = (int)(gidx % SL);
        g_Mf[gidx] = (s == 0) ? 1.0f : (float)mask[b * TL + s - 1];
    }
}

// ---------------- 128x128 double-buffered SGEMM (Pre + tags) ----------------
template <int ACT>
__global__ __launch_bounds__(256) void k_gemm128(const float* __restrict__ A,
                                                 const float* __restrict__ Bt,
                                                 const float* __restrict__ bias,
                                                 float* __restrict__ C,
                                                 float* __restrict__ C2,
                                                 int N, int K) {
    __shared__ __align__(16) float As[2][8][132];
    __shared__ __align__(16) float Bs[2][8][132];
    int m0 = blockIdx.y * 128, n0 = blockIdx.x * 128;
    int tid = threadIdx.x;
    int tx = tid & 15, ty = tid >> 4;

    int arow = tid >> 1, akq = (tid & 1) * 4;
    const float* Ap = A + (size_t)(m0 + arow) * K + akq;
    int bkr = tid >> 5, bnq = (tid & 31) * 4;
    const float* Bp = Bt + (size_t)bkr * N + n0 + bnq;

    float acc[8][8];
#pragma unroll
    for (int i = 0; i < 8; i++)
#pragma unroll
        for (int j = 0; j < 8; j++) acc[i][j] = 0.f;

    float4 av = *(const float4*)Ap;
    float4 bv = *(const float4*)Bp;
    As[0][akq + 0][arow] = av.x;
    As[0][akq + 1][arow] = av.y;
    As[0][akq + 2][arow] = av.z;
    As[0][akq + 3][arow] = av.w;
    *(float4*)&Bs[0][bkr][bnq] = bv;
    __syncthreads();

    int nk = K >> 3;
    for (int kt = 0; kt < nk; kt++) {
        int buf = kt & 1;
        if (kt + 1 < nk) {
            av = *(const float4*)(Ap + (kt + 1) * 8);
            bv = *(const float4*)(Bp + (size_t)(kt + 1) * 8 * N);
        }
#pragma unroll
        for (int kk = 0; kk < 8; kk++) {
            float a[8], b[8];
            *(float4*)(a)     = *(const float4*)&As[buf][kk][ty * 8];
            *(float4*)(a + 4) = *(const float4*)&As[buf][kk][ty * 8 + 4];
            *(float4*)(b)     = *(const float4*)&Bs[buf][kk][tx * 8];
            *(float4*)(b + 4) = *(const float4*)&Bs[buf][kk][tx * 8 + 4];
#pragma unroll
            for (int i = 0; i < 8; i++)
#pragma unroll
                for (int j = 0; j < 8; j++) acc[i][j] += a[i] * b[j];
        }
        if (kt + 1 < nk) {
            int nb = buf ^ 1;
            As[nb][akq + 0][arow] = av.x;
            As[nb][akq + 1][arow] = av.y;
            As[nb][akq + 2][arow] = av.z;
            As[nb][akq + 3][arow] = av.w;
            *(float4*)&Bs[nb][bkr][bnq] = bv;
        }
        __syncthreads();
    }

    float bj[8];
#pragma unroll
    for (int j = 0; j < 8; j++) bj[j] = bias[n0 + tx * 8 + j];

    if (ACT == 0) {
#pragma unroll
        for (int i = 0; i < 8; i++) {
            int row = m0 + ty * 8 + i;
            float v[8];
#pragma unroll
            for (int j = 0; j < 8; j++) v[j] = acc[i][j] + bj[j];
            *(float4*)(C + (size_t)row * N + n0 + tx * 8)     = *(float4*)(v);
            *(float4*)(C + (size_t)row * N + n0 + tx * 8 + 4) = *(float4*)(v + 4);
        }
    } else {
        float* dst = (blockIdx.x == 0) ? C : C2;
#pragma unroll
        for (int i = 0; i < 8; i++) {
            int row = m0 + ty * 8 + i;
            float v[8];
#pragma unroll
            for (int j = 0; j < 8; j++) {
                float x = acc[i][j] + bj[j];
                v[j] = (x > 0.f) ? x : expm1f(x);
            }
            *(float4*)(dst + (size_t)row * TAGL + tx * 8)     = *(float4*)(v);
            *(float4*)(dst + (size_t)row * TAGL + tx * 8 + 4) = *(float4*)(v + 4);
        }
    }
}

// ---------------- persistent bidirectional masked RNN (cluster-synced) ----------------
__global__ void __cluster_dims__(8, 1, 1) __launch_bounds__(256, 1)
k_rnn(const float* __restrict__ WhhF, const float* __restrict__ WhhB) {
    int bx = blockIdx.x;
    int dir = bx >> 6;
    int bid = bx & 63;
    int bg = bid >> 3;
    int jg = bid & 7;
    const float* Whh = dir ? WhhB : WhhF;
    int jbase = jg * 50, b0 = bg * 8;
    int tid = threadIdx.x;
    int jl = tid >> 3, kp = tid & 7;
    bool jact = (jl < 25);
    int j0 = jbase + jl * 2;
    int preoff = dir * HG;

    float w0[50], w1[50];
    if (jact) {
#pragma unroll
        for (int i = 0; i < 50; i++) {
            w0[i] = Whh[(size_t)j0 * HG + kp * 50 + i];
            w1[i] = Whh[(size_t)(j0 + 1) * HG + kp * 50 + i];
        }
    }
    float* Hp0 = g_H + dir * 2 * BB * HG;
    float* Hp1 = Hp0 + BB * HG;
    for (int idx = tid; idx < 400; idx += 256) {
        int bl = idx / 50, jj = idx % 50;
        __stcg(&Hp0[(b0 + bl) * HG + jbase + jj], 0.f);
        __stcg(&Hp1[(b0 + bl) * HG + jbase + jj], 0.f);
    }
    CLUSTER_SYNC_();

    __shared__ __align__(16) float Hs[8 * HG];

    for (int tv = 0; tv < SL; tv++) {
        int t = dir ? (SL - 1 - tv) : tv;
        float* Hcur = (tv & 1) ? Hp1 : Hp0;
        float* Hnxt = (tv & 1) ? Hp0 : Hp1;
        for (int idx = tid; idx < 8 * HG; idx += 256)
            Hs[idx] = __ldcg(&Hcur[(b0 + (idx / HG)) * HG + (idx % HG)]);
        __syncthreads();

        float s0v[8], s1v[8];
        if (jact) {
#pragma unroll
            for (int bl = 0; bl < 8; bl++) {
                const float2* hv = (const float2*)(Hs + bl * HG + kp * 50);
                float a0 = 0.f, a1 = 0.f, c0 = 0.f, c1 = 0.f;
#pragma unroll
                for (int i = 0; i < 25; i++) {
                    float2 h = hv[i];
                    a0 += w0[2 * i] * h.x;  c0 += w0[2 * i + 1] * h.y;
                    a1 += w1[2 * i] * h.x;  c1 += w1[2 * i + 1] * h.y;
                }
                s0v[bl] = a0 + c0;
                s1v[bl] = a1 + c1;
            }
        } else {
#pragma unroll
            for (int bl = 0; bl < 8; bl++) { s0v[bl] = 0.f; s1v[bl] = 0.f; }
        }
#pragma unroll
        for (int bl = 0; bl < 8; bl++) {
            float s0 = s0v[bl], s1 = s1v[bl];
            s0 += __shfl_xor_sync(0xffffffffu, s0, 1);
            s0 += __shfl_xor_sync(0xffffffffu, s0, 2);
            s0 += __shfl_xor_sync(0xffffffffu, s0, 4);
            s1 += __shfl_xor_sync(0xffffffffu, s1, 1);
            s1 += __shfl_xor_sync(0xffffffffu, s1, 2);
            s1 += __shfl_xor_sync(0xffffffffu, s1, 4);
            if (jact && kp == 0) {
                int b = b0 + bl;
                int mrow = b * SL + t;
                float mt = g_Mf[mrow];
                float om = 1.f - mt;
                size_t pbase = (size_t)mrow * NPRE + preoff;
                float h00 = Hs[bl * HG + j0];
                float h01 = Hs[bl * HG + j0 + 1];
                float hn0 = tanhf(g_Pre[pbase + j0] + s0);
                float hn1 = tanhf(g_Pre[pbase + j0 + 1] + s1);
                float u0 = mt * hn0 + om * h00;
                float u1 = mt * hn1 + om * h01;
                __stcg(&Hnxt[b * HG + j0], u0);
                __stcg(&Hnxt[b * HG + j0 + 1], u1);
                size_t gbase = (size_t)mrow * (2 * HG) + dir * HG;
                g_GS[gbase + j0] = u0 * mt;
                g_GS[gbase + j0 + 1] = u1 * mt;
            }
        }
        CLUSTER_SYNC_();
    }
}

// ---------------- tensor-core proj + 20-step estep loop ----------------
// CTA = 64 rows, 8 warps: warp (mw = wid&3) rows mw*16.., (nh = wid>>2) cols nh*128..
// A state in smem as split-bf16 word pairs, layout word(r,p) = r*136 + (p>>3)*8 + 2*(p&3) + ((p>>2)&1).
// B streamed per-ktile from pre-split gmem fragments into Bsm[split][n][slot] stride 10.
#define AST 136
#define ELOOP_WORDS (8704*2 + 5120 + 1024 + 64 + 128)
#define ELOOP_SMEM  (ELOOP_WORDS * 4)

__global__ __launch_bounds__(256, 2) void k_eloop(const float* __restrict__ wie,
                                                  const float* __restrict__ wcls,
                                                  const float* __restrict__ bcls,
                                                  const float* __restrict__ bos,
                                                  const float* __restrict__ bg2e) {
    extern __shared__ unsigned sm_u[];
    unsigned* Ah  = sm_u;
    unsigned* Al  = sm_u + 8704;
    unsigned* Bsm = sm_u + 17408;
    float* sbe = (float*)(sm_u + 22528);
    float* swi = sbe + 256;
    float* swc = sbe + 512;
    float* sbg = sbe + 768;
    float* xs  = sbe + 1024;
    float* lp  = xs + 64;

    int tid = threadIdx.x;
    int wid = tid >> 5, lane = tid & 31;
    int mw = wid & 3, nh = wid >> 2;
    int r4 = lane >> 2, c4 = lane & 3;
    int rlo = mw * 16 + r4, rhi = rlo + 8;
    int m0 = blockIdx.x * 64;

    sbe[tid] = g_biasE[tid & 255];
    swi[tid] = wie[tid & 255];
    swc[tid] = wcls[tid & 255];
    sbg[tid] = bg2e[tid & 255];
    if (tid < 64) xs[tid] = bos[0];
    float bcl = bcls[0];

    float acc[16][4];
    uint2 bp[8];

    // chunk copy helpers (2048 uint2 per chunk, 8 per thread)
#define LDCHUNK(gsrc) do { \
        const uint2* s_ = (const uint2*)(gsrc); \
        _Pragma("unroll") for (int i_ = 0; i_ < 8; i_++) bp[i_] = s_[i_ * 256 + tid]; \
    } while (0)
#define STCHUNK() do { \
        _Pragma("unroll") for (int i_ = 0; i_ < 8; i_++) { \
            int j_ = i_ * 256 + tid; \
            int sp_ = j_ >> 10; int w_ = (2 * j_) & 2047; \
            *(uint2*)&Bsm[sp_ * 2560 + (w_ >> 3) * 10 + (w_ & 7)] = bp[i_]; \
        } \
    } while (0)

    // ================= proj phase: acc = GS @ Wg2e^T (K = 800) =================
#pragma unroll
    for (int nt = 0; nt < 16; nt++)
#pragma unroll
        for (int q = 0; q < 4; q++) acc[nt][q] = 0.f;

    const float* gsA = g_GS + (size_t)m0 * (2*HG);
    LDCHUNK(g_Bp);
    for (int kt = 0; kt < 50; kt++) {
        __syncthreads();
        STCHUNK();
        if (kt + 1 < 50) LDCHUNK(g_Bp + (size_t)(kt + 1) * 4096);
        __syncthreads();
        // A-frags straight from fp32 GS
        float2 x0 = *(const float2*)(gsA + (size_t)rlo * 800 + kt * 16 + 2 * c4);
        float2 x2 = *(const float2*)(gsA + (size_t)rlo * 800 + kt * 16 + 2 * c4 + 8);
        float2 x1 = *(const float2*)(gsA + (size_t)rhi * 800 + kt * 16 + 2 * c4);
        float2 x3 = *(const float2*)(gsA + (size_t)rhi * 800 + kt * 16 + 2 * c4 + 8);
        unsigned a0h, a0l, a1h, a1l, a2h, a2l, a3h, a3l;
        splitpack(x0.x, x0.y, a0h, a0l);
        splitpack(x1.x, x1.y, a1h, a1l);
        splitpack(x2.x, x2.y, a2h, a2l);
        splitpack(x3.x, x3.y, a3h, a3l);
#pragma unroll
        for (int nt = 0; nt < 16; nt++) {
            int n = nh * 128 + nt * 8 + r4;
            uint2 Bh = *(uint2*)&Bsm[n * 10 + 2 * c4];
            uint2 Bl = *(uint2*)&Bsm[2560 + n * 10 + 2 * c4];
            mma16816(acc[nt], a0h, a1h, a2h, a3h, Bh.x, Bh.y);
            mma16816(acc[nt], a0h, a1h, a2h, a3h, Bl.x, Bl.y);
            mma16816(acc[nt], a0l, a1l, a2l, a3l, Bh.x, Bh.y);
        }
    }
    __syncthreads();
    // proj epilogue: He0 = acc + bg2e -> Apack (split bf16)
#pragma unroll
    for (int ntp = 0; ntp < 8; ntp++) {
        int nt = ntp * 2;
        int nb0 = nh * 128 + nt * 8 + 2 * c4;
        int nb1 = nb0 + 8;
        float p00 = acc[nt][0] + sbg[nb0],   p01 = acc[nt][1] + sbg[nb0+1];
        float p10 = acc[nt+1][0] + sbg[nb1], p11 = acc[nt+1][1] + sbg[nb1+1];
        float q00 = acc[nt][2] + sbg[nb0],   q01 = acc[nt][3] + sbg[nb0+1];
        float q10 = acc[nt+1][2] + sbg[nb1], q11 = acc[nt+1][3] + sbg[nb1+1];
        unsigned he0, le0, he1, le1;
        int wlo = rlo * AST + (nh * 8 + ntp) * 8 + 2 * c4;
        int whi = rhi * AST + (nh * 8 + ntp) * 8 + 2 * c4;
        splitpack(p00, p01, he0, le0); splitpack(p10, p11, he1, le1);
        *(uint2*)&Ah[wlo] = make_uint2(he0, he1);
        *(uint2*)&Al[wlo] = make_uint2(le0, le1);
        splitpack(q00, q01, he0, le0); splitpack(q10, q11, he1, le1);
        *(uint2*)&Ah[whi] = make_uint2(he0, he1);
        *(uint2*)&Al[whi] = make_uint2(le0, le1);
    }
    __syncthreads();

    // ================= 20 estep iterations =================
    for (int st = 0; st < MST; st++) {
#pragma unroll
        for (int nt = 0; nt < 16; nt++)
#pragma unroll
            for (int q = 0; q < 4; q++) acc[nt][q] = 0.f;

        LDCHUNK(g_Be);
        for (int kt = 0; kt < 16; kt++) {
            __syncthreads();
            STCHUNK();
            if (kt + 1 < 16) LDCHUNK(g_Be + (size_t)(kt + 1) * 4096);
            __syncthreads();
            uint2 UA  = *(uint2*)&Ah[rlo * AST + kt * 8 + 2 * c4];   // (a0h,a2h)
            uint2 VA  = *(uint2*)&Ah[rhi * AST + kt * 8 + 2 * c4];   // (a1h,a3h)
            uint2 UAl = *(uint2*)&Al[rlo * AST + kt * 8 + 2 * c4];
            uint2 VAl = *(uint2*)&Al[rhi * AST + kt * 8 + 2 * c4];
#pragma unroll
            for (int nt = 0; nt < 16; nt++) {
                int n = nh * 128 + nt * 8 + r4;
                uint2 Bh = *(uint2*)&Bsm[n * 10 + 2 * c4];
                uint2 Bl = *(uint2*)&Bsm[2560 + n * 10 + 2 * c4];
                mma16816(acc[nt], UA.x, VA.x, UA.y, VA.y, Bh.x, Bh.y);
                mma16816(acc[nt], UA.x, VA.x, UA.y, VA.y, Bl.x, Bl.y);
                mma16816(acc[nt], UAl.x, VAl.x, UAl.y, VAl.y, Bh.x, Bh.y);
            }
        }
        __syncthreads();   // all Apack reads done before overwrite

        float xel = xs[rlo], xeh = xs[rhi];
        float pl = 0.f, ph = 0.f;
#pragma unroll
        for (int ntp = 0; ntp < 8; ntp++) {
            int nt = ntp * 2;
            int nb0 = nh * 128 + nt * 8 + 2 * c4;
            int nb1 = nb0 + 8;
            float b00 = sbe[nb0], b01 = sbe[nb0+1], b10 = sbe[nb1], b11 = sbe[nb1+1];
            float w00 = swi[nb0], w01 = swi[nb0+1], w10 = swi[nb1], w11 = swi[nb1+1];
            float h00 = tanhfast(acc[nt][0]   + b00 + xel * w00);
            float h01 = tanhfast(acc[nt][1]   + b01 + xel * w01);
            float h10 = tanhfast(acc[nt+1][0] + b10 + xel * w10);
            float h11 = tanhfast(acc[nt+1][1] + b11 + xel * w11);
            float g00 = tanhfast(acc[nt][2]   + b00 + xeh * w00);
            float g01 = tanhfast(acc[nt][3]   + b01 + xeh * w01);
            float g10 = tanhfast(acc[nt+1][2] + b10 + xeh * w10);
            float g11 = tanhfast(acc[nt+1][3] + b11 + xeh * w11);
            float c00 = swc[nb0], c01 = swc[nb0+1], c10 = swc[nb1], c11 = swc[nb1+1];
            pl += h00 * c00 + h01 * c01 + h10 * c10 + h11 * c11;
            ph += g00 * c00 + g01 * c01 + g10 * c10 + g11 * c11;
            unsigned he0, le0, he1, le1;
            int wlo = rlo * AST + (nh * 8 + ntp) * 8 + 2 * c4;
            int whi = rhi * AST + (nh * 8 + ntp) * 8 + 2 * c4;
            splitpack(h00, h01, he0, le0); splitpack(h10, h11, he1, le1);
            *(uint2*)&Ah[wlo] = make_uint2(he0, he1);
            *(uint2*)&Al[wlo] = make_uint2(le0, le1);
            splitpack(g00, g01, he0, le0); splitpack(g10, g11, he1, le1);
            *(uint2*)&Ah[whi] = make_uint2(he0, he1);
            *(uint2*)&Al[whi] = make_uint2(le0, le1);
        }
        // logit reduction over the 4 lanes sharing a row
        pl += __shfl_xor_sync(0xffffffffu, pl, 1);
        pl += __shfl_xor_sync(0xffffffffu, pl, 2);
        ph += __shfl_xor_sync(0xffffffffu, ph, 1);
        ph += __shfl_xor_sync(0xffffffffu, ph, 2);
        if (c4 == 0) {
            lp[wid * 16 + r4]     = pl;
            lp[wid * 16 + 8 + r4] = ph;
        }
        __syncthreads();
        if (tid < 64) {
            int mwr = tid >> 4, ir = tid & 15;
            float logit = lp[mwr * 16 + ir] + lp[(mwr + 4) * 16 + ir] + bcl;
            g_Ap[(size_t)(m0 + tid) * MST + st] = logit;
            xs[tid] = logit;
        }
        __syncthreads();
    }
#undef LDCHUNK
#undef STCHUNK
}

// ---------------- arc band gather ----------------
__global__ void k_arc(float* __restrict__ out) {
    size_t idx = (size_t)blockIdx.x * blockDim.x + threadIdx.x;
    size_t total = (size_t)BB * SL * SL;
    if (idx >= total) return;
    int c = (int)(idx % SL);
    int r = (int)((idx / SL) % SL);
    int b = (int)(idx / ((size_t)SL * SL));
    int start = r - MST; if (start < 0) start = 0;
    float v = 0.f;
    if (c >= start && c < r) v = g_Ap[(size_t)(b * SL + r) * MST + (c - start)];
    out[idx] = v;
}

// ---------------- host launcher ----------------
extern "C" void kernel_launch(void* const* d_in, const int* in_sizes, int n_in,
                              void* d_out, int out_size) {
    const float* input  = (const float*)d_in[0];
    const float* tagemb = (const float*)d_in[1];
    const int*   mask   = (const int*)d_in[2];
    const float* sent   = (const float*)d_in[3];
    const float* Wih_f  = (const float*)d_in[4];
    const float* Whh_f  = (const float*)d_in[5];
    const float* bih_f  = (const float*)d_in[6];
    const float* bhh_f  = (const float*)d_in[7];
    const float* Wih_b  = (const float*)d_in[8];
    const float* Whh_b  = (const float*)d_in[9];
    const float* bih_b  = (const float*)d_in[10];
    const float* bhh_b  = (const float*)d_in[11];
    const float* Wg2e   = (const float*)d_in[12];
    const float* bg2e   = (const float*)d_in[13];
    const float* Wih_e  = (const float*)d_in[14];
    const float* Whh_e  = (const float*)d_in[15];
    const float* bih_e  = (const float*)d_in[16];
    const float* bhh_e  = (const float*)d_in[17];
    const float* Wcls   = (const float*)d_in[18];
    const float* bcls   = (const float*)d_in[19];
    const float* bos    = (const float*)d_in[20];
    const float* Wht    = (const float*)d_in[21];
    const float* bht    = (const float*)d_in[22];
    const float* Wdt    = (const float*)d_in[23];
    const float* bdt    = (const float*)d_in[24];
    float* out = (float*)d_out;

    float *pX, *pPre, *pGS;
    float *pWihFBT, *pWtagT, *pbFB, *pbTag;
    cudaGetSymbolAddress((void**)&pX, g_X);
    cudaGetSymbolAddress((void**)&pPre, g_Pre);
    cudaGetSymbolAddress((void**)&pGS, g_GS);
    cudaGetSymbolAddress((void**)&pWihFBT, g_WihFBT);
    cudaGetSymbolAddress((void**)&pWtagT, g_WtagT);
    cudaGetSymbolAddress((void**)&pbFB, g_biasFB);
    cudaGetSymbolAddress((void**)&pbTag, g_biasTag);

    static int smem_set = 0;
    if (!smem_set) {
        cudaFuncSetAttribute(k_eloop, cudaFuncAttributeMaxDynamicSharedMemorySize, ELOOP_SMEM);
        smem_set = 1;
    }

    // 1. fused setup (weights + pre-split B fragments + inputs)
    {
        size_t n = TSETUP;
        k_setup<<<(unsigned)((n + 255) / 256), 256>>>(Wih_f, Wih_b, Wg2e, Whh_e, Wht, Wdt,
                                                      bih_f, bhh_f, bih_b, bhh_b,
                                                      bih_e, bhh_e, bht, bdt,
                                                      input, tagemb, sent, mask);
    }
    // 2. fused Pre GEMM (N=896 padded)
    {
        dim3 grid(NPRE / 128, MR / 128);
        k_gemm128<0><<<grid, 256>>>(pX, pWihFBT, pbFB, pPre, nullptr, NPRE, DL);
    }
    // 3. bidirectional recurrence
    k_rnn<<<128, 256>>>(Whh_f, Whh_b);
    // 4. tensor-core proj + estep chain (single launch)
    k_eloop<<<MR / 64, 256, ELOOP_SMEM>>>(Wih_e, Wcls, bcls, bos, bg2e);
    // 5. head_tag / dep_tag fused GEMM -> d_out
    {
        dim3 grid(2, MR / 128);
        k_gemm128<2><<<grid, 256>>>(pGS, pWtagT, pbTag, out, out + (size_t)MR * TAGL,
                                    2 * TAGL, 2 * HG);
    }
    // 6. arc logits
    {
        size_t total = (size_t)BB * SL * SL;
        k_arc<<<(unsigned)((total + 255) / 256), 256>>>(out + 2 * (size_t)MR * TAGL);
    }
    (void)in_sizes; (void)n_in; (void)out_size;
}

// round 8
// speedup vs baseline: 1.2398x; 1.0570x over previous
#include <cuda_runtime.h>
#include <cuda_bf16.h>
#include <math.h>

#define BB   64
#define TL   383
#define SL   384
#define DL   896
#define HG   400
#define HEH  256
#define TAGL 128
#define MST  20
#define MR   (BB*SL)    // 24576
#define NPRE 896        // padded 2*HG

// ---------------- scratch (device globals) ----------------
__device__ float g_X[(size_t)MR*DL];
__device__ float g_Mf[MR];
__device__ float g_Pre[(size_t)MR*NPRE];
__device__ float g_GS[(size_t)MR*2*HG];
__device__ float g_H[2*2*BB*HG];
__device__ float g_Ap[MR*MST];
__device__ float g_biasFB[NPRE];
__device__ float g_biasE[HEH];
__device__ float g_biasTag[2*TAGL];
// pre-split bf16 B fragment arrays: [kt][split][n][slot], words of bf16x2
__device__ unsigned g_Be[16*2*2048];      // Whh_e^T   (K=256, N=256)
__device__ unsigned g_Bp[50*2*2048];      // Wg2e^T    (K=800, N=256)
__device__ unsigned g_Bpre[56*2*7168];    // [Wih_f|Wih_b]^T padded (K=896, N=896)
__device__ unsigned g_Btag[50*2*2048];    // [Wht|Wdt]^T (K=800, N=256)

#define CLUSTER_SYNC_() do { \
    asm volatile("barrier.cluster.arrive.aligned;" ::: "memory"); \
    asm volatile("barrier.cluster.wait.aligned;" ::: "memory"); \
} while (0)

// ---------------- helpers ----------------
__device__ __forceinline__ void splitpack(float x0, float x1, unsigned& hi, unsigned& lo) {
    __nv_bfloat16 b0 = __float2bfloat16_rn(x0);
    __nv_bfloat16 b1 = __float2bfloat16_rn(x1);
    float r0 = x0 - __bfloat162float(b0);
    float r1 = x1 - __bfloat162float(b1);
    __nv_bfloat16 c0 = __float2bfloat16_rn(r0);
    __nv_bfloat16 c1 = __float2bfloat16_rn(r1);
    hi = (unsigned)__bfloat16_as_ushort(b0) | ((unsigned)__bfloat16_as_ushort(b1) << 16);
    lo = (unsigned)__bfloat16_as_ushort(c0) | ((unsigned)__bfloat16_as_ushort(c1) << 16);
}

__device__ __forceinline__ void mma16816(float* d, unsigned a0, unsigned a1, unsigned a2,
                                         unsigned a3, unsigned b0, unsigned b1) {
    asm volatile(
        "mma.sync.aligned.m16n8k16.row.col.f32.bf16.bf16.f32 "
        "{%0,%1,%2,%3},{%4,%5,%6,%7},{%8,%9},{%0,%1,%2,%3};"
        : "+f"(d[0]), "+f"(d[1]), "+f"(d[2]), "+f"(d[3])
        : "r"(a0), "r"(a1), "r"(a2), "r"(a3), "r"(b0), "r"(b1));
}

__device__ __forceinline__ float tanhfast(float x) {
    float e = __expf(2.f * x);
    return 1.f - __fdividef(2.f, e + 1.f);
}

// ---------------- fused setup ----------------
#define S1 (56*2*7168)   // g_Bpre
#define S2 (50*2*2048)   // g_Bp
#define S3 (16*2*2048)   // g_Be
#define S4 (50*2*2048)   // g_Btag
#define S5 (NPRE)
#define S6 (HEH)
#define S7 (2*TAGL)
#define TPREP (S1+S2+S3+S4+S5+S6+S7)
#define TBUILD ((size_t)MR*DL + MR)
#define TSETUP (TPREP + TBUILD)

__global__ void k_setup(const float* __restrict__ Wih_f, const float* __restrict__ Wih_b,
                        const float* __restrict__ Wg2e, const float* __restrict__ Whh_e,
                        const float* __restrict__ Wht,  const float* __restrict__ Wdt,
                        const float* __restrict__ bih_f, const float* __restrict__ bhh_f,
                        const float* __restrict__ bih_b, const float* __restrict__ bhh_b,
                        const float* __restrict__ bih_e, const float* __restrict__ bhh_e,
                        const float* __restrict__ bht,   const float* __restrict__ bdt,
                        const float* __restrict__ inp, const float* __restrict__ tag,
                        const float* __restrict__ sent, const int* __restrict__ mask) {
    size_t gidx = (size_t)blockIdx.x * blockDim.x + threadIdx.x;
    if (gidx < TPREP) {
        int idx = (int)gidx;
        if (idx < S1) {   // g_Bpre: K=896, N=896 (n>=800 zero)
            int kt = idx / 14336, rest = idx % 14336;
            int split = rest / 7168, w = rest % 7168;
            int n = w >> 3, s = w & 7;
            int k = kt * 16 + 2 * (s >> 1) + 8 * (s & 1);
            float x0 = 0.f, x1 = 0.f;
            if (n < HG)          { x0 = Wih_f[(size_t)n * DL + k];        x1 = Wih_f[(size_t)n * DL + k + 1]; }
            else if (n < 2*HG)   { x0 = Wih_b[(size_t)(n-HG) * DL + k];   x1 = Wih_b[(size_t)(n-HG) * DL + k + 1]; }
            unsigned hi, lo; splitpack(x0, x1, hi, lo);
            g_Bpre[idx] = split ? lo : hi; return;
        }
        idx -= S1;
        if (idx < S2) {   // g_Bp from Wg2e, K=800, N=256
            int kt = idx >> 12, rest = idx & 4095;
            int split = rest >> 11, w = rest & 2047;
            int n = w >> 3, s = w & 7;
            int k = kt * 16 + 2 * (s >> 1) + 8 * (s & 1);
            float x0 = Wg2e[(size_t)n * (2*HG) + k];
            float x1 = Wg2e[(size_t)n * (2*HG) + k + 1];
            unsigned hi, lo; splitpack(x0, x1, hi, lo);
            g_Bp[idx] = split ? lo : hi; return;
        }
        idx -= S2;
        if (idx < S3) {   // g_Be from Whh_e, K=256
            int kt = idx >> 12, rest = idx & 4095;
            int split = rest >> 11, w = rest & 2047;
            int n = w >> 3, s = w & 7;
            int k = kt * 16 + 2 * (s >> 1) + 8 * (s & 1);
            float x0 = Whh_e[(size_t)n * HEH + k];
            float x1 = Whh_e[(size_t)n * HEH + k + 1];
            unsigned hi, lo; splitpack(x0, x1, hi, lo);
            g_Be[idx] = split ? lo : hi; return;
        }
        idx -= S3;
        if (idx < S4) {   // g_Btag: [Wht|Wdt], K=800, N=256
            int kt = idx >> 12, rest = idx & 4095;
            int split = rest >> 11, w = rest & 2047;
            int n = w >> 3, s = w & 7;
            int k = kt * 16 + 2 * (s >> 1) + 8 * (s & 1);
            float x0, x1;
            if (n < TAGL) { x0 = Wht[(size_t)n * (2*HG) + k];        x1 = Wht[(size_t)n * (2*HG) + k + 1]; }
            else          { x0 = Wdt[(size_t)(n-TAGL) * (2*HG) + k]; x1 = Wdt[(size_t)(n-TAGL) * (2*HG) + k + 1]; }
            unsigned hi, lo; splitpack(x0, x1, hi, lo);
            g_Btag[idx] = split ? lo : hi; return;
        }
        idx -= S4;
        if (idx < S5) {
            float v = 0.f;
            if (idx < HG) v = bih_f[idx] + bhh_f[idx];
            else if (idx < 2*HG) v = bih_b[idx-HG] + bhh_b[idx-HG];
            g_biasFB[idx] = v; return;
        }
        idx -= S5;
        if (idx < S6) { g_biasE[idx] = bih_e[idx] + bhh_e[idx]; return; }
        idx -= S6;
        g_biasTag[idx] = (idx < TAGL) ? bht[idx] : bdt[idx - TAGL];
        return;
    }
    gidx -= TPREP;
    size_t nx = (size_t)MR * DL;
    if (gidx < nx) {
        int d = (int)(gidx % DL);
        int m = (int)(gidx / DL);
        int b = m / SL, s = m % SL;
        float v;
        if (s == 0) v = sent[d];
        else {
            int t = s - 1;
            v = (d < 768) ? inp[(size_t)(b * TL + t) * 768 + d]
                          : tag[(size_t)(b * TL + t) * TAGL + (d - 768)];
        }
        g_X[gidx] = v;
        return;
    }
    gidx -= nx;
    if (gidx < MR) {
        int b = (int)(gidx / SL), s = (int)(gidx % SL);
        g_Mf[gidx] = (s == 0) ? 1.0f : (float)mask[b * TL + s - 1];
    }
}

// ---------------- split-bf16 HMMA GEMM, 128x128 tile ----------------
// C(M,N) = A(M,K) @ B(K,N) + bias, A fp32 (row stride K), B pre-split fragments.
// 256 thr = 8 warps; warp (mw=wid&3) rows mw*32.., (nh=wid>>2) cols nh*64..
// ACT=0: plain store stride N (col base n0). ACT=2: ELU, split store:
//   blockIdx.x==0 -> C, ==1 -> C2, both stride TAGL, local cols.
template <int ACT>
__global__ __launch_bounds__(256) void k_hgemm(const float* __restrict__ A,
                                               const unsigned* __restrict__ Bfrag,
                                               const float* __restrict__ bias,
                                               float* __restrict__ C, float* __restrict__ C2,
                                               int N, int K, int Nfrag) {
    __shared__ __align__(16) unsigned Ahs[1280];
    __shared__ __align__(16) unsigned Als[1280];
    __shared__ __align__(16) unsigned Bsm[2560];
    int m0 = blockIdx.y * 128, n0 = blockIdx.x * 128;
    int tid = threadIdx.x, wid = tid >> 5, lane = tid & 31;
    int mw = wid & 3, nh = wid >> 2;
    int r4 = lane >> 2, c4 = lane & 3;
    int nkt = K >> 4;
    int Nw8 = Nfrag * 8;

    int arow = tid >> 1, sg = (tid & 1) * 4;
    const float* Apt = A + (size_t)(m0 + arow) * K;

    float2 af[4];
    uint2  bf[4];
    float acc[2][8][4];
#pragma unroll
    for (int mt = 0; mt < 2; mt++)
#pragma unroll
        for (int nt = 0; nt < 8; nt++)
#pragma unroll
            for (int q = 0; q < 4; q++) acc[mt][nt][q] = 0.f;

#define HLD(KT) do { \
        _Pragma("unroll") for (int s_ = 0; s_ < 4; s_++) { \
            int s = sg + s_; int kl = 2 * (s >> 1) + 8 * (s & 1); \
            af[s_] = *(const float2*)(Apt + (KT) * 16 + kl); } \
        _Pragma("unroll") for (int i_ = 0; i_ < 4; i_++) { \
            int lw = 2 * (i_ * 256 + tid); \
            int sp = lw >> 10, wq = lw & 1023; \
            bf[i_] = *(const uint2*)(Bfrag + (size_t)(KT) * 2 * Nw8 + (size_t)sp * Nw8 + n0 * 8 + wq); } \
    } while (0)

#define HST() do { \
        _Pragma("unroll") for (int s_ = 0; s_ < 4; s_++) { \
            unsigned hi_, lo_; splitpack(af[s_].x, af[s_].y, hi_, lo_); \
            Ahs[arow * 10 + sg + s_] = hi_; Als[arow * 10 + sg + s_] = lo_; } \
        _Pragma("unroll") for (int i_ = 0; i_ < 4; i_++) { \
            int lw = 2 * (i_ * 256 + tid); \
            int sp = lw >> 10, wq = lw & 1023; \
            int n_ = wq >> 3, s_ = wq & 7; \
            *(uint2*)&Bsm[sp * 1280 + n_ * 10 + s_] = bf[i_]; } \
    } while (0)

    HLD(0);
    for (int kt = 0; kt < nkt; kt++) {
        __syncthreads();
        HST();
        if (kt + 1 < nkt) HLD(kt + 1);
        __syncthreads();
        uint2 Uh[2], Vh[2], Ul[2], Vl[2];
#pragma unroll
        for (int mt = 0; mt < 2; mt++) {
            int rb = mw * 32 + mt * 16 + r4;
            Uh[mt] = *(uint2*)&Ahs[rb * 10 + 2 * c4];
            Vh[mt] = *(uint2*)&Ahs[(rb + 8) * 10 + 2 * c4];
            Ul[mt] = *(uint2*)&Als[rb * 10 + 2 * c4];
            Vl[mt] = *(uint2*)&Als[(rb + 8) * 10 + 2 * c4];
        }
#pragma unroll
        for (int nt = 0; nt < 8; nt++) {
            int n = nh * 64 + nt * 8 + r4;
            uint2 Bh = *(uint2*)&Bsm[n * 10 + 2 * c4];
            uint2 Bl = *(uint2*)&Bsm[1280 + n * 10 + 2 * c4];
#pragma unroll
            for (int mt = 0; mt < 2; mt++) {
                mma16816(acc[mt][nt], Uh[mt].x, Vh[mt].x, Uh[mt].y, Vh[mt].y, Bh.x, Bh.y);
                mma16816(acc[mt][nt], Uh[mt].x, Vh[mt].x, Uh[mt].y, Vh[mt].y, Bl.x, Bl.y);
                mma16816(acc[mt][nt], Ul[mt].x, Vl[mt].x, Ul[mt].y, Vl[mt].y, Bh.x, Bh.y);
            }
        }
    }
#undef HLD
#undef HST

#pragma unroll
    for (int nt = 0; nt < 8; nt++) {
        int colL = nh * 64 + nt * 8 + 2 * c4;
        float b0 = bias[n0 + colL], b1 = bias[n0 + colL + 1];
#pragma unroll
        for (int mt = 0; mt < 2; mt++) {
            int r = m0 + mw * 32 + mt * 16 + r4;
            float v0 = acc[mt][nt][0] + b0, v1 = acc[mt][nt][1] + b1;
            float v2 = acc[mt][nt][2] + b0, v3 = acc[mt][nt][3] + b1;
            if (ACT == 2) {
                v0 = (v0 > 0.f) ? v0 : expm1f(v0);
                v1 = (v1 > 0.f) ? v1 : expm1f(v1);
                v2 = (v2 > 0.f) ? v2 : expm1f(v2);
                v3 = (v3 > 0.f) ? v3 : expm1f(v3);
                float* dst = (blockIdx.x == 0) ? C : C2;
                *(float2*)(dst + (size_t)r * TAGL + colL)       = make_float2(v0, v1);
                *(float2*)(dst + (size_t)(r + 8) * TAGL + colL) = make_float2(v2, v3);
            } else {
                *(float2*)(C + (size_t)r * N + n0 + colL)       = make_float2(v0, v1);
                *(float2*)(C + (size_t)(r + 8) * N + n0 + colL) = make_float2(v2, v3);
            }
        }
    }
}

// ---------------- persistent bidirectional masked RNN (cluster-synced) ----------------
__global__ void __cluster_dims__(8, 1, 1) __launch_bounds__(256, 1)
k_rnn(const float* __restrict__ WhhF, const float* __restrict__ WhhB) {
    int bx = blockIdx.x;
    int dir = bx >> 6;
    int bid = bx & 63;
    int bg = bid >> 3;
    int jg = bid & 7;
    const float* Whh = dir ? WhhB : WhhF;
    int jbase = jg * 50, b0 = bg * 8;
    int tid = threadIdx.x;
    int jl = tid >> 3, kp = tid & 7;
    bool jact = (jl < 25);
    int j0 = jbase + jl * 2;
    int preoff = dir * HG;

    float w0[50], w1[50];
    if (jact) {
#pragma unroll
        for (int i = 0; i < 50; i++) {
            w0[i] = Whh[(size_t)j0 * HG + kp * 50 + i];
            w1[i] = Whh[(size_t)(j0 + 1) * HG + kp * 50 + i];
        }
    }
    float* Hp0 = g_H + dir * 2 * BB * HG;
    float* Hp1 = Hp0 + BB * HG;
    for (int idx = tid; idx < 400; idx += 256) {
        int bl = idx / 50, jj = idx % 50;
        __stcg(&Hp0[(b0 + bl) * HG + jbase + jj], 0.f);
        __stcg(&Hp1[(b0 + bl) * HG + jbase + jj], 0.f);
    }
    CLUSTER_SYNC_();

    __shared__ __align__(16) float Hs[8 * HG];

    for (int tv = 0; tv < SL; tv++) {
        int t = dir ? (SL - 1 - tv) : tv;
        float* Hcur = (tv & 1) ? Hp1 : Hp0;
        float* Hnxt = (tv & 1) ? Hp0 : Hp1;
        for (int idx = tid; idx < 8 * HG; idx += 256)
            Hs[idx] = __ldcg(&Hcur[(b0 + (idx / HG)) * HG + (idx % HG)]);
        __syncthreads();

        float s0v[8], s1v[8];
        if (jact) {
#pragma unroll
            for (int bl = 0; bl < 8; bl++) {
                const float2* hv = (const float2*)(Hs + bl * HG + kp * 50);
                float a0 = 0.f, a1 = 0.f, c0 = 0.f, c1 = 0.f;
#pragma unroll
                for (int i = 0; i < 25; i++) {
                    float2 h = hv[i];
                    a0 += w0[2 * i] * h.x;  c0 += w0[2 * i + 1] * h.y;
                    a1 += w1[2 * i] * h.x;  c1 += w1[2 * i + 1] * h.y;
                }
                s0v[bl] = a0 + c0;
                s1v[bl] = a1 + c1;
            }
        } else {
#pragma unroll
            for (int bl = 0; bl < 8; bl++) { s0v[bl] = 0.f; s1v[bl] = 0.f; }
        }
#pragma unroll
        for (int bl = 0; bl < 8; bl++) {
            float s0 = s0v[bl], s1 = s1v[bl];
            s0 += __shfl_xor_sync(0xffffffffu, s0, 1);
            s0 += __shfl_xor_sync(0xffffffffu, s0, 2);
            s0 += __shfl_xor_sync(0xffffffffu, s0, 4);
            s1 += __shfl_xor_sync(0xffffffffu, s1, 1);
            s1 += __shfl_xor_sync(0xffffffffu, s1, 2);
            s1 += __shfl_xor_sync(0xffffffffu, s1, 4);
            if (jact && kp == 0) {
                int b = b0 + bl;
                int mrow = b * SL + t;
                float mt = g_Mf[mrow];
                float om = 1.f - mt;
                size_t pbase = (size_t)mrow * NPRE + preoff;
                float h00 = Hs[bl * HG + j0];
                float h01 = Hs[bl * HG + j0 + 1];
                float hn0 = tanhf(g_Pre[pbase + j0] + s0);
                float hn1 = tanhf(g_Pre[pbase + j0 + 1] + s1);
                float u0 = mt * hn0 + om * h00;
                float u1 = mt * hn1 + om * h01;
                __stcg(&Hnxt[b * HG + j0], u0);
                __stcg(&Hnxt[b * HG + j0 + 1], u1);
                size_t gbase = (size_t)mrow * (2 * HG) + dir * HG;
                g_GS[gbase + j0] = u0 * mt;
                g_GS[gbase + j0 + 1] = u1 * mt;
            }
        }
        CLUSTER_SYNC_();
    }
}

// ---------------- tensor-core proj + 20-step estep loop ----------------
#define AST 136
#define ELOOP_WORDS (8704*2 + 5120 + 1024 + 64 + 128)
#define ELOOP_SMEM  (ELOOP_WORDS * 4)

__global__ __launch_bounds__(256, 2) void k_eloop(const float* __restrict__ wie,
                                                  const float* __restrict__ wcls,
                                                  const float* __restrict__ bcls,
                                                  const float* __restrict__ bos,
                                                  const float* __restrict__ bg2e) {
    extern __shared__ unsigned sm_u[];
    unsigned* Ah  = sm_u;
    unsigned* Al  = sm_u + 8704;
    unsigned* Bsm = sm_u + 17408;
    float* sbe = (float*)(sm_u + 22528);
    float* swi = sbe + 256;
    float* swc = sbe + 512;
    float* sbg = sbe + 768;
    float* xs  = sbe + 1024;
    float* lp  = xs + 64;

    int tid = threadIdx.x;
    int wid = tid >> 5, lane = tid & 31;
    int mw = wid & 3, nh = wid >> 2;
    int r4 = lane >> 2, c4 = lane & 3;
    int rlo = mw * 16 + r4, rhi = rlo + 8;
    int m0 = blockIdx.x * 64;

    sbe[tid] = g_biasE[tid & 255];
    swi[tid] = wie[tid & 255];
    swc[tid] = wcls[tid & 255];
    sbg[tid] = bg2e[tid & 255];
    if (tid < 64) xs[tid] = bos[0];
    float bcl = bcls[0];

    float acc[16][4];
    uint2 bp[8];

#define LDCHUNK(gsrc) do { \
        const uint2* s_ = (const uint2*)(gsrc); \
        _Pragma("unroll") for (int i_ = 0; i_ < 8; i_++) bp[i_] = s_[i_ * 256 + tid]; \
    } while (0)
#define STCHUNK() do { \
        _Pragma("unroll") for (int i_ = 0; i_ < 8; i_++) { \
            int j_ = i_ * 256 + tid; \
            int sp_ = j_ >> 10; int w_ = (2 * j_) & 2047; \
            *(uint2*)&Bsm[sp_ * 2560 + (w_ >> 3) * 10 + (w_ & 7)] = bp[i_]; \
        } \
    } while (0)

    // ================= proj phase: acc = GS @ Wg2e^T (K = 800) =================
#pragma unroll
    for (int nt = 0; nt < 16; nt++)
#pragma unroll
        for (int q = 0; q < 4; q++) acc[nt][q] = 0.f;

    const float* gsA = g_GS + (size_t)m0 * (2*HG);
    LDCHUNK(g_Bp);
    for (int kt = 0; kt < 50; kt++) {
        __syncthreads();
        STCHUNK();
        if (kt + 1 < 50) LDCHUNK(g_Bp + (size_t)(kt + 1) * 4096);
        __syncthreads();
        float2 x0 = *(const float2*)(gsA + (size_t)rlo * 800 + kt * 16 + 2 * c4);
        float2 x2 = *(const float2*)(gsA + (size_t)rlo * 800 + kt * 16 + 2 * c4 + 8);
        float2 x1 = *(const float2*)(gsA + (size_t)rhi * 800 + kt * 16 + 2 * c4);
        float2 x3 = *(const float2*)(gsA + (size_t)rhi * 800 + kt * 16 + 2 * c4 + 8);
        unsigned a0h, a0l, a1h, a1l, a2h, a2l, a3h, a3l;
        splitpack(x0.x, x0.y, a0h, a0l);
        splitpack(x1.x, x1.y, a1h, a1l);
        splitpack(x2.x, x2.y, a2h, a2l);
        splitpack(x3.x, x3.y, a3h, a3l);
#pragma unroll
        for (int nt = 0; nt < 16; nt++) {
            int n = nh * 128 + nt * 8 + r4;
            uint2 Bh = *(uint2*)&Bsm[n * 10 + 2 * c4];
            uint2 Bl = *(uint2*)&Bsm[2560 + n * 10 + 2 * c4];
            mma16816(acc[nt], a0h, a1h, a2h, a3h, Bh.x, Bh.y);
            mma16816(acc[nt], a0h, a1h, a2h, a3h, Bl.x, Bl.y);
            mma16816(acc[nt], a0l, a1l, a2l, a3l, Bh.x, Bh.y);
        }
    }
    __syncthreads();
#pragma unroll
    for (int ntp = 0; ntp < 8; ntp++) {
        int nt = ntp * 2;
        int nb0 = nh * 128 + nt * 8 + 2 * c4;
        int nb1 = nb0 + 8;
        float p00 = acc[nt][0] + sbg[nb0],   p01 = acc[nt][1] + sbg[nb0+1];
        float p10 = acc[nt+1][0] + sbg[nb1], p11 = acc[nt+1][1] + sbg[nb1+1];
        float q00 = acc[nt][2] + sbg[nb0],   q01 = acc[nt][3] + sbg[nb0+1];
        float q10 = acc[nt+1][2] + sbg[nb1], q11 = acc[nt+1][3] + sbg[nb1+1];
        unsigned he0, le0, he1, le1;
        int wlo = rlo * AST + (nh * 8 + ntp) * 8 + 2 * c4;
        int whi = rhi * AST + (nh * 8 + ntp) * 8 + 2 * c4;
        splitpack(p00, p01, he0, le0); splitpack(p10, p11, he1, le1);
        *(uint2*)&Ah[wlo] = make_uint2(he0, he1);
        *(uint2*)&Al[wlo] = make_uint2(le0, le1);
        splitpack(q00, q01, he0, le0); splitpack(q10, q11, he1, le1);
        *(uint2*)&Ah[whi] = make_uint2(he0, he1);
        *(uint2*)&Al[whi] = make_uint2(le0, le1);
    }
    __syncthreads();

    // ================= 20 estep iterations =================
    for (int st = 0; st < MST; st++) {
#pragma unroll
        for (int nt = 0; nt < 16; nt++)
#pragma unroll
            for (int q = 0; q < 4; q++) acc[nt][q] = 0.f;

        LDCHUNK(g_Be);
        for (int kt = 0; kt < 16; kt++) {
            __syncthreads();
            STCHUNK();
            if (kt + 1 < 16) LDCHUNK(g_Be + (size_t)(kt + 1) * 4096);
            __syncthreads();
            uint2 UA  = *(uint2*)&Ah[rlo * AST + kt * 8 + 2 * c4];
            uint2 VA  = *(uint2*)&Ah[rhi * AST + kt * 8 + 2 * c4];
            uint2 UAl = *(uint2*)&Al[rlo * AST + kt * 8 + 2 * c4];
            uint2 VAl = *(uint2*)&Al[rhi * AST + kt * 8 + 2 * c4];
#pragma unroll
            for (int nt = 0; nt < 16; nt++) {
                int n = nh * 128 + nt * 8 + r4;
                uint2 Bh = *(uint2*)&Bsm[n * 10 + 2 * c4];
                uint2 Bl = *(uint2*)&Bsm[2560 + n * 10 + 2 * c4];
                mma16816(acc[nt], UA.x, VA.x, UA.y, VA.y, Bh.x, Bh.y);
                mma16816(acc[nt], UA.x, VA.x, UA.y, VA.y, Bl.x, Bl.y);
                mma16816(acc[nt], UAl.x, VAl.x, UAl.y, VAl.y, Bh.x, Bh.y);
            }
        }
        __syncthreads();

        float xel = xs[rlo], xeh = xs[rhi];
        float pl = 0.f, ph = 0.f;
#pragma unroll
        for (int ntp = 0; ntp < 8; ntp++) {
            int nt = ntp * 2;
            int nb0 = nh * 128 + nt * 8 + 2 * c4;
            int nb1 = nb0 + 8;
            float b00 = sbe[nb0], b01 = sbe[nb0+1], b10 = sbe[nb1], b11 = sbe[nb1+1];
            float w00 = swi[nb0], w01 = swi[nb0+1], w10 = swi[nb1], w11 = swi[nb1+1];
            float h00 = tanhfast(acc[nt][0]   + b00 + xel * w00);
            float h01 = tanhfast(acc[nt][1]   + b01 + xel * w01);
            float h10 = tanhfast(acc[nt+1][0] + b10 + xel * w10);
            float h11 = tanhfast(acc[nt+1][1] + b11 + xel * w11);
            float g00 = tanhfast(acc[nt][2]   + b00 + xeh * w00);
            float g01 = tanhfast(acc[nt][3]   + b01 + xeh * w01);
            float g10 = tanhfast(acc[nt+1][2] + b10 + xeh * w10);
            float g11 = tanhfast(acc[nt+1][3] + b11 + xeh * w11);
            float c00 = swc[nb0], c01 = swc[nb0+1], c10 = swc[nb1], c11 = swc[nb1+1];
            pl += h00 * c00 + h01 * c01 + h10 * c10 + h11 * c11;
            ph += g00 * c00 + g01 * c01 + g10 * c10 + g11 * c11;
            unsigned he0, le0, he1, le1;
            int wlo = rlo * AST + (nh * 8 + ntp) * 8 + 2 * c4;
            int whi = rhi * AST + (nh * 8 + ntp) * 8 + 2 * c4;
            splitpack(h00, h01, he0, le0); splitpack(h10, h11, he1, le1);
            *(uint2*)&Ah[wlo] = make_uint2(he0, he1);
            *(uint2*)&Al[wlo] = make_uint2(le0, le1);
            splitpack(g00, g01, he0, le0); splitpack(g10, g11, he1, le1);
            *(uint2*)&Ah[whi] = make_uint2(he0, he1);
            *(uint2*)&Al[whi] = make_uint2(le0, le1);
        }
        pl += __shfl_xor_sync(0xffffffffu, pl, 1);
        pl += __shfl_xor_sync(0xffffffffu, pl, 2);
        ph += __shfl_xor_sync(0xffffffffu, ph, 1);
        ph += __shfl_xor_sync(0xffffffffu, ph, 2);
        if (c4 == 0) {
            lp[wid * 16 + r4]     = pl;
            lp[wid * 16 + 8 + r4] = ph;
        }
        __syncthreads();
        if (tid < 64) {
            int mwr = tid >> 4, ir = tid & 15;
            float logit = lp[mwr * 16 + ir] + lp[(mwr + 4) * 16 + ir] + bcl;
            g_Ap[(size_t)(m0 + tid) * MST + st] = logit;
            xs[tid] = logit;
        }
        __syncthreads();
    }
#undef LDCHUNK
#undef STCHUNK
}

// ---------------- arc band gather ----------------
__global__ void k_arc(float* __restrict__ out) {
    size_t idx = (size_t)blockIdx.x * blockDim.x + threadIdx.x;
    size_t total = (size_t)BB * SL * SL;
    if (idx >= total) return;
    int c = (int)(idx % SL);
    int r = (int)((idx / SL) % SL);
    int b = (int)(idx / ((size_t)SL * SL));
    int start = r - MST; if (start < 0) start = 0;
    float v = 0.f;
    if (c >= start && c < r) v = g_Ap[(size_t)(b * SL + r) * MST + (c - start)];
    out[idx] = v;
}

// ---------------- host launcher ----------------
extern "C" void kernel_launch(void* const* d_in, const int* in_sizes, int n_in,
                              void* d_out, int out_size) {
    const float* input  = (const float*)d_in[0];
    const float* tagemb = (const float*)d_in[1];
    const int*   mask   = (const int*)d_in[2];
    const float* sent   = (const float*)d_in[3];
    const float* Wih_f  = (const float*)d_in[4];
    const float* Whh_f  = (const float*)d_in[5];
    const float* bih_f  = (const float*)d_in[6];
    const float* bhh_f  = (const float*)d_in[7];
    const float* Wih_b  = (const float*)d_in[8];
    const float* Whh_b  = (const float*)d_in[9];
    const float* bih_b  = (const float*)d_in[10];
    const float* bhh_b  = (const float*)d_in[11];
    const float* Wg2e   = (const float*)d_in[12];
    const float* bg2e   = (const float*)d_in[13];
    const float* Wih_e  = (const float*)d_in[14];
    const float* Whh_e  = (const float*)d_in[15];
    const float* bih_e  = (const float*)d_in[16];
    const float* bhh_e  = (const float*)d_in[17];
    const float* Wcls   = (const float*)d_in[18];
    const float* bcls   = (const float*)d_in[19];
    const float* bos    = (const float*)d_in[20];
    const float* Wht    = (const float*)d_in[21];
    const float* bht    = (const float*)d_in[22];
    const float* Wdt    = (const float*)d_in[23];
    const float* bdt    = (const float*)d_in[24];
    float* out = (float*)d_out;

    float *pX, *pPre, *pGS, *pbFB, *pbTag;
    unsigned *pBpre, *pBtag;
    cudaGetSymbolAddress((void**)&pX, g_X);
    cudaGetSymbolAddress((void**)&pPre, g_Pre);
    cudaGetSymbolAddress((void**)&pGS, g_GS);
    cudaGetSymbolAddress((void**)&pbFB, g_biasFB);
    cudaGetSymbolAddress((void**)&pbTag, g_biasTag);
    cudaGetSymbolAddress((void**)&pBpre, g_Bpre);
    cudaGetSymbolAddress((void**)&pBtag, g_Btag);

    static int smem_set = 0;
    if (!smem_set) {
        cudaFuncSetAttribute(k_eloop, cudaFuncAttributeMaxDynamicSharedMemorySize, ELOOP_SMEM);
        smem_set = 1;
    }

    // 1. fused setup (weights + pre-split B fragments + inputs)
    {
        size_t n = TSETUP;
        k_setup<<<(unsigned)((n + 255) / 256), 256>>>(Wih_f, Wih_b, Wg2e, Whh_e, Wht, Wdt,
                                                      bih_f, bhh_f, bih_b, bhh_b,
                                                      bih_e, bhh_e, bht, bdt,
                                                      input, tagemb, sent, mask);
    }
    // 2. Pre GEMM (split-bf16 HMMA, N=896 padded, K=896)
    {
        dim3 grid(NPRE / 128, MR / 128);
        k_hgemm<0><<<grid, 256>>>(pX, pBpre, pbFB, pPre, nullptr, NPRE, DL, NPRE);
    }
    // 3. bidirectional recurrence
    k_rnn<<<128, 256>>>(Whh_f, Whh_b);
    // 4. tensor-core proj + estep chain (single launch)
    k_eloop<<<MR / 64, 256, ELOOP_SMEM>>>(Wih_e, Wcls, bcls, bos, bg2e);
    // 5. head/dep tags GEMM (split-bf16 HMMA, K=800, ELU + split store)
    {
        dim3 grid(2, MR / 128);
        k_hgemm<2><<<grid, 256>>>(pGS, pBtag, pbTag, out, out + (size_t)MR * TAGL,
                                  2 * TAGL, 2 * HG, 2 * TAGL);
    }
    // 6. arc logits
    {
        size_t total = (size_t)BB * SL * SL;
        k_arc<<<(unsigned)((total + 255) / 256), 256>>>(out + 2 * (size_t)MR * TAGL);
    }
    (void)in_sizes; (void)n_in; (void)out_size;
}

// round 9
// speedup vs baseline: 2.1827x; 1.7606x over previous
#include <cuda_runtime.h>
#include <cuda_bf16.h>
#include <math.h>

#define BB   64
#define TL   383
#define SL   384
#define DL   896
#define HG   400
#define HEH  256
#define TAGL 128
#define MST  20
#define MR   (BB*SL)    // 24576
#define NPRE 896        // padded 2*HG

// ---------------- scratch (device globals) ----------------
__device__ float g_X[(size_t)MR*DL];
__device__ float g_Mf[MR];
__device__ float g_Pre[(size_t)MR*NPRE];
__device__ float g_GS[(size_t)MR*2*HG];
__device__ float g_Ap[MR*MST];
__device__ float g_biasFB[NPRE];
__device__ float g_biasE[HEH];
__device__ float g_biasTag[2*TAGL];
// pre-split bf16 B fragment arrays: [kt][split][n][slot], words of bf16x2
__device__ unsigned g_Be[16*2*2048];      // Whh_e^T   (K=256, N=256)
__device__ unsigned g_Bp[50*2*2048];      // Wg2e^T    (K=800, N=256)
__device__ unsigned g_Bpre[56*2*7168];    // [Wih_f|Wih_b]^T padded (K=896, N=896)
__device__ unsigned g_Btag[50*2*2048];    // [Wht|Wdt]^T (K=800, N=256)
__device__ unsigned g_Bw[16*25600];       // Whh fragments: [dir*8+jg][kt 25][split 2][n 64][slot 8]
// H exchange in packed fragment form: [cluster 4][pp 2][split 2][b 32][word 200]
__device__ unsigned g_HXP[4*2*2*32*200];

#define CLUSTER_SYNC_() do { \
    asm volatile("barrier.cluster.arrive.aligned;" ::: "memory"); \
    asm volatile("barrier.cluster.wait.aligned;" ::: "memory"); \
} while (0)

// ---------------- helpers ----------------
__device__ __forceinline__ void splitpack(float x0, float x1, unsigned& hi, unsigned& lo) {
    __nv_bfloat16 b0 = __float2bfloat16_rn(x0);
    __nv_bfloat16 b1 = __float2bfloat16_rn(x1);
    float r0 = x0 - __bfloat162float(b0);
    float r1 = x1 - __bfloat162float(b1);
    __nv_bfloat16 c0 = __float2bfloat16_rn(r0);
    __nv_bfloat16 c1 = __float2bfloat16_rn(r1);
    hi = (unsigned)__bfloat16_as_ushort(b0) | ((unsigned)__bfloat16_as_ushort(b1) << 16);
    lo = (unsigned)__bfloat16_as_ushort(c0) | ((unsigned)__bfloat16_as_ushort(c1) << 16);
}

__device__ __forceinline__ void mma16816(float* d, unsigned a0, unsigned a1, unsigned a2,
                                         unsigned a3, unsigned b0, unsigned b1) {
    asm volatile(
        "mma.sync.aligned.m16n8k16.row.col.f32.bf16.bf16.f32 "
        "{%0,%1,%2,%3},{%4,%5,%6,%7},{%8,%9},{%0,%1,%2,%3};"
        : "+f"(d[0]), "+f"(d[1]), "+f"(d[2]), "+f"(d[3])
        : "r"(a0), "r"(a1), "r"(a2), "r"(a3), "r"(b0), "r"(b1));
}

__device__ __forceinline__ float tanhfast(float x) {
    float e = __expf(2.f * x);
    return 1.f - __fdividef(2.f, e + 1.f);
}

// word position p within a k-row for even k: k(p) = (p>>3)*16 + 2*((p&7)>>1) + 8*((p&7)&1)
__device__ __forceinline__ int word_of_k(int k) {
    int kt = k >> 4, rem = k & 15;
    int s = (rem < 8) ? rem : (rem - 7);
    return kt * 8 + s;
}

// ---------------- fused setup ----------------
#define S1 (56*2*7168)   // g_Bpre
#define S2 (50*2*2048)   // g_Bp
#define S3 (16*2*2048)   // g_Be
#define S4 (50*2*2048)   // g_Btag
#define S5 (16*25600)    // g_Bw
#define S6 (NPRE)
#define S7 (HEH)
#define S8 (2*TAGL)
#define TPREP (S1+S2+S3+S4+S5+S6+S7+S8)
#define TBUILD ((size_t)MR*DL + MR)
#define TSETUP (TPREP + TBUILD)

__global__ void k_setup(const float* __restrict__ Wih_f, const float* __restrict__ Wih_b,
                        const float* __restrict__ Wg2e, const float* __restrict__ Whh_e,
                        const float* __restrict__ Wht,  const float* __restrict__ Wdt,
                        const float* __restrict__ Whh_f, const float* __restrict__ Whh_b,
                        const float* __restrict__ bih_f, const float* __restrict__ bhh_f,
                        const float* __restrict__ bih_b, const float* __restrict__ bhh_b,
                        const float* __restrict__ bih_e, const float* __restrict__ bhh_e,
                        const float* __restrict__ bht,   const float* __restrict__ bdt,
                        const float* __restrict__ inp, const float* __restrict__ tag,
                        const float* __restrict__ sent, const int* __restrict__ mask) {
    size_t gidx = (size_t)blockIdx.x * blockDim.x + threadIdx.x;
    if (gidx < TPREP) {
        int idx = (int)gidx;
        if (idx < S1) {   // g_Bpre: K=896, N=896 (n>=800 zero)
            int kt = idx / 14336, rest = idx % 14336;
            int split = rest / 7168, w = rest % 7168;
            int n = w >> 3, s = w & 7;
            int k = kt * 16 + 2 * (s >> 1) + 8 * (s & 1);
            float x0 = 0.f, x1 = 0.f;
            if (n < HG)          { x0 = Wih_f[(size_t)n * DL + k];        x1 = Wih_f[(size_t)n * DL + k + 1]; }
            else if (n < 2*HG)   { x0 = Wih_b[(size_t)(n-HG) * DL + k];   x1 = Wih_b[(size_t)(n-HG) * DL + k + 1]; }
            unsigned hi, lo; splitpack(x0, x1, hi, lo);
            g_Bpre[idx] = split ? lo : hi; return;
        }
        idx -= S1;
        if (idx < S2) {   // g_Bp from Wg2e, K=800, N=256
            int kt = idx >> 12, rest = idx & 4095;
            int split = rest >> 11, w = rest & 2047;
            int n = w >> 3, s = w & 7;
            int k = kt * 16 + 2 * (s >> 1) + 8 * (s & 1);
            float x0 = Wg2e[(size_t)n * (2*HG) + k];
            float x1 = Wg2e[(size_t)n * (2*HG) + k + 1];
            unsigned hi, lo; splitpack(x0, x1, hi, lo);
            g_Bp[idx] = split ? lo : hi; return;
        }
        idx -= S2;
        if (idx < S3) {   // g_Be from Whh_e, K=256
            int kt = idx >> 12, rest = idx & 4095;
            int split = rest >> 11, w = rest & 2047;
            int n = w >> 3, s = w & 7;
            int k = kt * 16 + 2 * (s >> 1) + 8 * (s & 1);
            float x0 = Whh_e[(size_t)n * HEH + k];
            float x1 = Whh_e[(size_t)n * HEH + k + 1];
            unsigned hi, lo; splitpack(x0, x1, hi, lo);
            g_Be[idx] = split ? lo : hi; return;
        }
        idx -= S3;
        if (idx < S4) {   // g_Btag: [Wht|Wdt], K=800, N=256
            int kt = idx >> 12, rest = idx & 4095;
            int split = rest >> 11, w = rest & 2047;
            int n = w >> 3, s = w & 7;
            int k = kt * 16 + 2 * (s >> 1) + 8 * (s & 1);
            float x0, x1;
            if (n < TAGL) { x0 = Wht[(size_t)n * (2*HG) + k];        x1 = Wht[(size_t)n * (2*HG) + k + 1]; }
            else          { x0 = Wdt[(size_t)(n-TAGL) * (2*HG) + k]; x1 = Wdt[(size_t)(n-TAGL) * (2*HG) + k + 1]; }
            unsigned hi, lo; splitpack(x0, x1, hi, lo);
            g_Btag[idx] = split ? lo : hi; return;
        }
        idx -= S4;
        if (idx < S5) {   // g_Bw: Whh fragments, K=400, N=64 per (dir,jg)
            int ctx = idx / 25600, rest = idx % 25600;
            int dir = ctx >> 3, jgx = ctx & 7;
            int kt = rest >> 10, r2 = rest & 1023;
            int split = r2 >> 9, r3 = r2 & 511;
            int n = r3 >> 3, s = r3 & 7;
            int k = kt * 16 + 2 * (s >> 1) + 8 * (s & 1);
            float x0 = 0.f, x1 = 0.f;
            if (n < 50) {
                const float* W = dir ? Whh_b : Whh_f;
                int j = jgx * 50 + n;
                x0 = W[(size_t)j * HG + k];
                x1 = W[(size_t)j * HG + k + 1];
            }
            unsigned hi, lo; splitpack(x0, x1, hi, lo);
            g_Bw[idx] = split ? lo : hi; return;
        }
        idx -= S5;
        if (idx < S6) {
            float v = 0.f;
            if (idx < HG) v = bih_f[idx] + bhh_f[idx];
            else if (idx < 2*HG) v = bih_b[idx-HG] + bhh_b[idx-HG];
            g_biasFB[idx] = v; return;
        }
        idx -= S6;
        if (idx < S7) { g_biasE[idx] = bih_e[idx] + bhh_e[idx]; return; }
        idx -= S7;
        g_biasTag[idx] = (idx < TAGL) ? bht[idx] : bdt[idx - TAGL];
        return;
    }
    gidx -= TPREP;
    size_t nx = (size_t)MR * DL;
    if (gidx < nx) {
        int d = (int)(gidx % DL);
        int m = (int)(gidx / DL);
        int b = m / SL, s = m % SL;
        float v;
        if (s == 0) v = sent[d];
        else {
            int t = s - 1;
            v = (d < 768) ? inp[(size_t)(b * TL + t) * 768 + d]
                          : tag[(size_t)(b * TL + t) * TAGL + (d - 768)];
        }
        g_X[gidx] = v;
        return;
    }
    gidx -= nx;
    if (gidx < MR) {
        int b = (int)(gidx / SL), s = (int)(gidx % SL);
        g_Mf[gidx] = (s == 0) ? 1.0f : (float)mask[b * TL + s - 1];
    }
}

// ---------------- split-bf16 HMMA GEMM, 128x128 tile ----------------
template <int ACT>
__global__ __launch_bounds__(256) void k_hgemm(const float* __restrict__ A,
                                               const unsigned* __restrict__ Bfrag,
                                               const float* __restrict__ bias,
                                               float* __restrict__ C, float* __restrict__ C2,
                                               int N, int K, int Nfrag) {
    __shared__ __align__(16) unsigned Ahs[1280];
    __shared__ __align__(16) unsigned Als[1280];
    __shared__ __align__(16) unsigned Bsm[2560];
    int m0 = blockIdx.y * 128, n0 = blockIdx.x * 128;
    int tid = threadIdx.x, wid = tid >> 5, lane = tid & 31;
    int mw = wid & 3, nh = wid >> 2;
    int r4 = lane >> 2, c4 = lane & 3;
    int nkt = K >> 4;
    int Nw8 = Nfrag * 8;

    int arow = tid >> 1, sg = (tid & 1) * 4;
    const float* Apt = A + (size_t)(m0 + arow) * K;

    float2 af[4];
    uint2  bf[4];
    float acc[2][8][4];
#pragma unroll
    for (int mt = 0; mt < 2; mt++)
#pragma unroll
        for (int nt = 0; nt < 8; nt++)
#pragma unroll
            for (int q = 0; q < 4; q++) acc[mt][nt][q] = 0.f;

#define HLD(KT) do { \
        _Pragma("unroll") for (int s_ = 0; s_ < 4; s_++) { \
            int s = sg + s_; int kl = 2 * (s >> 1) + 8 * (s & 1); \
            af[s_] = *(const float2*)(Apt + (KT) * 16 + kl); } \
        _Pragma("unroll") for (int i_ = 0; i_ < 4; i_++) { \
            int lw = 2 * (i_ * 256 + tid); \
            int sp = lw >> 10, wq = lw & 1023; \
            bf[i_] = *(const uint2*)(Bfrag + (size_t)(KT) * 2 * Nw8 + (size_t)sp * Nw8 + n0 * 8 + wq); } \
    } while (0)

#define HST() do { \
        _Pragma("unroll") for (int s_ = 0; s_ < 4; s_++) { \
            unsigned hi_, lo_; splitpack(af[s_].x, af[s_].y, hi_, lo_); \
            Ahs[arow * 10 + sg + s_] = hi_; Als[arow * 10 + sg + s_] = lo_; } \
        _Pragma("unroll") for (int i_ = 0; i_ < 4; i_++) { \
            int lw = 2 * (i_ * 256 + tid); \
            int sp = lw >> 10, wq = lw & 1023; \
            int n_ = wq >> 3, s_ = wq & 7; \
            *(uint2*)&Bsm[sp * 1280 + n_ * 10 + s_] = bf[i_]; } \
    } while (0)

    HLD(0);
    for (int kt = 0; kt < nkt; kt++) {
        __syncthreads();
        HST();
        if (kt + 1 < nkt) HLD(kt + 1);
        __syncthreads();
        uint2 Uh[2], Vh[2], Ul[2], Vl[2];
#pragma unroll
        for (int mt = 0; mt < 2; mt++) {
            int rb = mw * 32 + mt * 16 + r4;
            Uh[mt] = *(uint2*)&Ahs[rb * 10 + 2 * c4];
            Vh[mt] = *(uint2*)&Ahs[(rb + 8) * 10 + 2 * c4];
            Ul[mt] = *(uint2*)&Als[rb * 10 + 2 * c4];
            Vl[mt] = *(uint2*)&Als[(rb + 8) * 10 + 2 * c4];
        }
#pragma unroll
        for (int nt = 0; nt < 8; nt++) {
            int n = nh * 64 + nt * 8 + r4;
            uint2 Bh = *(uint2*)&Bsm[n * 10 + 2 * c4];
            uint2 Bl = *(uint2*)&Bsm[1280 + n * 10 + 2 * c4];
#pragma unroll
            for (int mt = 0; mt < 2; mt++) {
                mma16816(acc[mt][nt], Uh[mt].x, Vh[mt].x, Uh[mt].y, Vh[mt].y, Bh.x, Bh.y);
                mma16816(acc[mt][nt], Uh[mt].x, Vh[mt].x, Uh[mt].y, Vh[mt].y, Bl.x, Bl.y);
                mma16816(acc[mt][nt], Ul[mt].x, Vl[mt].x, Ul[mt].y, Vl[mt].y, Bh.x, Bh.y);
            }
        }
    }
#undef HLD
#undef HST

#pragma unroll
    for (int nt = 0; nt < 8; nt++) {
        int colL = nh * 64 + nt * 8 + 2 * c4;
        float b0 = bias[n0 + colL], b1 = bias[n0 + colL + 1];
#pragma unroll
        for (int mt = 0; mt < 2; mt++) {
            int r = m0 + mw * 32 + mt * 16 + r4;
            float v0 = acc[mt][nt][0] + b0, v1 = acc[mt][nt][1] + b1;
            float v2 = acc[mt][nt][2] + b0, v3 = acc[mt][nt][3] + b1;
            if (ACT == 2) {
                v0 = (v0 > 0.f) ? v0 : expm1f(v0);
                v1 = (v1 > 0.f) ? v1 : expm1f(v1);
                v2 = (v2 > 0.f) ? v2 : expm1f(v2);
                v3 = (v3 > 0.f) ? v3 : expm1f(v3);
                float* dst = (blockIdx.x == 0) ? C : C2;
                *(float2*)(dst + (size_t)r * TAGL + colL)       = make_float2(v0, v1);
                *(float2*)(dst + (size_t)(r + 8) * TAGL + colL) = make_float2(v2, v3);
            } else {
                *(float2*)(C + (size_t)r * N + n0 + colL)       = make_float2(v0, v1);
                *(float2*)(C + (size_t)(r + 8) * N + n0 + colL) = make_float2(v2, v3);
            }
        }
    }
}

// ---------------- HMMA bidirectional masked RNN (cluster-synced) ----------------
// 32 CTAs = 4 clusters of 8. cluster = (dir, 32-batch group); CTA = 32 batches x 50 j (pad 64).
// Whh fragments resident in smem; H exchanged as pre-split fragments via g_HXP (L2).
#define RAS 210      // A-row stride in words
#define RNN_SMEM ((32000 + 2*32*RAS) * 4)

__global__ void __cluster_dims__(8, 1, 1) __launch_bounds__(256, 1) k_rnn() {
    extern __shared__ unsigned rsm[];
    unsigned* Bs = rsm;             // 25 kt x 2 split x 64 n x 10 = 32000 words
    unsigned* Ah = rsm + 32000;     // 32 x 210
    unsigned* Al = Ah + 32 * RAS;

    int bx = blockIdx.x;
    int cl = bx >> 3, jg = bx & 7;
    int dir = cl >> 1, bg = cl & 1;
    int bbase = bg * 32;
    int tid = threadIdx.x, wid = tid >> 5, lane = tid & 31;
    int mw = wid & 1, ng = wid >> 1;
    int r4 = lane >> 2, c4 = lane & 3;
    int rlo = mw * 16 + r4, rhi = rlo + 8;

    // one-time: B fragments -> smem (padded n*10 layout)
    {
        const uint2* bsrc = (const uint2*)(g_Bw + (size_t)(dir * 8 + jg) * 25600);
#pragma unroll
        for (int i = 0; i < 50; i++) {
            int idx = tid + i * 256;      // 12800 uint2
            uint2 v = __ldcg(bsrc + idx);
            int g = idx >> 8, r = idx & 255;
            int n = r >> 2, sp = (r & 3) * 2;
            *(uint2*)&Bs[g * 640 + n * 10 + sp] = v;
        }
    }
    // zero exactly the words this CTA will write (permuted k->word mapping), pp=0
    {
        unsigned* hxp0 = g_HXP + (size_t)(cl * 2 + 0) * 12800;
        for (int idx = tid; idx < 1600; idx += 256) {
            int split = idx / 800, rest = idx % 800;
            int b = rest / 25, w = rest % 25;
            int p = word_of_k(jg * 50 + 2 * w);
            __stcg(&hxp0[split * 6400 + b * 200 + p], 0u);
        }
    }
    __syncthreads();
    CLUSTER_SYNC_();

    // per-lane output columns
    int jl[2], valid[2], wdp[2];
#pragma unroll
    for (int q = 0; q < 2; q++) {
        jl[q] = ng * 16 + q * 8 + 2 * c4;
        valid[q] = (jl[q] < 50);
        wdp[q] = word_of_k(jg * 50 + jl[q]);
    }
    float h[2][2][2];
#pragma unroll
    for (int a = 0; a < 2; a++)
#pragma unroll
        for (int b = 0; b < 2; b++)
#pragma unroll
            for (int c = 0; c < 2; c++) h[a][b][c] = 0.f;

    for (int tv = 0; tv < SL; tv++) {
        int t = dir ? (SL - 1 - tv) : tv;
        int pp = tv & 1;
        const uint2* src = (const uint2*)(g_HXP + (size_t)(cl * 2 + pp) * 12800);
        // stage A fragments (hi+lo, 6400 uint2) + prefetch pre/mask
        uint2 bp[25];
#pragma unroll
        for (int i = 0; i < 25; i++) {
            int idx = tid + i * 256;
            int b2 = idx / 100, wp = idx % 100;
            int split = b2 >> 5, b = b2 & 31;
            bp[i] = __ldcg(src + (size_t)split * 3200 + b * 100 + wp);
        }
        float mv[2];
        mv[0] = g_Mf[(bbase + rlo) * SL + t];
        mv[1] = g_Mf[(bbase + rhi) * SL + t];
        float2 pre[2][2];
#pragma unroll
        for (int rq = 0; rq < 2; rq++) {
            int R = rq ? rhi : rlo;
            size_t mbase = (size_t)((bbase + R) * SL + t) * NPRE + dir * HG + jg * 50;
#pragma unroll
            for (int q = 0; q < 2; q++)
                pre[rq][q] = *(const float2*)(g_Pre + mbase + jl[q]);
        }
#pragma unroll
        for (int i = 0; i < 25; i++) {
            int idx = tid + i * 256;
            int b2 = idx / 100, wp = idx % 100;
            int split = b2 >> 5, b = b2 & 31;
            unsigned* dst = split ? Al : Ah;
            *(uint2*)&dst[b * RAS + wp * 2] = bp[i];
        }
        __syncthreads();

        float acc[2][4];
#pragma unroll
        for (int q = 0; q < 2; q++)
#pragma unroll
            for (int z = 0; z < 4; z++) acc[q][z] = 0.f;
#pragma unroll
        for (int kt = 0; kt < 25; kt++) {
            uint2 UA  = *(uint2*)&Ah[rlo * RAS + kt * 8 + 2 * c4];
            uint2 VA  = *(uint2*)&Ah[rhi * RAS + kt * 8 + 2 * c4];
            uint2 UAl = *(uint2*)&Al[rlo * RAS + kt * 8 + 2 * c4];
            uint2 VAl = *(uint2*)&Al[rhi * RAS + kt * 8 + 2 * c4];
#pragma unroll
            for (int q = 0; q < 2; q++) {
                int n = ng * 16 + q * 8 + r4;
                uint2 Bh = *(uint2*)&Bs[(kt * 2) * 640 + n * 10 + 2 * c4];
                uint2 Bl = *(uint2*)&Bs[(kt * 2 + 1) * 640 + n * 10 + 2 * c4];
                mma16816(acc[q], UA.x, VA.x, UA.y, VA.y, Bh.x, Bh.y);
                mma16816(acc[q], UA.x, VA.x, UA.y, VA.y, Bl.x, Bl.y);
                mma16816(acc[q], UAl.x, VAl.x, UAl.y, VAl.y, Bh.x, Bh.y);
            }
        }
        __syncthreads();   // Ah/Al reads done before next step's staging overwrite

        unsigned* dsth = g_HXP + (size_t)(cl * 2 + (pp ^ 1)) * 12800;
#pragma unroll
        for (int rq = 0; rq < 2; rq++) {
            int R = rq ? rhi : rlo;
            float mt = mv[rq], om = 1.f - mt;
            size_t grow = (size_t)((bbase + R) * SL + t) * (2 * HG) + dir * HG + jg * 50;
#pragma unroll
            for (int q = 0; q < 2; q++) {
                float u0 = mt * tanhfast(pre[rq][q].x + acc[q][rq * 2 + 0]) + om * h[rq][q][0];
                float u1 = mt * tanhfast(pre[rq][q].y + acc[q][rq * 2 + 1]) + om * h[rq][q][1];
                h[rq][q][0] = u0; h[rq][q][1] = u1;
                if (valid[q]) {
                    unsigned hi, lo; splitpack(u0, u1, hi, lo);
                    __stcg(&dsth[R * 200 + wdp[q]], hi);
                    __stcg(&dsth[6400 + R * 200 + wdp[q]], lo);
                    *(float2*)(g_GS + grow + jl[q]) = make_float2(u0 * mt, u1 * mt);
                }
            }
        }
        CLUSTER_SYNC_();
    }
}

// ---------------- tensor-core proj + 20-step estep loop ----------------
#define AST 136
#define ELOOP_WORDS (8704*2 + 5120 + 1024 + 64 + 128)
#define ELOOP_SMEM  (ELOOP_WORDS * 4)

__global__ __launch_bounds__(256, 2) void k_eloop(const float* __restrict__ wie,
                                                  const float* __restrict__ wcls,
                                                  const float* __restrict__ bcls,
                                                  const float* __restrict__ bos,
                                                  const float* __restrict__ bg2e) {
    extern __shared__ unsigned sm_u[];
    unsigned* Ah  = sm_u;
    unsigned* Al  = sm_u + 8704;
    unsigned* Bsm = sm_u + 17408;
    float* sbe = (float*)(sm_u + 22528);
    float* swi = sbe + 256;
    float* swc = sbe + 512;
    float* sbg = sbe + 768;
    float* xs  = sbe + 1024;
    float* lp  = xs + 64;

    int tid = threadIdx.x;
    int wid = tid >> 5, lane = tid & 31;
    int mw = wid & 3, nh = wid >> 2;
    int r4 = lane >> 2, c4 = lane & 3;
    int rlo = mw * 16 + r4, rhi = rlo + 8;
    int m0 = blockIdx.x * 64;

    sbe[tid] = g_biasE[tid & 255];
    swi[tid] = wie[tid & 255];
    swc[tid] = wcls[tid & 255];
    sbg[tid] = bg2e[tid & 255];
    if (tid < 64) xs[tid] = bos[0];
    float bcl = bcls[0];

    float acc[16][4];
    uint2 bp[8];

#define LDCHUNK(gsrc) do { \
        const uint2* s_ = (const uint2*)(gsrc); \
        _Pragma("unroll") for (int i_ = 0; i_ < 8; i_++) bp[i_] = s_[i_ * 256 + tid]; \
    } while (0)
#define STCHUNK() do { \
        _Pragma("unroll") for (int i_ = 0; i_ < 8; i_++) { \
            int j_ = i_ * 256 + tid; \
            int sp_ = j_ >> 10; int w_ = (2 * j_) & 2047; \
            *(uint2*)&Bsm[sp_ * 2560 + (w_ >> 3) * 10 + (w_ & 7)] = bp[i_]; \
        } \
    } while (0)

    // ================= proj phase: acc = GS @ Wg2e^T (K = 800) =================
#pragma unroll
    for (int nt = 0; nt < 16; nt++)
#pragma unroll
        for (int q = 0; q < 4; q++) acc[nt][q] = 0.f;

    const float* gsA = g_GS + (size_t)m0 * (2*HG);
    LDCHUNK(g_Bp);
    for (int kt = 0; kt < 50; kt++) {
        __syncthreads();
        STCHUNK();
        if (kt + 1 < 50) LDCHUNK(g_Bp + (size_t)(kt + 1) * 4096);
        __syncthreads();
        float2 x0 = *(const float2*)(gsA + (size_t)rlo * 800 + kt * 16 + 2 * c4);
        float2 x2 = *(const float2*)(gsA + (size_t)rlo * 800 + kt * 16 + 2 * c4 + 8);
        float2 x1 = *(const float2*)(gsA + (size_t)rhi * 800 + kt * 16 + 2 * c4);
        float2 x3 = *(const float2*)(gsA + (size_t)rhi * 800 + kt * 16 + 2 * c4 + 8);
        unsigned a0h, a0l, a1h, a1l, a2h, a2l, a3h, a3l;
        splitpack(x0.x, x0.y, a0h, a0l);
        splitpack(x1.x, x1.y, a1h, a1l);
        splitpack(x2.x, x2.y, a2h, a2l);
        splitpack(x3.x, x3.y, a3h, a3l);
#pragma unroll
        for (int nt = 0; nt < 16; nt++) {
            int n = nh * 128 + nt * 8 + r4;
            uint2 Bh = *(uint2*)&Bsm[n * 10 + 2 * c4];
            uint2 Bl = *(uint2*)&Bsm[2560 + n * 10 + 2 * c4];
            mma16816(acc[nt], a0h, a1h, a2h, a3h, Bh.x, Bh.y);
            mma16816(acc[nt], a0h, a1h, a2h, a3h, Bl.x, Bl.y);
            mma16816(acc[nt], a0l, a1l, a2l, a3l, Bh.x, Bh.y);
        }
    }
    __syncthreads();
#pragma unroll
    for (int ntp = 0; ntp < 8; ntp++) {
        int nt = ntp * 2;
        int nb0 = nh * 128 + nt * 8 + 2 * c4;
        int nb1 = nb0 + 8;
        float p00 = acc[nt][0] + sbg[nb0],   p01 = acc[nt][1] + sbg[nb0+1];
        float p10 = acc[nt+1][0] + sbg[nb1], p11 = acc[nt+1][1] + sbg[nb1+1];
        float q00 = acc[nt][2] + sbg[nb0],   q01 = acc[nt][3] + sbg[nb0+1];
        float q10 = acc[nt+1][2] + sbg[nb1], q11 = acc[nt+1][3] + sbg[nb1+1];
        unsigned he0, le0, he1, le1;
        int wlo = rlo * AST + (nh * 8 + ntp) * 8 + 2 * c4;
        int whi = rhi * AST + (nh * 8 + ntp) * 8 + 2 * c4;
        splitpack(p00, p01, he0, le0); splitpack(p10, p11, he1, le1);
        *(uint2*)&Ah[wlo] = make_uint2(he0, he1);
        *(uint2*)&Al[wlo] = make_uint2(le0, le1);
        splitpack(q00, q01, he0, le0); splitpack(q10, q11, he1, le1);
        *(uint2*)&Ah[whi] = make_uint2(he0, he1);
        *(uint2*)&Al[whi] = make_uint2(le0, le1);
    }
    __syncthreads();

    // ================= 20 estep iterations =================
    for (int st = 0; st < MST; st++) {
#pragma unroll
        for (int nt = 0; nt < 16; nt++)
#pragma unroll
            for (int q = 0; q < 4; q++) acc[nt][q] = 0.f;

        LDCHUNK(g_Be);
        for (int kt = 0; kt < 16; kt++) {
            __syncthreads();
            STCHUNK();
            if (kt + 1 < 16) LDCHUNK(g_Be + (size_t)(kt + 1) * 4096);
            __syncthreads();
            uint2 UA  = *(uint2*)&Ah[rlo * AST + kt * 8 + 2 * c4];
            uint2 VA  = *(uint2*)&Ah[rhi * AST + kt * 8 + 2 * c4];
            uint2 UAl = *(uint2*)&Al[rlo * AST + kt * 8 + 2 * c4];
            uint2 VAl = *(uint2*)&Al[rhi * AST + kt * 8 + 2 * c4];
#pragma unroll
            for (int nt = 0; nt < 16; nt++) {
                int n = nh * 128 + nt * 8 + r4;
                uint2 Bh = *(uint2*)&Bsm[n * 10 + 2 * c4];
                uint2 Bl = *(uint2*)&Bsm[2560 + n * 10 + 2 * c4];
                mma16816(acc[nt], UA.x, VA.x, UA.y, VA.y, Bh.x, Bh.y);
                mma16816(acc[nt], UA.x, VA.x, UA.y, VA.y, Bl.x, Bl.y);
                mma16816(acc[nt], UAl.x, VAl.x, UAl.y, VAl.y, Bh.x, Bh.y);
            }
        }
        __syncthreads();

        float xel = xs[rlo], xeh = xs[rhi];
        float pl = 0.f, ph = 0.f;
#pragma unroll
        for (int ntp = 0; ntp < 8; ntp++) {
            int nt = ntp * 2;
            int nb0 = nh * 128 + nt * 8 + 2 * c4;
            int nb1 = nb0 + 8;
            float b00 = sbe[nb0], b01 = sbe[nb0+1], b10 = sbe[nb1], b11 = sbe[nb1+1];
            float w00 = swi[nb0], w01 = swi[nb0+1], w10 = swi[nb1], w11 = swi[nb1+1];
            float h00 = tanhfast(acc[nt][0]   + b00 + xel * w00);
            float h01 = tanhfast(acc[nt][1]   + b01 + xel * w01);
            float h10 = tanhfast(acc[nt+1][0] + b10 + xel * w10);
            float h11 = tanhfast(acc[nt+1][1] + b11 + xel * w11);
            float g00 = tanhfast(acc[nt][2]   + b00 + xeh * w00);
            float g01 = tanhfast(acc[nt][3]   + b01 + xeh * w01);
            float g10 = tanhfast(acc[nt+1][2] + b10 + xeh * w10);
            float g11 = tanhfast(acc[nt+1][3] + b11 + xeh * w11);
            float c00 = swc[nb0], c01 = swc[nb0+1], c10 = swc[nb1], c11 = swc[nb1+1];
            pl += h00 * c00 + h01 * c01 + h10 * c10 + h11 * c11;
            ph += g00 * c00 + g01 * c01 + g10 * c10 + g11 * c11;
            unsigned he0, le0, he1, le1;
            int wlo = rlo * AST + (nh * 8 + ntp) * 8 + 2 * c4;
            int whi = rhi * AST + (nh * 8 + ntp) * 8 + 2 * c4;
            splitpack(h00, h01, he0, le0); splitpack(h10, h11, he1, le1);
            *(uint2*)&Ah[wlo] = make_uint2(he0, he1);
            *(uint2*)&Al[wlo] = make_uint2(le0, le1);
            splitpack(g00, g01, he0, le0); splitpack(g10, g11, he1, le1);
            *(uint2*)&Ah[whi] = make_uint2(he0, he1);
            *(uint2*)&Al[whi] = make_uint2(le0, le1);
        }
        pl += __shfl_xor_sync(0xffffffffu, pl, 1);
        pl += __shfl_xor_sync(0xffffffffu, pl, 2);
        ph += __shfl_xor_sync(0xffffffffu, ph, 1);
        ph += __shfl_xor_sync(0xffffffffu, ph, 2);
        if (c4 == 0) {
            lp[wid * 16 + r4]     = pl;
            lp[wid * 16 + 8 + r4] = ph;
        }
        __syncthreads();
        if (tid < 64) {
            int mwr = tid >> 4, ir = tid & 15;
            float logit = lp[mwr * 16 + ir] + lp[(mwr + 4) * 16 + ir] + bcl;
            g_Ap[(size_t)(m0 + tid) * MST + st] = logit;
            xs[tid] = logit;
        }
        __syncthreads();
    }
#undef LDCHUNK
#undef STCHUNK
}

// ---------------- arc band gather ----------------
__global__ void k_arc(float* __restrict__ out) {
    size_t idx = (size_t)blockIdx.x * blockDim.x + threadIdx.x;
    size_t total = (size_t)BB * SL * SL;
    if (idx >= total) return;
    int c = (int)(idx % SL);
    int r = (int)((idx / SL) % SL);
    int b = (int)(idx / ((size_t)SL * SL));
    int start = r - MST; if (start < 0) start = 0;
    float v = 0.f;
    if (c >= start && c < r) v = g_Ap[(size_t)(b * SL + r) * MST + (c - start)];
    out[idx] = v;
}

// ---------------- host launcher ----------------
extern "C" void kernel_launch(void* const* d_in, const int* in_sizes, int n_in,
                              void* d_out, int out_size) {
    const float* input  = (const float*)d_in[0];
    const float* tagemb = (const float*)d_in[1];
    const int*   mask   = (const int*)d_in[2];
    const float* sent   = (const float*)d_in[3];
    const float* Wih_f  = (const float*)d_in[4];
    const float* Whh_f  = (const float*)d_in[5];
    const float* bih_f  = (const float*)d_in[6];
    const float* bhh_f  = (const float*)d_in[7];
    const float* Wih_b  = (const float*)d_in[8];
    const float* Whh_b  = (const float*)d_in[9];
    const float* bih_b  = (const float*)d_in[10];
    const float* bhh_b  = (const float*)d_in[11];
    const float* Wg2e   = (const float*)d_in[12];
    const float* bg2e   = (const float*)d_in[13];
    const float* Wih_e  = (const float*)d_in[14];
    const float* Whh_e  = (const float*)d_in[15];
    const float* bih_e  = (const float*)d_in[16];
    const float* bhh_e  = (const float*)d_in[17];
    const float* Wcls   = (const float*)d_in[18];
    const float* bcls   = (const float*)d_in[19];
    const float* bos    = (const float*)d_in[20];
    const float* Wht    = (const float*)d_in[21];
    const float* bht    = (const float*)d_in[22];
    const float* Wdt    = (const float*)d_in[23];
    const float* bdt    = (const float*)d_in[24];
    float* out = (float*)d_out;

    float *pX, *pPre, *pGS, *pbFB, *pbTag;
    unsigned *pBpre, *pBtag;
    cudaGetSymbolAddress((void**)&pX, g_X);
    cudaGetSymbolAddress((void**)&pPre, g_Pre);
    cudaGetSymbolAddress((void**)&pGS, g_GS);
    cudaGetSymbolAddress((void**)&pbFB, g_biasFB);
    cudaGetSymbolAddress((void**)&pbTag, g_biasTag);
    cudaGetSymbolAddress((void**)&pBpre, g_Bpre);
    cudaGetSymbolAddress((void**)&pBtag, g_Btag);

    static int smem_set = 0;
    if (!smem_set) {
        cudaFuncSetAttribute(k_eloop, cudaFuncAttributeMaxDynamicSharedMemorySize, ELOOP_SMEM);
        cudaFuncSetAttribute(k_rnn, cudaFuncAttributeMaxDynamicSharedMemorySize, RNN_SMEM);
        smem_set = 1;
    }

    // 1. fused setup (weights + pre-split B fragments + inputs)
    {
        size_t n = TSETUP;
        k_setup<<<(unsigned)((n + 255) / 256), 256>>>(Wih_f, Wih_b, Wg2e, Whh_e, Wht, Wdt,
                                                      Whh_f, Whh_b,
                                                      bih_f, bhh_f, bih_b, bhh_b,
                                                      bih_e, bhh_e, bht, bdt,
                                                      input, tagemb, sent, mask);
    }
    // 2. Pre GEMM (split-bf16 HMMA, N=896 padded, K=896)
    {
        dim3 grid(NPRE / 128, MR / 128);
        k_hgemm<0><<<grid, 256>>>(pX, pBpre, pbFB, pPre, nullptr, NPRE, DL, NPRE);
    }
    // 3. bidirectional recurrence (HMMA, 4 clusters of 8 CTAs)
    k_rnn<<<32, 256, RNN_SMEM>>>();
    // 4. tensor-core proj + estep chain (single launch)
    k_eloop<<<MR / 64, 256, ELOOP_SMEM>>>(Wih_e, Wcls, bcls, bos, bg2e);
    // 5. head/dep tags GEMM (split-bf16 HMMA, K=800, ELU + split store)
    {
        dim3 grid(2, MR / 128);
        k_hgemm<2><<<grid, 256>>>(pGS, pBtag, pbTag, out, out + (size_t)MR * TAGL,
                                  2 * TAGL, 2 * HG, 2 * TAGL);
    }
    // 6. arc logits
    {
        size_t total = (size_t)BB * SL * SL;
        k_arc<<<(unsigned)((total + 255) / 256), 256>>>(out + 2 * (size_t)MR * TAGL);
    }
    (void)in_sizes; (void)n_in; (void)out_size;
}

// round 10
// speedup vs baseline: 2.6536x; 1.2157x over previous
#include <cuda_runtime.h>
#include <cuda_bf16.h>
#include <math.h>

#define BB   64
#define TL   383
#define SL   384
#define DL   896
#define HG   400
#define HEH  256
#define TAGL 128
#define MST  20
#define MR   (BB*SL)    // 24576
#define NPRE 896        // padded 2*HG

// ---------------- scratch (device globals) ----------------
__device__ float g_X[(size_t)MR*DL];
__device__ float g_Mf[MR];
__device__ float g_Pre[(size_t)MR*NPRE];
__device__ float g_GS[(size_t)MR*2*HG];
__device__ float g_Ap[MR*MST];
__device__ float g_biasFB[NPRE];
__device__ float g_biasE[HEH];
__device__ float g_biasTag[2*TAGL];
// pre-split bf16 B fragment arrays: [kt][split][n][slot], words of bf16x2
__device__ unsigned g_Be[16*2*2048];      // Whh_e^T   (K=256, N=256)
__device__ unsigned g_Bp[50*2*2048];      // Wg2e^T    (K=800, N=256)
__device__ unsigned g_Bpre[56*2*7168];    // [Wih_f|Wih_b]^T padded (K=896, N=896)
__device__ unsigned g_Btag[50*2*2048];    // [Wht|Wdt]^T (K=800, N=256)
__device__ unsigned g_Bw[16*25600];       // Whh fragments: [dir*8+jg][kt 25][split 2][n 64][slot 8]
// H exchange in packed fragment form: [cluster 4][pp 2][split 2][b 32][word 200]
__device__ unsigned g_HXP[4*2*2*32*200];

#define CLUSTER_SYNC_() do { \
    asm volatile("barrier.cluster.arrive.aligned;" ::: "memory"); \
    asm volatile("barrier.cluster.wait.aligned;" ::: "memory"); \
} while (0)

// ---------------- helpers ----------------
__device__ __forceinline__ void splitpack(float x0, float x1, unsigned& hi, unsigned& lo) {
    __nv_bfloat16 b0 = __float2bfloat16_rn(x0);
    __nv_bfloat16 b1 = __float2bfloat16_rn(x1);
    float r0 = x0 - __bfloat162float(b0);
    float r1 = x1 - __bfloat162float(b1);
    __nv_bfloat16 c0 = __float2bfloat16_rn(r0);
    __nv_bfloat16 c1 = __float2bfloat16_rn(r1);
    hi = (unsigned)__bfloat16_as_ushort(b0) | ((unsigned)__bfloat16_as_ushort(b1) << 16);
    lo = (unsigned)__bfloat16_as_ushort(c0) | ((unsigned)__bfloat16_as_ushort(c1) << 16);
}

__device__ __forceinline__ void mma16816(float* d, unsigned a0, unsigned a1, unsigned a2,
                                         unsigned a3, unsigned b0, unsigned b1) {
    asm volatile(
        "mma.sync.aligned.m16n8k16.row.col.f32.bf16.bf16.f32 "
        "{%0,%1,%2,%3},{%4,%5,%6,%7},{%8,%9},{%0,%1,%2,%3};"
        : "+f"(d[0]), "+f"(d[1]), "+f"(d[2]), "+f"(d[3])
        : "r"(a0), "r"(a1), "r"(a2), "r"(a3), "r"(b0), "r"(b1));
}

__device__ __forceinline__ float tanhfast(float x) {
    float e = __expf(2.f * x);
    return 1.f - __fdividef(2.f, e + 1.f);
}

// word position p within a k-row: k(p) = (p>>3)*16 + 2*((p&7)>>1) + 8*((p&7)&1)
__device__ __forceinline__ int word_of_k(int k) {
    int kt = k >> 4, rem = k & 15;
    int s = (rem < 8) ? rem : (rem - 7);
    return kt * 8 + s;
}

// ---------------- fused setup ----------------
#define S1 (56*2*7168)   // g_Bpre
#define S2 (50*2*2048)   // g_Bp
#define S3 (16*2*2048)   // g_Be
#define S4 (50*2*2048)   // g_Btag
#define S5 (16*25600)    // g_Bw
#define S6 (NPRE)
#define S7 (HEH)
#define S8 (2*TAGL)
#define TPREP (S1+S2+S3+S4+S5+S6+S7+S8)
#define TBUILD ((size_t)MR*DL + MR)
#define TSETUP (TPREP + TBUILD)

__global__ void k_setup(const float* __restrict__ Wih_f, const float* __restrict__ Wih_b,
                        const float* __restrict__ Wg2e, const float* __restrict__ Whh_e,
                        const float* __restrict__ Wht,  const float* __restrict__ Wdt,
                        const float* __restrict__ Whh_f, const float* __restrict__ Whh_b,
                        const float* __restrict__ bih_f, const float* __restrict__ bhh_f,
                        const float* __restrict__ bih_b, const float* __restrict__ bhh_b,
                        const float* __restrict__ bih_e, const float* __restrict__ bhh_e,
                        const float* __restrict__ bht,   const float* __restrict__ bdt,
                        const float* __restrict__ inp, const float* __restrict__ tag,
                        const float* __restrict__ sent, const int* __restrict__ mask) {
    size_t gidx = (size_t)blockIdx.x * blockDim.x + threadIdx.x;
    if (gidx < TPREP) {
        int idx = (int)gidx;
        if (idx < S1) {
            int kt = idx / 14336, rest = idx % 14336;
            int split = rest / 7168, w = rest % 7168;
            int n = w >> 3, s = w & 7;
            int k = kt * 16 + 2 * (s >> 1) + 8 * (s & 1);
            float x0 = 0.f, x1 = 0.f;
            if (n < HG)          { x0 = Wih_f[(size_t)n * DL + k];        x1 = Wih_f[(size_t)n * DL + k + 1]; }
            else if (n < 2*HG)   { x0 = Wih_b[(size_t)(n-HG) * DL + k];   x1 = Wih_b[(size_t)(n-HG) * DL + k + 1]; }
            unsigned hi, lo; splitpack(x0, x1, hi, lo);
            g_Bpre[idx] = split ? lo : hi; return;
        }
        idx -= S1;
        if (idx < S2) {
            int kt = idx >> 12, rest = idx & 4095;
            int split = rest >> 11, w = rest & 2047;
            int n = w >> 3, s = w & 7;
            int k = kt * 16 + 2 * (s >> 1) + 8 * (s & 1);
            float x0 = Wg2e[(size_t)n * (2*HG) + k];
            float x1 = Wg2e[(size_t)n * (2*HG) + k + 1];
            unsigned hi, lo; splitpack(x0, x1, hi, lo);
            g_Bp[idx] = split ? lo : hi; return;
        }
        idx -= S2;
        if (idx < S3) {
            int kt = idx >> 12, rest = idx & 4095;
            int split = rest >> 11, w = rest & 2047;
            int n = w >> 3, s = w & 7;
            int k = kt * 16 + 2 * (s >> 1) + 8 * (s & 1);
            float x0 = Whh_e[(size_t)n * HEH + k];
            float x1 = Whh_e[(size_t)n * HEH + k + 1];
            unsigned hi, lo; splitpack(x0, x1, hi, lo);
            g_Be[idx] = split ? lo : hi; return;
        }
        idx -= S3;
        if (idx < S4) {
            int kt = idx >> 12, rest = idx & 4095;
            int split = rest >> 11, w = rest & 2047;
            int n = w >> 3, s = w & 7;
            int k = kt * 16 + 2 * (s >> 1) + 8 * (s & 1);
            float x0, x1;
            if (n < TAGL) { x0 = Wht[(size_t)n * (2*HG) + k];        x1 = Wht[(size_t)n * (2*HG) + k + 1]; }
            else          { x0 = Wdt[(size_t)(n-TAGL) * (2*HG) + k]; x1 = Wdt[(size_t)(n-TAGL) * (2*HG) + k + 1]; }
            unsigned hi, lo; splitpack(x0, x1, hi, lo);
            g_Btag[idx] = split ? lo : hi; return;
        }
        idx -= S4;
        if (idx < S5) {
            int ctx = idx / 25600, rest = idx % 25600;
            int dir = ctx >> 3, jgx = ctx & 7;
            int kt = rest >> 10, r2 = rest & 1023;
            int split = r2 >> 9, r3 = r2 & 511;
            int n = r3 >> 3, s = r3 & 7;
            int k = kt * 16 + 2 * (s >> 1) + 8 * (s & 1);
            float x0 = 0.f, x1 = 0.f;
            if (n < 50) {
                const float* W = dir ? Whh_b : Whh_f;
                int j = jgx * 50 + n;
                x0 = W[(size_t)j * HG + k];
                x1 = W[(size_t)j * HG + k + 1];
            }
            unsigned hi, lo; splitpack(x0, x1, hi, lo);
            g_Bw[idx] = split ? lo : hi; return;
        }
        idx -= S5;
        if (idx < S6) {
            float v = 0.f;
            if (idx < HG) v = bih_f[idx] + bhh_f[idx];
            else if (idx < 2*HG) v = bih_b[idx-HG] + bhh_b[idx-HG];
            g_biasFB[idx] = v; return;
        }
        idx -= S6;
        if (idx < S7) { g_biasE[idx] = bih_e[idx] + bhh_e[idx]; return; }
        idx -= S7;
        g_biasTag[idx] = (idx < TAGL) ? bht[idx] : bdt[idx - TAGL];
        return;
    }
    gidx -= TPREP;
    size_t nx = (size_t)MR * DL;
    if (gidx < nx) {
        int d = (int)(gidx % DL);
        int m = (int)(gidx / DL);
        int b = m / SL, s = m % SL;
        float v;
        if (s == 0) v = sent[d];
        else {
            int t = s - 1;
            v = (d < 768) ? inp[(size_t)(b * TL + t) * 768 + d]
                          : tag[(size_t)(b * TL + t) * TAGL + (d - 768)];
        }
        g_X[gidx] = v;
        return;
    }
    gidx -= nx;
    if (gidx < MR) {
        int b = (int)(gidx / SL), s = (int)(gidx % SL);
        g_Mf[gidx] = (s == 0) ? 1.0f : (float)mask[b * TL + s - 1];
    }
}

// ---------------- split-bf16 HMMA GEMM, 128x128 tile (double-buffered, stride-8) ----------------
template <int ACT>
__global__ __launch_bounds__(256) void k_hgemm(const float* __restrict__ A,
                                               const unsigned* __restrict__ Bfrag,
                                               const float* __restrict__ bias,
                                               float* __restrict__ C, float* __restrict__ C2,
                                               int N, int K, int Nfrag) {
    __shared__ __align__(16) unsigned Ahs[2][1024];
    __shared__ __align__(16) unsigned Als[2][1024];
    __shared__ __align__(16) unsigned Bsm[2][2048];
    int m0 = blockIdx.y * 128, n0 = blockIdx.x * 128;
    int tid = threadIdx.x, wid = tid >> 5, lane = tid & 31;
    int mw = wid & 3, nh = wid >> 2;
    int r4 = lane >> 2, c4 = lane & 3;
    int nkt = K >> 4;
    int Nw8 = Nfrag * 8;

    int arow = tid >> 1, sg = (tid & 1) * 4;
    const float* Apt = A + (size_t)(m0 + arow) * K;

    float2 af[4];
    uint2  bf[4];
    float acc[2][8][4];
#pragma unroll
    for (int mt = 0; mt < 2; mt++)
#pragma unroll
        for (int nt = 0; nt < 8; nt++)
#pragma unroll
            for (int q = 0; q < 4; q++) acc[mt][nt][q] = 0.f;

#define HLD(KT) do { \
        _Pragma("unroll") for (int s_ = 0; s_ < 4; s_++) { \
            int s = sg + s_; int kl = 2 * (s >> 1) + 8 * (s & 1); \
            af[s_] = *(const float2*)(Apt + (size_t)(KT) * 16 + kl); } \
        _Pragma("unroll") for (int i_ = 0; i_ < 4; i_++) { \
            int lw = 2 * (i_ * 256 + tid); \
            int sp = lw >> 10, wq = lw & 1023; \
            bf[i_] = *(const uint2*)(Bfrag + (size_t)(KT) * 2 * Nw8 + (size_t)sp * Nw8 + n0 * 8 + wq); } \
    } while (0)

#define HST(BUF) do { \
        unsigned h_[4], l_[4]; \
        _Pragma("unroll") for (int s_ = 0; s_ < 4; s_++) splitpack(af[s_].x, af[s_].y, h_[s_], l_[s_]); \
        *(uint4*)&Ahs[BUF][arow * 8 + sg] = make_uint4(h_[0], h_[1], h_[2], h_[3]); \
        *(uint4*)&Als[BUF][arow * 8 + sg] = make_uint4(l_[0], l_[1], l_[2], l_[3]); \
        _Pragma("unroll") for (int i_ = 0; i_ < 4; i_++) \
            *(uint2*)&Bsm[BUF][2 * (i_ * 256 + tid)] = bf[i_]; \
    } while (0)

    HLD(0);
    HST(0);
    __syncthreads();
    for (int kt = 0; kt < nkt; kt++) {
        int buf = kt & 1;
        if (kt + 1 < nkt) HLD(kt + 1);
        uint2 Uh[2], Vh[2], Ul[2], Vl[2];
#pragma unroll
        for (int mt = 0; mt < 2; mt++) {
            int rb = mw * 32 + mt * 16 + r4;
            Uh[mt] = *(uint2*)&Ahs[buf][rb * 8 + 2 * c4];
            Vh[mt] = *(uint2*)&Ahs[buf][(rb + 8) * 8 + 2 * c4];
            Ul[mt] = *(uint2*)&Als[buf][rb * 8 + 2 * c4];
            Vl[mt] = *(uint2*)&Als[buf][(rb + 8) * 8 + 2 * c4];
        }
#pragma unroll
        for (int nt = 0; nt < 8; nt++) {
            int n = nh * 64 + nt * 8 + r4;
            uint2 Bh = *(uint2*)&Bsm[buf][n * 8 + 2 * c4];
            uint2 Bl = *(uint2*)&Bsm[buf][1024 + n * 8 + 2 * c4];
#pragma unroll
            for (int mt = 0; mt < 2; mt++) {
                mma16816(acc[mt][nt], Uh[mt].x, Vh[mt].x, Uh[mt].y, Vh[mt].y, Bh.x, Bh.y);
                mma16816(acc[mt][nt], Uh[mt].x, Vh[mt].x, Uh[mt].y, Vh[mt].y, Bl.x, Bl.y);
                mma16816(acc[mt][nt], Ul[mt].x, Vl[mt].x, Ul[mt].y, Vl[mt].y, Bh.x, Bh.y);
            }
        }
        if (kt + 1 < nkt) HST(buf ^ 1);
        __syncthreads();
    }
#undef HLD
#undef HST

#pragma unroll
    for (int nt = 0; nt < 8; nt++) {
        int colL = nh * 64 + nt * 8 + 2 * c4;
        float b0 = bias[n0 + colL], b1 = bias[n0 + colL + 1];
#pragma unroll
        for (int mt = 0; mt < 2; mt++) {
            int r = m0 + mw * 32 + mt * 16 + r4;
            float v0 = acc[mt][nt][0] + b0, v1 = acc[mt][nt][1] + b1;
            float v2 = acc[mt][nt][2] + b0, v3 = acc[mt][nt][3] + b1;
            if (ACT == 2) {
                v0 = (v0 > 0.f) ? v0 : expm1f(v0);
                v1 = (v1 > 0.f) ? v1 : expm1f(v1);
                v2 = (v2 > 0.f) ? v2 : expm1f(v2);
                v3 = (v3 > 0.f) ? v3 : expm1f(v3);
                float* dst = (blockIdx.x == 0) ? C : C2;
                *(float2*)(dst + (size_t)r * TAGL + colL)       = make_float2(v0, v1);
                *(float2*)(dst + (size_t)(r + 8) * TAGL + colL) = make_float2(v2, v3);
            } else {
                *(float2*)(C + (size_t)r * N + n0 + colL)       = make_float2(v0, v1);
                *(float2*)(C + (size_t)(r + 8) * N + n0 + colL) = make_float2(v2, v3);
            }
        }
    }
}

// ---------------- HMMA bidirectional masked RNN (cluster-synced) ----------------
#define RAS 200
#define RNN_SMEM ((25600 + 2*32*RAS) * 4)

__global__ void __cluster_dims__(8, 1, 1) __launch_bounds__(256, 1) k_rnn() {
    extern __shared__ unsigned rsm[];
    unsigned* Bs = rsm;             // 25 kt x 2 split x 64 n x 8 = 25600 words
    unsigned* Ah = rsm + 25600;     // 32 x 200
    unsigned* Al = Ah + 32 * RAS;

    int bx = blockIdx.x;
    int cl = bx >> 3, jg = bx & 7;
    int dir = cl >> 1, bg = cl & 1;
    int bbase = bg * 32;
    int tid = threadIdx.x, wid = tid >> 5, lane = tid & 31;
    int mw = wid & 1, ng = wid >> 1;
    int r4 = lane >> 2, c4 = lane & 3;
    int rlo = mw * 16 + r4, rhi = rlo + 8;

    // one-time: B fragments -> smem (linear, stride-8 natural layout)
    {
        const uint2* bsrc = (const uint2*)(g_Bw + (size_t)(dir * 8 + jg) * 25600);
#pragma unroll
        for (int i = 0; i < 50; i++) {
            int idx = tid + i * 256;
            uint2 v = __ldcg(bsrc + idx);
            *(uint2*)&Bs[2 * idx] = v;
        }
    }
    // zero exactly the words this CTA will write, pp=0
    {
        unsigned* hxp0 = g_HXP + (size_t)(cl * 2 + 0) * 12800;
        for (int idx = tid; idx < 1600; idx += 256) {
            int split = idx / 800, rest = idx % 800;
            int b = rest / 25, w = rest % 25;
            int p = word_of_k(jg * 50 + 2 * w);
            __stcg(&hxp0[split * 6400 + b * 200 + p], 0u);
        }
    }
    __syncthreads();
    CLUSTER_SYNC_();

    int jl[2], valid[2], wdp[2];
#pragma unroll
    for (int q = 0; q < 2; q++) {
        jl[q] = ng * 16 + q * 8 + 2 * c4;
        valid[q] = (jl[q] < 50);
        wdp[q] = word_of_k(jg * 50 + jl[q]);
    }
    float h[2][2][2];
#pragma unroll
    for (int a = 0; a < 2; a++)
#pragma unroll
        for (int b = 0; b < 2; b++)
#pragma unroll
            for (int c = 0; c < 2; c++) h[a][b][c] = 0.f;

    for (int tv = 0; tv < SL; tv++) {
        int t = dir ? (SL - 1 - tv) : tv;
        int pp = tv & 1;
        const uint2* src = (const uint2*)(g_HXP + (size_t)(cl * 2 + pp) * 12800);
        uint2 bp[25];
#pragma unroll
        for (int i = 0; i < 25; i++) {
            int idx = tid + i * 256;
            int b2 = idx / 100, wp = idx % 100;
            int split = b2 >> 5, b = b2 & 31;
            bp[i] = __ldcg(src + (size_t)split * 3200 + b * 100 + wp);
        }
        float mv[2];
        mv[0] = g_Mf[(bbase + rlo) * SL + t];
        mv[1] = g_Mf[(bbase + rhi) * SL + t];
        float2 pre[2][2];
#pragma unroll
        for (int rq = 0; rq < 2; rq++) {
            int R = rq ? rhi : rlo;
            size_t mbase = (size_t)((bbase + R) * SL + t) * NPRE + dir * HG + jg * 50;
#pragma unroll
            for (int q = 0; q < 2; q++)
                pre[rq][q] = *(const float2*)(g_Pre + mbase + jl[q]);
        }
#pragma unroll
        for (int i = 0; i < 25; i++) {
            int idx = tid + i * 256;
            int b2 = idx / 100, wp = idx % 100;
            int split = b2 >> 5, b = b2 & 31;
            unsigned* dst = split ? Al : Ah;
            *(uint2*)&dst[b * RAS + wp * 2] = bp[i];
        }
        __syncthreads();

        float acc[2][4];
#pragma unroll
        for (int q = 0; q < 2; q++)
#pragma unroll
            for (int z = 0; z < 4; z++) acc[q][z] = 0.f;
#pragma unroll
        for (int kt = 0; kt < 25; kt++) {
            uint2 UA  = *(uint2*)&Ah[rlo * RAS + kt * 8 + 2 * c4];
            uint2 VA  = *(uint2*)&Ah[rhi * RAS + kt * 8 + 2 * c4];
            uint2 UAl = *(uint2*)&Al[rlo * RAS + kt * 8 + 2 * c4];
            uint2 VAl = *(uint2*)&Al[rhi * RAS + kt * 8 + 2 * c4];
#pragma unroll
            for (int q = 0; q < 2; q++) {
                int n = ng * 16 + q * 8 + r4;
                uint2 Bh = *(uint2*)&Bs[(kt * 2) * 512 + n * 8 + 2 * c4];
                uint2 Bl = *(uint2*)&Bs[(kt * 2 + 1) * 512 + n * 8 + 2 * c4];
                mma16816(acc[q], UA.x, VA.x, UA.y, VA.y, Bh.x, Bh.y);
                mma16816(acc[q], UA.x, VA.x, UA.y, VA.y, Bl.x, Bl.y);
                mma16816(acc[q], UAl.x, VAl.x, UAl.y, VAl.y, Bh.x, Bh.y);
            }
        }
        __syncthreads();

        unsigned* dsth = g_HXP + (size_t)(cl * 2 + (pp ^ 1)) * 12800;
#pragma unroll
        for (int rq = 0; rq < 2; rq++) {
            int R = rq ? rhi : rlo;
            float mt = mv[rq], om = 1.f - mt;
            size_t grow = (size_t)((bbase + R) * SL + t) * (2 * HG) + dir * HG + jg * 50;
#pragma unroll
            for (int q = 0; q < 2; q++) {
                float u0 = mt * tanhfast(pre[rq][q].x + acc[q][rq * 2 + 0]) + om * h[rq][q][0];
                float u1 = mt * tanhfast(pre[rq][q].y + acc[q][rq * 2 + 1]) + om * h[rq][q][1];
                h[rq][q][0] = u0; h[rq][q][1] = u1;
                if (valid[q]) {
                    unsigned hi, lo; splitpack(u0, u1, hi, lo);
                    __stcg(&dsth[R * 200 + wdp[q]], hi);
                    __stcg(&dsth[6400 + R * 200 + wdp[q]], lo);
                    *(float2*)(g_GS + grow + jl[q]) = make_float2(u0 * mt, u1 * mt);
                }
            }
        }
        CLUSTER_SYNC_();
    }
}

// ---------------- tensor-core proj + 20-step estep loop (128 rows/CTA) ----------------
#define AST 136
#define ELOOP_WORDS (2*17408 + 8192 + 1024 + 128 + 256)
#define ELOOP_SMEM  (ELOOP_WORDS * 4)

__global__ __launch_bounds__(256, 1) void k_eloop(const float* __restrict__ wie,
                                                  const float* __restrict__ wcls,
                                                  const float* __restrict__ bcls,
                                                  const float* __restrict__ bos,
                                                  const float* __restrict__ bg2e) {
    extern __shared__ unsigned sm_u[];
    unsigned* Ah  = sm_u;               // 128 x 136
    unsigned* Al  = sm_u + 17408;
    unsigned* Bsm = sm_u + 34816;       // 2 bufs x 4096
    float* sbe = (float*)(sm_u + 43008);
    float* swi = sbe + 256;
    float* swc = sbe + 512;
    float* sbg = sbe + 768;
    float* xs  = sbe + 1024;            // 128
    float* lp  = xs + 128;              // 256

    int tid = threadIdx.x;
    int wid = tid >> 5, lane = tid & 31;
    int mw = wid & 3, nh = wid >> 2;
    int r4 = lane >> 2, c4 = lane & 3;
    int m0 = blockIdx.x * 128;
    int rlo[2], rhi[2];
#pragma unroll
    for (int mt = 0; mt < 2; mt++) { rlo[mt] = mw * 32 + mt * 16 + r4; rhi[mt] = rlo[mt] + 8; }

    sbe[tid] = g_biasE[tid & 255];
    swi[tid] = wie[tid & 255];
    swc[tid] = wcls[tid & 255];
    sbg[tid] = bg2e[tid & 255];
    if (tid < 128) xs[tid] = bos[0];
    float bcl = bcls[0];

    float acc[2][16][4];
    uint2 bp[8];

#define LDCHUNK(gsrc) do { \
        const uint2* s_ = (const uint2*)(gsrc); \
        _Pragma("unroll") for (int i_ = 0; i_ < 8; i_++) bp[i_] = s_[i_ * 256 + tid]; \
    } while (0)
#define STCHUNK(BUF) do { \
        _Pragma("unroll") for (int i_ = 0; i_ < 8; i_++) \
            *(uint2*)&Bsm[(BUF) * 4096 + 2 * (i_ * 256 + tid)] = bp[i_]; \
    } while (0)

    // ================= proj phase: acc = GS @ Wg2e^T (K = 800) =================
#pragma unroll
    for (int mt = 0; mt < 2; mt++)
#pragma unroll
        for (int nt = 0; nt < 16; nt++)
#pragma unroll
            for (int q = 0; q < 4; q++) acc[mt][nt][q] = 0.f;

    const float* gsA = g_GS + (size_t)m0 * (2*HG);
    LDCHUNK(g_Bp);
    STCHUNK(0);
    __syncthreads();
    for (int kt = 0; kt < 50; kt++) {
        int buf = kt & 1;
        if (kt + 1 < 50) LDCHUNK(g_Bp + (size_t)(kt + 1) * 4096);
        unsigned a0h[2], a0l[2], a1h[2], a1l[2], a2h[2], a2l[2], a3h[2], a3l[2];
#pragma unroll
        for (int mt = 0; mt < 2; mt++) {
            float2 x0 = *(const float2*)(gsA + (size_t)rlo[mt] * 800 + kt * 16 + 2 * c4);
            float2 x2 = *(const float2*)(gsA + (size_t)rlo[mt] * 800 + kt * 16 + 2 * c4 + 8);
            float2 x1 = *(const float2*)(gsA + (size_t)rhi[mt] * 800 + kt * 16 + 2 * c4);
            float2 x3 = *(const float2*)(gsA + (size_t)rhi[mt] * 800 + kt * 16 + 2 * c4 + 8);
            splitpack(x0.x, x0.y, a0h[mt], a0l[mt]);
            splitpack(x1.x, x1.y, a1h[mt], a1l[mt]);
            splitpack(x2.x, x2.y, a2h[mt], a2l[mt]);
            splitpack(x3.x, x3.y, a3h[mt], a3l[mt]);
        }
        const unsigned* bb = &Bsm[buf * 4096];
#pragma unroll
        for (int nt = 0; nt < 16; nt++) {
            int n = nh * 128 + nt * 8 + r4;
            uint2 Bh = *(const uint2*)&bb[n * 8 + 2 * c4];
            uint2 Bl = *(const uint2*)&bb[2048 + n * 8 + 2 * c4];
#pragma unroll
            for (int mt = 0; mt < 2; mt++) {
                mma16816(acc[mt][nt], a0h[mt], a1h[mt], a2h[mt], a3h[mt], Bh.x, Bh.y);
                mma16816(acc[mt][nt], a0h[mt], a1h[mt], a2h[mt], a3h[mt], Bl.x, Bl.y);
                mma16816(acc[mt][nt], a0l[mt], a1l[mt], a2l[mt], a3l[mt], Bh.x, Bh.y);
            }
        }
        if (kt + 1 < 50) STCHUNK(buf ^ 1);
        __syncthreads();
    }
    // proj epilogue: He0 = acc + bg2e -> packed A state
#pragma unroll
    for (int mt = 0; mt < 2; mt++)
#pragma unroll
    for (int ntp = 0; ntp < 8; ntp++) {
        int nt = ntp * 2;
        int nb0 = nh * 128 + nt * 8 + 2 * c4;
        int nb1 = nb0 + 8;
        float p00 = acc[mt][nt][0] + sbg[nb0],   p01 = acc[mt][nt][1] + sbg[nb0+1];
        float p10 = acc[mt][nt+1][0] + sbg[nb1], p11 = acc[mt][nt+1][1] + sbg[nb1+1];
        float q00 = acc[mt][nt][2] + sbg[nb0],   q01 = acc[mt][nt][3] + sbg[nb0+1];
        float q10 = acc[mt][nt+1][2] + sbg[nb1], q11 = acc[mt][nt+1][3] + sbg[nb1+1];
        unsigned he0, le0, he1, le1;
        int wlo = rlo[mt] * AST + (nh * 8 + ntp) * 8 + 2 * c4;
        int whi = rhi[mt] * AST + (nh * 8 + ntp) * 8 + 2 * c4;
        splitpack(p00, p01, he0, le0); splitpack(p10, p11, he1, le1);
        *(uint2*)&Ah[wlo] = make_uint2(he0, he1);
        *(uint2*)&Al[wlo] = make_uint2(le0, le1);
        splitpack(q00, q01, he0, le0); splitpack(q10, q11, he1, le1);
        *(uint2*)&Ah[whi] = make_uint2(he0, he1);
        *(uint2*)&Al[whi] = make_uint2(le0, le1);
    }
    __syncthreads();

    // ================= 20 estep iterations =================
    for (int st = 0; st < MST; st++) {
#pragma unroll
        for (int mt = 0; mt < 2; mt++)
#pragma unroll
            for (int nt = 0; nt < 16; nt++)
#pragma unroll
                for (int q = 0; q < 4; q++) acc[mt][nt][q] = 0.f;

        LDCHUNK(g_Be);
        STCHUNK(0);
        __syncthreads();
        for (int kt = 0; kt < 16; kt++) {
            int buf = kt & 1;
            if (kt + 1 < 16) LDCHUNK(g_Be + (size_t)(kt + 1) * 4096);
            uint2 UA[2], VA[2], UAl[2], VAl[2];
#pragma unroll
            for (int mt = 0; mt < 2; mt++) {
                UA[mt]  = *(uint2*)&Ah[rlo[mt] * AST + kt * 8 + 2 * c4];
                VA[mt]  = *(uint2*)&Ah[rhi[mt] * AST + kt * 8 + 2 * c4];
                UAl[mt] = *(uint2*)&Al[rlo[mt] * AST + kt * 8 + 2 * c4];
                VAl[mt] = *(uint2*)&Al[rhi[mt] * AST + kt * 8 + 2 * c4];
            }
            const unsigned* bb = &Bsm[buf * 4096];
#pragma unroll
            for (int nt = 0; nt < 16; nt++) {
                int n = nh * 128 + nt * 8 + r4;
                uint2 Bh = *(const uint2*)&bb[n * 8 + 2 * c4];
                uint2 Bl = *(const uint2*)&bb[2048 + n * 8 + 2 * c4];
#pragma unroll
                for (int mt = 0; mt < 2; mt++) {
                    mma16816(acc[mt][nt], UA[mt].x, VA[mt].x, UA[mt].y, VA[mt].y, Bh.x, Bh.y);
                    mma16816(acc[mt][nt], UA[mt].x, VA[mt].x, UA[mt].y, VA[mt].y, Bl.x, Bl.y);
                    mma16816(acc[mt][nt], UAl[mt].x, VAl[mt].x, UAl[mt].y, VAl[mt].y, Bh.x, Bh.y);
                }
            }
            if (kt + 1 < 16) STCHUNK(buf ^ 1);
            __syncthreads();
        }

#pragma unroll
        for (int mt = 0; mt < 2; mt++) {
            float xel = xs[rlo[mt]], xeh = xs[rhi[mt]];
            float pl = 0.f, ph = 0.f;
#pragma unroll
            for (int ntp = 0; ntp < 8; ntp++) {
                int nt = ntp * 2;
                int nb0 = nh * 128 + nt * 8 + 2 * c4;
                int nb1 = nb0 + 8;
                float b00 = sbe[nb0], b01 = sbe[nb0+1], b10 = sbe[nb1], b11 = sbe[nb1+1];
                float w00 = swi[nb0], w01 = swi[nb0+1], w10 = swi[nb1], w11 = swi[nb1+1];
                float h00 = tanhfast(acc[mt][nt][0]   + b00 + xel * w00);
                float h01 = tanhfast(acc[mt][nt][1]   + b01 + xel * w01);
                float h10 = tanhfast(acc[mt][nt+1][0] + b10 + xel * w10);
                float h11 = tanhfast(acc[mt][nt+1][1] + b11 + xel * w11);
                float g00 = tanhfast(acc[mt][nt][2]   + b00 + xeh * w00);
                float g01 = tanhfast(acc[mt][nt][3]   + b01 + xeh * w01);
                float g10 = tanhfast(acc[mt][nt+1][2] + b10 + xeh * w10);
                float g11 = tanhfast(acc[mt][nt+1][3] + b11 + xeh * w11);
                float c00 = swc[nb0], c01 = swc[nb0+1], c10 = swc[nb1], c11 = swc[nb1+1];
                pl += h00 * c00 + h01 * c01 + h10 * c10 + h11 * c11;
                ph += g00 * c00 + g01 * c01 + g10 * c10 + g11 * c11;
                unsigned he0, le0, he1, le1;
                int wlo = rlo[mt] * AST + (nh * 8 + ntp) * 8 + 2 * c4;
                int whi = rhi[mt] * AST + (nh * 8 + ntp) * 8 + 2 * c4;
                splitpack(h00, h01, he0, le0); splitpack(h10, h11, he1, le1);
                *(uint2*)&Ah[wlo] = make_uint2(he0, he1);
                *(uint2*)&Al[wlo] = make_uint2(le0, le1);
                splitpack(g00, g01, he0, le0); splitpack(g10, g11, he1, le1);
                *(uint2*)&Ah[whi] = make_uint2(he0, he1);
                *(uint2*)&Al[whi] = make_uint2(le0, le1);
            }
            pl += __shfl_xor_sync(0xffffffffu, pl, 1);
            pl += __shfl_xor_sync(0xffffffffu, pl, 2);
            ph += __shfl_xor_sync(0xffffffffu, ph, 1);
            ph += __shfl_xor_sync(0xffffffffu, ph, 2);
            if (c4 == 0) {
                lp[nh * 128 + rlo[mt]] = pl;
                lp[nh * 128 + rhi[mt]] = ph;
            }
        }
        __syncthreads();
        if (tid < 128) {
            float logit = lp[tid] + lp[128 + tid] + bcl;
            g_Ap[(size_t)(m0 + tid) * MST + st] = logit;
            xs[tid] = logit;
        }
        __syncthreads();
    }
#undef LDCHUNK
#undef STCHUNK
}

// ---------------- arc band gather ----------------
__global__ void k_arc(float* __restrict__ out) {
    size_t idx = (size_t)blockIdx.x * blockDim.x + threadIdx.x;
    size_t total = (size_t)BB * SL * SL;
    if (idx >= total) return;
    int c = (int)(idx % SL);
    int r = (int)((idx / SL) % SL);
    int b = (int)(idx / ((size_t)SL * SL));
    int start = r - MST; if (start < 0) start = 0;
    float v = 0.f;
    if (c >= start && c < r) v = g_Ap[(size_t)(b * SL + r) * MST + (c - start)];
    out[idx] = v;
}

// ---------------- host launcher ----------------
extern "C" void kernel_launch(void* const* d_in, const int* in_sizes, int n_in,
                              void* d_out, int out_size) {
    const float* input  = (const float*)d_in[0];
    const float* tagemb = (const float*)d_in[1];
    const int*   mask   = (const int*)d_in[2];
    const float* sent   = (const float*)d_in[3];
    const float* Wih_f  = (const float*)d_in[4];
    const float* Whh_f  = (const float*)d_in[5];
    const float* bih_f  = (const float*)d_in[6];
    const float* bhh_f  = (const float*)d_in[7];
    const float* Wih_b  = (const float*)d_in[8];
    const float* Whh_b  = (const float*)d_in[9];
    const float* bih_b  = (const float*)d_in[10];
    const float* bhh_b  = (const float*)d_in[11];
    const float* Wg2e   = (const float*)d_in[12];
    const float* bg2e   = (const float*)d_in[13];
    const float* Wih_e  = (const float*)d_in[14];
    const float* Whh_e  = (const float*)d_in[15];
    const float* bih_e  = (const float*)d_in[16];
    const float* bhh_e  = (const float*)d_in[17];
    const float* Wcls   = (const float*)d_in[18];
    const float* bcls   = (const float*)d_in[19];
    const float* bos    = (const float*)d_in[20];
    const float* Wht    = (const float*)d_in[21];
    const float* bht    = (const float*)d_in[22];
    const float* Wdt    = (const float*)d_in[23];
    const float* bdt    = (const float*)d_in[24];
    float* out = (float*)d_out;

    float *pX, *pPre, *pGS, *pbFB, *pbTag;
    unsigned *pBpre, *pBtag;
    cudaGetSymbolAddress((void**)&pX, g_X);
    cudaGetSymbolAddress((void**)&pPre, g_Pre);
    cudaGetSymbolAddress((void**)&pGS, g_GS);
    cudaGetSymbolAddress((void**)&pbFB, g_biasFB);
    cudaGetSymbolAddress((void**)&pbTag, g_biasTag);
    cudaGetSymbolAddress((void**)&pBpre, g_Bpre);
    cudaGetSymbolAddress((void**)&pBtag, g_Btag);

    static int smem_set = 0;
    if (!smem_set) {
        cudaFuncSetAttribute(k_eloop, cudaFuncAttributeMaxDynamicSharedMemorySize, ELOOP_SMEM);
        cudaFuncSetAttribute(k_rnn, cudaFuncAttributeMaxDynamicSharedMemorySize, RNN_SMEM);
        smem_set = 1;
    }

    // 1. fused setup
    {
        size_t n = TSETUP;
        k_setup<<<(unsigned)((n + 255) / 256), 256>>>(Wih_f, Wih_b, Wg2e, Whh_e, Wht, Wdt,
                                                      Whh_f, Whh_b,
                                                      bih_f, bhh_f, bih_b, bhh_b,
                                                      bih_e, bhh_e, bht, bdt,
                                                      input, tagemb, sent, mask);
    }
    // 2. Pre GEMM (split-bf16 HMMA)
    {
        dim3 grid(NPRE / 128, MR / 128);
        k_hgemm<0><<<grid, 256>>>(pX, pBpre, pbFB, pPre, nullptr, NPRE, DL, NPRE);
    }
    // 3. bidirectional recurrence (HMMA, 4 clusters of 8 CTAs)
    k_rnn<<<32, 256, RNN_SMEM>>>();
    // 4. tensor-core proj + estep chain (128 rows/CTA)
    k_eloop<<<MR / 128, 256, ELOOP_SMEM>>>(Wih_e, Wcls, bcls, bos, bg2e);
    // 5. head/dep tags GEMM
    {
        dim3 grid(2, MR / 128);
        k_hgemm<2><<<grid, 256>>>(pGS, pBtag, pbTag, out, out + (size_t)MR * TAGL,
                                  2 * TAGL, 2 * HG, 2 * TAGL);
    }
    // 6. arc logits
    {
        size_t total = (size_t)BB * SL * SL;
        k_arc<<<(unsigned)((total + 255) / 256), 256>>>(out + 2 * (size_t)MR * TAGL);
    }
    (void)in_sizes; (void)n_in; (void)out_size;
}

// round 11
// speedup vs baseline: 2.9727x; 1.1202x over previous
#include <cuda_runtime.h>
#include <cuda_bf16.h>
#include <math.h>

#define BB   64
#define TL   383
#define SL   384
#define DL   896
#define HG   400
#define HEH  256
#define TAGL 128
#define MST  20
#define MR   (BB*SL)    // 24576
#define NPRE 896        // padded 2*HG

// ---------------- scratch (device globals) ----------------
__device__ float g_X[(size_t)MR*DL];
__device__ float g_Mf[MR];
__device__ float g_Pre[(size_t)MR*NPRE];
__device__ float g_GS[(size_t)MR*2*HG];
__device__ float g_Ap[MR*MST];
__device__ float g_biasFB[NPRE];
__device__ float g_biasE[HEH];
__device__ float g_biasTag[2*TAGL];
__device__ unsigned g_Be[16*2*2048];
__device__ unsigned g_Bp[50*2*2048];
__device__ unsigned g_Bpre[56*2*7168];
__device__ unsigned g_Btag[50*2*2048];
__device__ unsigned g_Bw[16*25600];
__device__ unsigned g_HXP[4*2*2*32*200];

#define CLUSTER_SYNC_() do { \
    asm volatile("barrier.cluster.arrive.aligned;" ::: "memory"); \
    asm volatile("barrier.cluster.wait.aligned;" ::: "memory"); \
} while (0)

// ---------------- helpers ----------------
__device__ __forceinline__ void splitpack(float x0, float x1, unsigned& hi, unsigned& lo) {
    __nv_bfloat16 b0 = __float2bfloat16_rn(x0);
    __nv_bfloat16 b1 = __float2bfloat16_rn(x1);
    float r0 = x0 - __bfloat162float(b0);
    float r1 = x1 - __bfloat162float(b1);
    __nv_bfloat16 c0 = __float2bfloat16_rn(r0);
    __nv_bfloat16 c1 = __float2bfloat16_rn(r1);
    hi = (unsigned)__bfloat16_as_ushort(b0) | ((unsigned)__bfloat16_as_ushort(b1) << 16);
    lo = (unsigned)__bfloat16_as_ushort(c0) | ((unsigned)__bfloat16_as_ushort(c1) << 16);
}

__device__ __forceinline__ void mma16816(float* d, unsigned a0, unsigned a1, unsigned a2,
                                         unsigned a3, unsigned b0, unsigned b1) {
    asm volatile(
        "mma.sync.aligned.m16n8k16.row.col.f32.bf16.bf16.f32 "
        "{%0,%1,%2,%3},{%4,%5,%6,%7},{%8,%9},{%0,%1,%2,%3};"
        : "+f"(d[0]), "+f"(d[1]), "+f"(d[2]), "+f"(d[3])
        : "r"(a0), "r"(a1), "r"(a2), "r"(a3), "r"(b0), "r"(b1));
}

__device__ __forceinline__ float tanhfast(float x) {
    float e = __expf(2.f * x);
    return 1.f - __fdividef(2.f, e + 1.f);
}

__device__ __forceinline__ int word_of_k(int k) {
    int kt = k >> 4, rem = k & 15;
    int s = (rem < 8) ? rem : (rem - 7);
    return kt * 8 + s;
}

// ---------------- fused setup ----------------
#define S1 (56*2*7168)
#define S2 (50*2*2048)
#define S3 (16*2*2048)
#define S4 (50*2*2048)
#define S5 (16*25600)
#define S6 (NPRE)
#define S7 (HEH)
#define S8 (2*TAGL)
#define TPREP (S1+S2+S3+S4+S5+S6+S7+S8)
#define TBUILD ((size_t)MR*DL + MR)
#define TSETUP (TPREP + TBUILD)

__global__ void k_setup(const float* __restrict__ Wih_f, const float* __restrict__ Wih_b,
                        const float* __restrict__ Wg2e, const float* __restrict__ Whh_e,
                        const float* __restrict__ Wht,  const float* __restrict__ Wdt,
                        const float* __restrict__ Whh_f, const float* __restrict__ Whh_b,
                        const float* __restrict__ bih_f, const float* __restrict__ bhh_f,
                        const float* __restrict__ bih_b, const float* __restrict__ bhh_b,
                        const float* __restrict__ bih_e, const float* __restrict__ bhh_e,
                        const float* __restrict__ bht,   const float* __restrict__ bdt,
                        const float* __restrict__ inp, const float* __restrict__ tag,
                        const float* __restrict__ sent, const int* __restrict__ mask) {
    size_t gidx = (size_t)blockIdx.x * blockDim.x + threadIdx.x;
    if (gidx < TPREP) {
        int idx = (int)gidx;
        if (idx < S1) {
            int kt = idx / 14336, rest = idx % 14336;
            int split = rest / 7168, w = rest % 7168;
            int n = w >> 3, s = w & 7;
            int k = kt * 16 + 2 * (s >> 1) + 8 * (s & 1);
            float x0 = 0.f, x1 = 0.f;
            if (n < HG)          { x0 = Wih_f[(size_t)n * DL + k];        x1 = Wih_f[(size_t)n * DL + k + 1]; }
            else if (n < 2*HG)   { x0 = Wih_b[(size_t)(n-HG) * DL + k];   x1 = Wih_b[(size_t)(n-HG) * DL + k + 1]; }
            unsigned hi, lo; splitpack(x0, x1, hi, lo);
            g_Bpre[idx] = split ? lo : hi; return;
        }
        idx -= S1;
        if (idx < S2) {
            int kt = idx >> 12, rest = idx & 4095;
            int split = rest >> 11, w = rest & 2047;
            int n = w >> 3, s = w & 7;
            int k = kt * 16 + 2 * (s >> 1) + 8 * (s & 1);
            float x0 = Wg2e[(size_t)n * (2*HG) + k];
            float x1 = Wg2e[(size_t)n * (2*HG) + k + 1];
            unsigned hi, lo; splitpack(x0, x1, hi, lo);
            g_Bp[idx] = split ? lo : hi; return;
        }
        idx -= S2;
        if (idx < S3) {
            int kt = idx >> 12, rest = idx & 4095;
            int split = rest >> 11, w = rest & 2047;
            int n = w >> 3, s = w & 7;
            int k = kt * 16 + 2 * (s >> 1) + 8 * (s & 1);
            float x0 = Whh_e[(size_t)n * HEH + k];
            float x1 = Whh_e[(size_t)n * HEH + k + 1];
            unsigned hi, lo; splitpack(x0, x1, hi, lo);
            g_Be[idx] = split ? lo : hi; return;
        }
        idx -= S3;
        if (idx < S4) {
            int kt = idx >> 12, rest = idx & 4095;
            int split = rest >> 11, w = rest & 2047;
            int n = w >> 3, s = w & 7;
            int k = kt * 16 + 2 * (s >> 1) + 8 * (s & 1);
            float x0, x1;
            if (n < TAGL) { x0 = Wht[(size_t)n * (2*HG) + k];        x1 = Wht[(size_t)n * (2*HG) + k + 1]; }
            else          { x0 = Wdt[(size_t)(n-TAGL) * (2*HG) + k]; x1 = Wdt[(size_t)(n-TAGL) * (2*HG) + k + 1]; }
            unsigned hi, lo; splitpack(x0, x1, hi, lo);
            g_Btag[idx] = split ? lo : hi; return;
        }
        idx -= S4;
        if (idx < S5) {
            int ctx = idx / 25600, rest = idx % 25600;
            int dir = ctx >> 3, jgx = ctx & 7;
            int kt = rest >> 10, r2 = rest & 1023;
            int split = r2 >> 9, r3 = r2 & 511;
            int n = r3 >> 3, s = r3 & 7;
            int k = kt * 16 + 2 * (s >> 1) + 8 * (s & 1);
            float x0 = 0.f, x1 = 0.f;
            if (n < 50) {
                const float* W = dir ? Whh_b : Whh_f;
                int j = jgx * 50 + n;
                x0 = W[(size_t)j * HG + k];
                x1 = W[(size_t)j * HG + k + 1];
            }
            unsigned hi, lo; splitpack(x0, x1, hi, lo);
            g_Bw[idx] = split ? lo : hi; return;
        }
        idx -= S5;
        if (idx < S6) {
            float v = 0.f;
            if (idx < HG) v = bih_f[idx] + bhh_f[idx];
            else if (idx < 2*HG) v = bih_b[idx-HG] + bhh_b[idx-HG];
            g_biasFB[idx] = v; return;
        }
        idx -= S6;
        if (idx < S7) { g_biasE[idx] = bih_e[idx] + bhh_e[idx]; return; }
        idx -= S7;
        g_biasTag[idx] = (idx < TAGL) ? bht[idx] : bdt[idx - TAGL];
        return;
    }
    gidx -= TPREP;
    size_t nx = (size_t)MR * DL;
    if (gidx < nx) {
        int d = (int)(gidx % DL);
        int m = (int)(gidx / DL);
        int b = m / SL, s = m % SL;
        float v;
        if (s == 0) v = sent[d];
        else {
            int t = s - 1;
            v = (d < 768) ? inp[(size_t)(b * TL + t) * 768 + d]
                          : tag[(size_t)(b * TL + t) * TAGL + (d - 768)];
        }
        g_X[gidx] = v;
        return;
    }
    gidx -= nx;
    if (gidx < MR) {
        int b = (int)(gidx / SL), s = (int)(gidx % SL);
        g_Mf[gidx] = (s == 0) ? 1.0f : (float)mask[b * TL + s - 1];
    }
}

// ---------------- split-bf16 HMMA GEMM, 128x128 tile ----------------
template <int ACT>
__global__ __launch_bounds__(256) void k_hgemm(const float* __restrict__ A,
                                               const unsigned* __restrict__ Bfrag,
                                               const float* __restrict__ bias,
                                               float* __restrict__ C, float* __restrict__ C2,
                                               int N, int K, int Nfrag) {
    __shared__ __align__(16) unsigned Ahs[2][1024];
    __shared__ __align__(16) unsigned Als[2][1024];
    __shared__ __align__(16) unsigned Bsm[2][2048];
    int m0 = blockIdx.y * 128, n0 = blockIdx.x * 128;
    int tid = threadIdx.x, wid = tid >> 5, lane = tid & 31;
    int mw = wid & 3, nh = wid >> 2;
    int r4 = lane >> 2, c4 = lane & 3;
    int nkt = K >> 4;
    int Nw8 = Nfrag * 8;

    int arow = tid >> 1, sg = (tid & 1) * 4;
    const float* Apt = A + (size_t)(m0 + arow) * K;

    float2 af[4];
    uint2  bf[4];
    float acc[2][8][4];
#pragma unroll
    for (int mt = 0; mt < 2; mt++)
#pragma unroll
        for (int nt = 0; nt < 8; nt++)
#pragma unroll
            for (int q = 0; q < 4; q++) acc[mt][nt][q] = 0.f;

#define HLD(KT) do { \
        _Pragma("unroll") for (int s_ = 0; s_ < 4; s_++) { \
            int s = sg + s_; int kl = 2 * (s >> 1) + 8 * (s & 1); \
            af[s_] = *(const float2*)(Apt + (size_t)(KT) * 16 + kl); } \
        _Pragma("unroll") for (int i_ = 0; i_ < 4; i_++) { \
            int lw = 2 * (i_ * 256 + tid); \
            int sp = lw >> 10, wq = lw & 1023; \
            bf[i_] = *(const uint2*)(Bfrag + (size_t)(KT) * 2 * Nw8 + (size_t)sp * Nw8 + n0 * 8 + wq); } \
    } while (0)

#define HST(BUF) do { \
        unsigned h_[4], l_[4]; \
        _Pragma("unroll") for (int s_ = 0; s_ < 4; s_++) splitpack(af[s_].x, af[s_].y, h_[s_], l_[s_]); \
        *(uint4*)&Ahs[BUF][arow * 8 + sg] = make_uint4(h_[0], h_[1], h_[2], h_[3]); \
        *(uint4*)&Als[BUF][arow * 8 + sg] = make_uint4(l_[0], l_[1], l_[2], l_[3]); \
        _Pragma("unroll") for (int i_ = 0; i_ < 4; i_++) \
            *(uint2*)&Bsm[BUF][2 * (i_ * 256 + tid)] = bf[i_]; \
    } while (0)

    HLD(0);
    HST(0);
    __syncthreads();
    for (int kt = 0; kt < nkt; kt++) {
        int buf = kt & 1;
        if (kt + 1 < nkt) HLD(kt + 1);
        uint2 Uh[2], Vh[2], Ul[2], Vl[2];
#pragma unroll
        for (int mt = 0; mt < 2; mt++) {
            int rb = mw * 32 + mt * 16 + r4;
            Uh[mt] = *(uint2*)&Ahs[buf][rb * 8 + 2 * c4];
            Vh[mt] = *(uint2*)&Ahs[buf][(rb + 8) * 8 + 2 * c4];
            Ul[mt] = *(uint2*)&Als[buf][rb * 8 + 2 * c4];
            Vl[mt] = *(uint2*)&Als[buf][(rb + 8) * 8 + 2 * c4];
        }
#pragma unroll
        for (int nt = 0; nt < 8; nt++) {
            int n = nh * 64 + nt * 8 + r4;
            uint2 Bh = *(uint2*)&Bsm[buf][n * 8 + 2 * c4];
            uint2 Bl = *(uint2*)&Bsm[buf][1024 + n * 8 + 2 * c4];
#pragma unroll
            for (int mt = 0; mt < 2; mt++) {
                mma16816(acc[mt][nt], Uh[mt].x, Vh[mt].x, Uh[mt].y, Vh[mt].y, Bh.x, Bh.y);
                mma16816(acc[mt][nt], Uh[mt].x, Vh[mt].x, Uh[mt].y, Vh[mt].y, Bl.x, Bl.y);
                mma16816(acc[mt][nt], Ul[mt].x, Vl[mt].x, Ul[mt].y, Vl[mt].y, Bh.x, Bh.y);
            }
        }
        if (kt + 1 < nkt) HST(buf ^ 1);
        __syncthreads();
    }
#undef HLD
#undef HST

#pragma unroll
    for (int nt = 0; nt < 8; nt++) {
        int colL = nh * 64 + nt * 8 + 2 * c4;
        float b0 = bias[n0 + colL], b1 = bias[n0 + colL + 1];
#pragma unroll
        for (int mt = 0; mt < 2; mt++) {
            int r = m0 + mw * 32 + mt * 16 + r4;
            float v0 = acc[mt][nt][0] + b0, v1 = acc[mt][nt][1] + b1;
            float v2 = acc[mt][nt][2] + b0, v3 = acc[mt][nt][3] + b1;
            if (ACT == 2) {
                v0 = (v0 > 0.f) ? v0 : expm1f(v0);
                v1 = (v1 > 0.f) ? v1 : expm1f(v1);
                v2 = (v2 > 0.f) ? v2 : expm1f(v2);
                v3 = (v3 > 0.f) ? v3 : expm1f(v3);
                float* dst = (blockIdx.x == 0) ? C : C2;
                *(float2*)(dst + (size_t)r * TAGL + colL)       = make_float2(v0, v1);
                *(float2*)(dst + (size_t)(r + 8) * TAGL + colL) = make_float2(v2, v3);
            } else {
                *(float2*)(C + (size_t)r * N + n0 + colL)       = make_float2(v0, v1);
                *(float2*)(C + (size_t)(r + 8) * N + n0 + colL) = make_float2(v2, v3);
            }
        }
    }
}

// ---------------- HMMA bidirectional masked RNN (cluster-synced) ----------------
#define RAS 200
#define RNN_SMEM ((25600 + 2*32*RAS) * 4)

__global__ void __cluster_dims__(8, 1, 1) __launch_bounds__(256, 1) k_rnn() {
    extern __shared__ unsigned rsm[];
    unsigned* Bs = rsm;
    unsigned* Ah = rsm + 25600;
    unsigned* Al = Ah + 32 * RAS;

    int bx = blockIdx.x;
    int cl = bx >> 3, jg = bx & 7;
    int dir = cl >> 1, bg = cl & 1;
    int bbase = bg * 32;
    int tid = threadIdx.x, wid = tid >> 5, lane = tid & 31;
    int mw = wid & 1, ng = wid >> 1;
    int r4 = lane >> 2, c4 = lane & 3;
    int rlo = mw * 16 + r4, rhi = rlo + 8;

    {
        const uint2* bsrc = (const uint2*)(g_Bw + (size_t)(dir * 8 + jg) * 25600);
#pragma unroll
        for (int i = 0; i < 50; i++) {
            int idx = tid + i * 256;
            uint2 v = __ldcg(bsrc + idx);
            *(uint2*)&Bs[2 * idx] = v;
        }
    }
    {
        unsigned* hxp0 = g_HXP + (size_t)(cl * 2 + 0) * 12800;
        for (int idx = tid; idx < 1600; idx += 256) {
            int split = idx / 800, rest = idx % 800;
            int b = rest / 25, w = rest % 25;
            int p = word_of_k(jg * 50 + 2 * w);
            __stcg(&hxp0[split * 6400 + b * 200 + p], 0u);
        }
    }
    __syncthreads();
    CLUSTER_SYNC_();

    int jl[2], valid[2], wdp[2];
#pragma unroll
    for (int q = 0; q < 2; q++) {
        jl[q] = ng * 16 + q * 8 + 2 * c4;
        valid[q] = (jl[q] < 50);
        wdp[q] = word_of_k(jg * 50 + jl[q]);
    }
    float h[2][2][2];
#pragma unroll
    for (int a = 0; a < 2; a++)
#pragma unroll
        for (int b = 0; b < 2; b++)
#pragma unroll
            for (int c = 0; c < 2; c++) h[a][b][c] = 0.f;

    for (int tv = 0; tv < SL; tv++) {
        int t = dir ? (SL - 1 - tv) : tv;
        int pp = tv & 1;
        const uint2* src = (const uint2*)(g_HXP + (size_t)(cl * 2 + pp) * 12800);
        uint2 bp[25];
#pragma unroll
        for (int i = 0; i < 25; i++) {
            int idx = tid + i * 256;
            int b2 = idx / 100, wp = idx % 100;
            int split = b2 >> 5, b = b2 & 31;
            bp[i] = __ldcg(src + (size_t)split * 3200 + b * 100 + wp);
        }
        float mv[2];
        mv[0] = g_Mf[(bbase + rlo) * SL + t];
        mv[1] = g_Mf[(bbase + rhi) * SL + t];
        float2 pre[2][2];
#pragma unroll
        for (int rq = 0; rq < 2; rq++) {
            int R = rq ? rhi : rlo;
            size_t mbase = (size_t)((bbase + R) * SL + t) * NPRE + dir * HG + jg * 50;
#pragma unroll
            for (int q = 0; q < 2; q++)
                pre[rq][q] = *(const float2*)(g_Pre + mbase + jl[q]);
        }
#pragma unroll
        for (int i = 0; i < 25; i++) {
            int idx = tid + i * 256;
            int b2 = idx / 100, wp = idx % 100;
            int split = b2 >> 5, b = b2 & 31;
            unsigned* dst = split ? Al : Ah;
            *(uint2*)&dst[b * RAS + wp * 2] = bp[i];
        }
        __syncthreads();

        float acc[2][4];
#pragma unroll
        for (int q = 0; q < 2; q++)
#pragma unroll
            for (int z = 0; z < 4; z++) acc[q][z] = 0.f;
#pragma unroll
        for (int kt = 0; kt < 25; kt++) {
            uint2 UA  = *(uint2*)&Ah[rlo * RAS + kt * 8 + 2 * c4];
            uint2 VA  = *(uint2*)&Ah[rhi * RAS + kt * 8 + 2 * c4];
            uint2 UAl = *(uint2*)&Al[rlo * RAS + kt * 8 + 2 * c4];
            uint2 VAl = *(uint2*)&Al[rhi * RAS + kt * 8 + 2 * c4];
#pragma unroll
            for (int q = 0; q < 2; q++) {
                int n = ng * 16 + q * 8 + r4;
                uint2 Bh = *(uint2*)&Bs[(kt * 2) * 512 + n * 8 + 2 * c4];
                uint2 Bl = *(uint2*)&Bs[(kt * 2 + 1) * 512 + n * 8 + 2 * c4];
                mma16816(acc[q], UA.x, VA.x, UA.y, VA.y, Bh.x, Bh.y);
                mma16816(acc[q], UA.x, VA.x, UA.y, VA.y, Bl.x, Bl.y);
                mma16816(acc[q], UAl.x, VAl.x, UAl.y, VAl.y, Bh.x, Bh.y);
            }
        }
        __syncthreads();

        unsigned* dsth = g_HXP + (size_t)(cl * 2 + (pp ^ 1)) * 12800;
#pragma unroll
        for (int rq = 0; rq < 2; rq++) {
            int R = rq ? rhi : rlo;
            float mt = mv[rq], om = 1.f - mt;
            size_t grow = (size_t)((bbase + R) * SL + t) * (2 * HG) + dir * HG + jg * 50;
#pragma unroll
            for (int q = 0; q < 2; q++) {
                float u0 = mt * tanhfast(pre[rq][q].x + acc[q][rq * 2 + 0]) + om * h[rq][q][0];
                float u1 = mt * tanhfast(pre[rq][q].y + acc[q][rq * 2 + 1]) + om * h[rq][q][1];
                h[rq][q][0] = u0; h[rq][q][1] = u1;
                if (valid[q]) {
                    unsigned hi, lo; splitpack(u0, u1, hi, lo);
                    __stcg(&dsth[R * 200 + wdp[q]], hi);
                    __stcg(&dsth[6400 + R * 200 + wdp[q]], lo);
                    *(float2*)(g_GS + grow + jl[q]) = make_float2(u0 * mt, u1 * mt);
                }
            }
        }
        CLUSTER_SYNC_();
    }
}

// ---------------- tensor-core proj + 20-step estep loop (64 rows/CTA, 2 CTAs/SM) ----------------
#define AST 136
#define ELOOP_WORDS (2*8704 + 8192 + 1024 + 64 + 128)
#define ELOOP_SMEM  (ELOOP_WORDS * 4)

__global__ __launch_bounds__(256, 2) void k_eloop(const float* __restrict__ wie,
                                                  const float* __restrict__ wcls,
                                                  const float* __restrict__ bcls,
                                                  const float* __restrict__ bos,
                                                  const float* __restrict__ bg2e) {
    extern __shared__ unsigned sm_u[];
    unsigned* Ah  = sm_u;               // 64 x 136
    unsigned* Al  = sm_u + 8704;
    unsigned* Bsm = sm_u + 17408;       // 2 bufs x 4096
    float* sbe = (float*)(sm_u + 25600);
    float* swi = sbe + 256;
    float* swc = sbe + 512;
    float* sbg = sbe + 768;
    float* xs  = sbe + 1024;            // 64
    float* lp  = xs + 64;               // 128

    int tid = threadIdx.x;
    int wid = tid >> 5, lane = tid & 31;
    int mw = wid & 3, nh = wid >> 2;
    int r4 = lane >> 2, c4 = lane & 3;
    int m0 = blockIdx.x * 64;
    int rlo = mw * 16 + r4, rhi = rlo + 8;

    sbe[tid] = g_biasE[tid & 255];
    swi[tid] = wie[tid & 255];
    swc[tid] = wcls[tid & 255];
    sbg[tid] = bg2e[tid & 255];
    if (tid < 64) xs[tid] = bos[0];
    float bcl = bcls[0];

    float acc[16][4];
    uint2 bp[8];

#define LDCHUNK(gsrc) do { \
        const uint2* s_ = (const uint2*)(gsrc); \
        _Pragma("unroll") for (int i_ = 0; i_ < 8; i_++) bp[i_] = s_[i_ * 256 + tid]; \
    } while (0)
#define STCHUNK(BUF) do { \
        _Pragma("unroll") for (int i_ = 0; i_ < 8; i_++) \
            *(uint2*)&Bsm[(BUF) * 4096 + 2 * (i_ * 256 + tid)] = bp[i_]; \
    } while (0)

    // ================= proj phase: acc = GS @ Wg2e^T (K = 800) =================
#pragma unroll
    for (int nt = 0; nt < 16; nt++)
#pragma unroll
        for (int q = 0; q < 4; q++) acc[nt][q] = 0.f;

    const float* gsA = g_GS + (size_t)m0 * (2*HG);
    LDCHUNK(g_Bp);
    STCHUNK(0);
    __syncthreads();
    for (int kt = 0; kt < 50; kt++) {
        int buf = kt & 1;
        if (kt + 1 < 50) LDCHUNK(g_Bp + (size_t)(kt + 1) * 4096);
        float2 x0 = *(const float2*)(gsA + (size_t)rlo * 800 + kt * 16 + 2 * c4);
        float2 x2 = *(const float2*)(gsA + (size_t)rlo * 800 + kt * 16 + 2 * c4 + 8);
        float2 x1 = *(const float2*)(gsA + (size_t)rhi * 800 + kt * 16 + 2 * c4);
        float2 x3 = *(const float2*)(gsA + (size_t)rhi * 800 + kt * 16 + 2 * c4 + 8);
        unsigned a0h, a0l, a1h, a1l, a2h, a2l, a3h, a3l;
        splitpack(x0.x, x0.y, a0h, a0l);
        splitpack(x1.x, x1.y, a1h, a1l);
        splitpack(x2.x, x2.y, a2h, a2l);
        splitpack(x3.x, x3.y, a3h, a3l);
        const unsigned* bb = &Bsm[buf * 4096];
#pragma unroll
        for (int nt = 0; nt < 16; nt++) {
            int n = nh * 128 + nt * 8 + r4;
            uint2 Bh = *(const uint2*)&bb[n * 8 + 2 * c4];
            uint2 Bl = *(const uint2*)&bb[2048 + n * 8 + 2 * c4];
            mma16816(acc[nt], a0h, a1h, a2h, a3h, Bh.x, Bh.y);
            mma16816(acc[nt], a0h, a1h, a2h, a3h, Bl.x, Bl.y);
            mma16816(acc[nt], a0l, a1l, a2l, a3l, Bh.x, Bh.y);
        }
        if (kt + 1 < 50) STCHUNK(buf ^ 1);
        __syncthreads();
    }
    // proj epilogue
#pragma unroll
    for (int ntp = 0; ntp < 8; ntp++) {
        int nt = ntp * 2;
        int nb0 = nh * 128 + nt * 8 + 2 * c4;
        int nb1 = nb0 + 8;
        float p00 = acc[nt][0] + sbg[nb0],   p01 = acc[nt][1] + sbg[nb0+1];
        float p10 = acc[nt+1][0] + sbg[nb1], p11 = acc[nt+1][1] + sbg[nb1+1];
        float q00 = acc[nt][2] + sbg[nb0],   q01 = acc[nt][3] + sbg[nb0+1];
        float q10 = acc[nt+1][2] + sbg[nb1], q11 = acc[nt+1][3] + sbg[nb1+1];
        unsigned he0, le0, he1, le1;
        int wlo = rlo * AST + (nh * 8 + ntp) * 8 + 2 * c4;
        int whi = rhi * AST + (nh * 8 + ntp) * 8 + 2 * c4;
        splitpack(p00, p01, he0, le0); splitpack(p10, p11, he1, le1);
        *(uint2*)&Ah[wlo] = make_uint2(he0, he1);
        *(uint2*)&Al[wlo] = make_uint2(le0, le1);
        splitpack(q00, q01, he0, le0); splitpack(q10, q11, he1, le1);
        *(uint2*)&Ah[whi] = make_uint2(he0, he1);
        *(uint2*)&Al[whi] = make_uint2(le0, le1);
    }
    __syncthreads();

    // ================= 20 estep iterations =================
    for (int st = 0; st < MST; st++) {
#pragma unroll
        for (int nt = 0; nt < 16; nt++)
#pragma unroll
            for (int q = 0; q < 4; q++) acc[nt][q] = 0.f;

        LDCHUNK(g_Be);
        STCHUNK(0);
        __syncthreads();
        for (int kt = 0; kt < 16; kt++) {
            int buf = kt & 1;
            if (kt + 1 < 16) LDCHUNK(g_Be + (size_t)(kt + 1) * 4096);
            uint2 UA  = *(uint2*)&Ah[rlo * AST + kt * 8 + 2 * c4];
            uint2 VA  = *(uint2*)&Ah[rhi * AST + kt * 8 + 2 * c4];
            uint2 UAl = *(uint2*)&Al[rlo * AST + kt * 8 + 2 * c4];
            uint2 VAl = *(uint2*)&Al[rhi * AST + kt * 8 + 2 * c4];
            const unsigned* bb = &Bsm[buf * 4096];
#pragma unroll
            for (int nt = 0; nt < 16; nt++) {
                int n = nh * 128 + nt * 8 + r4;
                uint2 Bh = *(const uint2*)&bb[n * 8 + 2 * c4];
                uint2 Bl = *(const uint2*)&bb[2048 + n * 8 + 2 * c4];
                mma16816(acc[nt], UA.x, VA.x, UA.y, VA.y, Bh.x, Bh.y);
                mma16816(acc[nt], UA.x, VA.x, UA.y, VA.y, Bl.x, Bl.y);
                mma16816(acc[nt], UAl.x, VAl.x, UAl.y, VAl.y, Bh.x, Bh.y);
            }
            if (kt + 1 < 16) STCHUNK(buf ^ 1);
            __syncthreads();
        }

        float xel = xs[rlo], xeh = xs[rhi];
        float pl = 0.f, ph = 0.f;
#pragma unroll
        for (int ntp = 0; ntp < 8; ntp++) {
            int nt = ntp * 2;
            int nb0 = nh * 128 + nt * 8 + 2 * c4;
            int nb1 = nb0 + 8;
            float b00 = sbe[nb0], b01 = sbe[nb0+1], b10 = sbe[nb1], b11 = sbe[nb1+1];
            float w00 = swi[nb0], w01 = swi[nb0+1], w10 = swi[nb1], w11 = swi[nb1+1];
            float h00 = tanhfast(acc[nt][0]   + b00 + xel * w00);
            float h01 = tanhfast(acc[nt][1]   + b01 + xel * w01);
            float h10 = tanhfast(acc[nt+1][0] + b10 + xel * w10);
            float h11 = tanhfast(acc[nt+1][1] + b11 + xel * w11);
            float g00 = tanhfast(acc[nt][2]   + b00 + xeh * w00);
            float g01 = tanhfast(acc[nt][3]   + b01 + xeh * w01);
            float g10 = tanhfast(acc[nt+1][2] + b10 + xeh * w10);
            float g11 = tanhfast(acc[nt+1][3] + b11 + xeh * w11);
            float c00 = swc[nb0], c01 = swc[nb0+1], c10 = swc[nb1], c11 = swc[nb1+1];
            pl += h00 * c00 + h01 * c01 + h10 * c10 + h11 * c11;
            ph += g00 * c00 + g01 * c01 + g10 * c10 + g11 * c11;
            unsigned he0, le0, he1, le1;
            int wlo = rlo * AST + (nh * 8 + ntp) * 8 + 2 * c4;
            int whi = rhi * AST + (nh * 8 + ntp) * 8 + 2 * c4;
            splitpack(h00, h01, he0, le0); splitpack(h10, h11, he1, le1);
            *(uint2*)&Ah[wlo] = make_uint2(he0, he1);
            *(uint2*)&Al[wlo] = make_uint2(le0, le1);
            splitpack(g00, g01, he0, le0); splitpack(g10, g11, he1, le1);
            *(uint2*)&Ah[whi] = make_uint2(he0, he1);
            *(uint2*)&Al[whi] = make_uint2(le0, le1);
        }
        pl += __shfl_xor_sync(0xffffffffu, pl, 1);
        pl += __shfl_xor_sync(0xffffffffu, pl, 2);
        ph += __shfl_xor_sync(0xffffffffu, ph, 1);
        ph += __shfl_xor_sync(0xffffffffu, ph, 2);
        if (c4 == 0) {
            lp[nh * 64 + rlo] = pl;
            lp[nh * 64 + rhi] = ph;
        }
        __syncthreads();
        if (tid < 64) {
            float logit = lp[tid] + lp[64 + tid] + bcl;
            g_Ap[(size_t)(m0 + tid) * MST + st] = logit;
            xs[tid] = logit;
        }
        __syncthreads();
    }
#undef LDCHUNK
#undef STCHUNK
}

// ---------------- arc band gather ----------------
__global__ void k_arc(float* __restrict__ out) {
    size_t idx = (size_t)blockIdx.x * blockDim.x + threadIdx.x;
    size_t total = (size_t)BB * SL * SL;
    if (idx >= total) return;
    int c = (int)(idx % SL);
    int r = (int)((idx / SL) % SL);
    int b = (int)(idx / ((size_t)SL * SL));
    int start = r - MST; if (start < 0) start = 0;
    float v = 0.f;
    if (c >= start && c < r) v = g_Ap[(size_t)(b * SL + r) * MST + (c - start)];
    out[idx] = v;
}

// ---------------- host launcher ----------------
extern "C" void kernel_launch(void* const* d_in, const int* in_sizes, int n_in,
                              void* d_out, int out_size) {
    const float* input  = (const float*)d_in[0];
    const float* tagemb = (const float*)d_in[1];
    const int*   mask   = (const int*)d_in[2];
    const float* sent   = (const float*)d_in[3];
    const float* Wih_f  = (const float*)d_in[4];
    const float* Whh_f  = (const float*)d_in[5];
    const float* bih_f  = (const float*)d_in[6];
    const float* bhh_f  = (const float*)d_in[7];
    const float* Wih_b  = (const float*)d_in[8];
    const float* Whh_b  = (const float*)d_in[9];
    const float* bih_b  = (const float*)d_in[10];
    const float* bhh_b  = (const float*)d_in[11];
    const float* Wg2e   = (const float*)d_in[12];
    const float* bg2e   = (const float*)d_in[13];
    const float* Wih_e  = (const float*)d_in[14];
    const float* Whh_e  = (const float*)d_in[15];
    const float* bih_e  = (const float*)d_in[16];
    const float* bhh_e  = (const float*)d_in[17];
    const float* Wcls   = (const float*)d_in[18];
    const float* bcls   = (const float*)d_in[19];
    const float* bos    = (const float*)d_in[20];
    const float* Wht    = (const float*)d_in[21];
    const float* bht    = (const float*)d_in[22];
    const float* Wdt    = (const float*)d_in[23];
    const float* bdt    = (const float*)d_in[24];
    float* out = (float*)d_out;

    float *pX, *pPre, *pGS, *pbFB, *pbTag;
    unsigned *pBpre, *pBtag;
    cudaGetSymbolAddress((void**)&pX, g_X);
    cudaGetSymbolAddress((void**)&pPre, g_Pre);
    cudaGetSymbolAddress((void**)&pGS, g_GS);
    cudaGetSymbolAddress((void**)&pbFB, g_biasFB);
    cudaGetSymbolAddress((void**)&pbTag, g_biasTag);
    cudaGetSymbolAddress((void**)&pBpre, g_Bpre);
    cudaGetSymbolAddress((void**)&pBtag, g_Btag);

    static cudaStream_t s2 = nullptr;
    static cudaEvent_t evA = nullptr, evB = nullptr;
    static int inited = 0;
    if (!inited) {
        cudaFuncSetAttribute(k_eloop, cudaFuncAttributeMaxDynamicSharedMemorySize, ELOOP_SMEM);
        cudaFuncSetAttribute(k_rnn, cudaFuncAttributeMaxDynamicSharedMemorySize, RNN_SMEM);
        cudaStreamCreateWithFlags(&s2, cudaStreamNonBlocking);
        cudaEventCreateWithFlags(&evA, cudaEventDisableTiming);
        cudaEventCreateWithFlags(&evB, cudaEventDisableTiming);
        inited = 1;
    }

    // 1. fused setup
    {
        size_t n = TSETUP;
        k_setup<<<(unsigned)((n + 255) / 256), 256>>>(Wih_f, Wih_b, Wg2e, Whh_e, Wht, Wdt,
                                                      Whh_f, Whh_b,
                                                      bih_f, bhh_f, bih_b, bhh_b,
                                                      bih_e, bhh_e, bht, bdt,
                                                      input, tagemb, sent, mask);
    }
    // 2. Pre GEMM (split-bf16 HMMA)
    {
        dim3 grid(NPRE / 128, MR / 128);
        k_hgemm<0><<<grid, 256>>>(pX, pBpre, pbFB, pPre, nullptr, NPRE, DL, NPRE);
    }
    // 3. bidirectional recurrence
    k_rnn<<<32, 256, RNN_SMEM>>>();
    // fork: tags GEMM depends only on g_GS -> run concurrently with eloop
    cudaEventRecord(evA, 0);
    cudaStreamWaitEvent(s2, evA, 0);
    {
        dim3 grid(2, MR / 128);
        k_hgemm<2><<<grid, 256, 0, s2>>>(pGS, pBtag, pbTag, out, out + (size_t)MR * TAGL,
                                         2 * TAGL, 2 * HG, 2 * TAGL);
    }
    cudaEventRecord(evB, s2);
    // 4. proj + estep chain (64 rows/CTA, 2 CTAs/SM)
    k_eloop<<<MR / 64, 256, ELOOP_SMEM>>>(Wih_e, Wcls, bcls, bos, bg2e);
    // 5. arc logits
    {
        size_t total = (size_t)BB * SL * SL;
        k_arc<<<(unsigned)((total + 255) / 256), 256>>>(out + 2 * (size_t)MR * TAGL);
    }
    // join side stream
    cudaStreamWaitEvent(0, evB, 0);
    (void)in_sizes; (void)n_in; (void)out_size;
}

// round 12
// speedup vs baseline: 3.5678x; 1.2002x over previous
#include <cuda_runtime.h>
#include <cuda_bf16.h>
#include <math.h>

#define BB   64
#define TL   383
#define SL   384
#define DL   896
#define HG   400
#define HEH  256
#define TAGL 128
#define MST  20
#define MR   (BB*SL)    // 24576
#define NPRE 896        // padded 2*HG

// ---------------- scratch (device globals) ----------------
__device__ float g_X[(size_t)MR*DL];
__device__ float g_Mf[MR];
__device__ float g_Pre[(size_t)MR*NPRE];
__device__ float g_GS[(size_t)MR*2*HG];
__device__ float g_Ap[MR*MST];
__device__ float g_biasFB[NPRE];
__device__ float g_biasE[HEH];
__device__ float g_biasTag[2*TAGL];
__device__ unsigned g_Be[16*2*2048];
__device__ unsigned g_Bp[50*2*2048];
__device__ unsigned g_Bpre[56*2*7168];
__device__ unsigned g_Btag[50*2*2048];
__device__ unsigned g_Bw[16*25600];
// H exchange: [cluster 8][pp 2][split 2][b 16][word 200]
__device__ unsigned g_HXP[8*2*2*16*200];

#define CLUSTER_SYNC_() do { \
    asm volatile("barrier.cluster.arrive.aligned;" ::: "memory"); \
    asm volatile("barrier.cluster.wait.aligned;" ::: "memory"); \
} while (0)

// ---------------- helpers ----------------
__device__ __forceinline__ void splitpack(float x0, float x1, unsigned& hi, unsigned& lo) {
    __nv_bfloat16 b0 = __float2bfloat16_rn(x0);
    __nv_bfloat16 b1 = __float2bfloat16_rn(x1);
    float r0 = x0 - __bfloat162float(b0);
    float r1 = x1 - __bfloat162float(b1);
    __nv_bfloat16 c0 = __float2bfloat16_rn(r0);
    __nv_bfloat16 c1 = __float2bfloat16_rn(r1);
    hi = (unsigned)__bfloat16_as_ushort(b0) | ((unsigned)__bfloat16_as_ushort(b1) << 16);
    lo = (unsigned)__bfloat16_as_ushort(c0) | ((unsigned)__bfloat16_as_ushort(c1) << 16);
}

__device__ __forceinline__ void mma16816(float* d, unsigned a0, unsigned a1, unsigned a2,
                                         unsigned a3, unsigned b0, unsigned b1) {
    asm volatile(
        "mma.sync.aligned.m16n8k16.row.col.f32.bf16.bf16.f32 "
        "{%0,%1,%2,%3},{%4,%5,%6,%7},{%8,%9},{%0,%1,%2,%3};"
        : "+f"(d[0]), "+f"(d[1]), "+f"(d[2]), "+f"(d[3])
        : "r"(a0), "r"(a1), "r"(a2), "r"(a3), "r"(b0), "r"(b1));
}

__device__ __forceinline__ float tanhfast(float x) {
    float e = __expf(2.f * x);
    return 1.f - __fdividef(2.f, e + 1.f);
}

__device__ __forceinline__ int word_of_k(int k) {
    int kt = k >> 4, rem = k & 15;
    int s = (rem < 8) ? rem : (rem - 7);
    return kt * 8 + s;
}

// ---------------- setup (split: main / side) ----------------
#define S1 (56*2*7168)   // g_Bpre
#define S6 (NPRE)        // biasFB
#define TBUILD ((size_t)MR*DL + MR)
#define TMAIN ((size_t)S1 + S6 + TBUILD)

__global__ void k_setup_main(const float* __restrict__ Wih_f, const float* __restrict__ Wih_b,
                             const float* __restrict__ bih_f, const float* __restrict__ bhh_f,
                             const float* __restrict__ bih_b, const float* __restrict__ bhh_b,
                             const float* __restrict__ inp, const float* __restrict__ tag,
                             const float* __restrict__ sent, const int* __restrict__ mask) {
    size_t gidx = (size_t)blockIdx.x * blockDim.x + threadIdx.x;
    if (gidx < S1) {
        int idx = (int)gidx;
        int kt = idx / 14336, rest = idx % 14336;
        int split = rest / 7168, w = rest % 7168;
        int n = w >> 3, s = w & 7;
        int k = kt * 16 + 2 * (s >> 1) + 8 * (s & 1);
        float x0 = 0.f, x1 = 0.f;
        if (n < HG)          { x0 = Wih_f[(size_t)n * DL + k];        x1 = Wih_f[(size_t)n * DL + k + 1]; }
        else if (n < 2*HG)   { x0 = Wih_b[(size_t)(n-HG) * DL + k];   x1 = Wih_b[(size_t)(n-HG) * DL + k + 1]; }
        unsigned hi, lo; splitpack(x0, x1, hi, lo);
        g_Bpre[idx] = split ? lo : hi; return;
    }
    gidx -= S1;
    if (gidx < S6) {
        int idx = (int)gidx;
        float v = 0.f;
        if (idx < HG) v = bih_f[idx] + bhh_f[idx];
        else if (idx < 2*HG) v = bih_b[idx-HG] + bhh_b[idx-HG];
        g_biasFB[idx] = v; return;
    }
    gidx -= S6;
    size_t nx = (size_t)MR * DL;
    if (gidx < nx) {
        int d = (int)(gidx % DL);
        int m = (int)(gidx / DL);
        int b = m / SL, s = m % SL;
        float v;
        if (s == 0) v = sent[d];
        else {
            int t = s - 1;
            v = (d < 768) ? inp[(size_t)(b * TL + t) * 768 + d]
                          : tag[(size_t)(b * TL + t) * TAGL + (d - 768)];
        }
        g_X[gidx] = v;
        return;
    }
    gidx -= nx;
    if (gidx < MR) {
        int b = (int)(gidx / SL), s = (int)(gidx % SL);
        g_Mf[gidx] = (s == 0) ? 1.0f : (float)mask[b * TL + s - 1];
    }
}

#define P2 (50*2*2048)   // g_Bp
#define P3 (16*2*2048)   // g_Be
#define P4 (50*2*2048)   // g_Btag
#define P5 (16*25600)    // g_Bw
#define P7 (HEH)
#define P8 (2*TAGL)
#define TSIDE (P2+P3+P4+P5+P7+P8)

__global__ void k_setup_side(const float* __restrict__ Wg2e, const float* __restrict__ Whh_e,
                             const float* __restrict__ Wht,  const float* __restrict__ Wdt,
                             const float* __restrict__ Whh_f, const float* __restrict__ Whh_b,
                             const float* __restrict__ bih_e, const float* __restrict__ bhh_e,
                             const float* __restrict__ bht,   const float* __restrict__ bdt) {
    int idx = blockIdx.x * blockDim.x + threadIdx.x;
    if (idx < P2) {
        int kt = idx >> 12, rest = idx & 4095;
        int split = rest >> 11, w = rest & 2047;
        int n = w >> 3, s = w & 7;
        int k = kt * 16 + 2 * (s >> 1) + 8 * (s & 1);
        float x0 = Wg2e[(size_t)n * (2*HG) + k];
        float x1 = Wg2e[(size_t)n * (2*HG) + k + 1];
        unsigned hi, lo; splitpack(x0, x1, hi, lo);
        g_Bp[idx] = split ? lo : hi; return;
    }
    idx -= P2;
    if (idx < P3) {
        int kt = idx >> 12, rest = idx & 4095;
        int split = rest >> 11, w = rest & 2047;
        int n = w >> 3, s = w & 7;
        int k = kt * 16 + 2 * (s >> 1) + 8 * (s & 1);
        float x0 = Whh_e[(size_t)n * HEH + k];
        float x1 = Whh_e[(size_t)n * HEH + k + 1];
        unsigned hi, lo; splitpack(x0, x1, hi, lo);
        g_Be[idx] = split ? lo : hi; return;
    }
    idx -= P3;
    if (idx < P4) {
        int kt = idx >> 12, rest = idx & 4095;
        int split = rest >> 11, w = rest & 2047;
        int n = w >> 3, s = w & 7;
        int k = kt * 16 + 2 * (s >> 1) + 8 * (s & 1);
        float x0, x1;
        if (n < TAGL) { x0 = Wht[(size_t)n * (2*HG) + k];        x1 = Wht[(size_t)n * (2*HG) + k + 1]; }
        else          { x0 = Wdt[(size_t)(n-TAGL) * (2*HG) + k]; x1 = Wdt[(size_t)(n-TAGL) * (2*HG) + k + 1]; }
        unsigned hi, lo; splitpack(x0, x1, hi, lo);
        g_Btag[idx] = split ? lo : hi; return;
    }
    idx -= P4;
    if (idx < P5) {
        int ctx = idx / 25600, rest = idx % 25600;
        int dir = ctx >> 3, jgx = ctx & 7;
        int kt = rest >> 10, r2 = rest & 1023;
        int split = r2 >> 9, r3 = r2 & 511;
        int n = r3 >> 3, s = r3 & 7;
        int k = kt * 16 + 2 * (s >> 1) + 8 * (s & 1);
        float x0 = 0.f, x1 = 0.f;
        if (n < 50) {
            const float* W = dir ? Whh_b : Whh_f;
            int j = jgx * 50 + n;
            x0 = W[(size_t)j * HG + k];
            x1 = W[(size_t)j * HG + k + 1];
        }
        unsigned hi, lo; splitpack(x0, x1, hi, lo);
        g_Bw[idx] = split ? lo : hi; return;
    }
    idx -= P5;
    if (idx < P7) { g_biasE[idx] = bih_e[idx] + bhh_e[idx]; return; }
    idx -= P7;
    if (idx < P8) g_biasTag[idx] = (idx < TAGL) ? bht[idx] : bdt[idx - TAGL];
}

// ---------------- split-bf16 HMMA GEMM, 128x128 tile ----------------
template <int ACT>
__global__ __launch_bounds__(256) void k_hgemm(const float* __restrict__ A,
                                               const unsigned* __restrict__ Bfrag,
                                               const float* __restrict__ bias,
                                               float* __restrict__ C, float* __restrict__ C2,
                                               int N, int K, int Nfrag) {
    __shared__ __align__(16) unsigned Ahs[2][1024];
    __shared__ __align__(16) unsigned Als[2][1024];
    __shared__ __align__(16) unsigned Bsm[2][2048];
    int m0 = blockIdx.y * 128, n0 = blockIdx.x * 128;
    int tid = threadIdx.x, wid = tid >> 5, lane = tid & 31;
    int mw = wid & 3, nh = wid >> 2;
    int r4 = lane >> 2, c4 = lane & 3;
    int nkt = K >> 4;
    int Nw8 = Nfrag * 8;

    int arow = tid >> 1, sg = (tid & 1) * 4;
    const float* Apt = A + (size_t)(m0 + arow) * K;

    float2 af[4];
    uint2  bf[4];
    float acc[2][8][4];
#pragma unroll
    for (int mt = 0; mt < 2; mt++)
#pragma unroll
        for (int nt = 0; nt < 8; nt++)
#pragma unroll
            for (int q = 0; q < 4; q++) acc[mt][nt][q] = 0.f;

#define HLD(KT) do { \
        _Pragma("unroll") for (int s_ = 0; s_ < 4; s_++) { \
            int s = sg + s_; int kl = 2 * (s >> 1) + 8 * (s & 1); \
            af[s_] = *(const float2*)(Apt + (size_t)(KT) * 16 + kl); } \
        _Pragma("unroll") for (int i_ = 0; i_ < 4; i_++) { \
            int lw = 2 * (i_ * 256 + tid); \
            int sp = lw >> 10, wq = lw & 1023; \
            bf[i_] = *(const uint2*)(Bfrag + (size_t)(KT) * 2 * Nw8 + (size_t)sp * Nw8 + n0 * 8 + wq); } \
    } while (0)

#define HST(BUF) do { \
        unsigned h_[4], l_[4]; \
        _Pragma("unroll") for (int s_ = 0; s_ < 4; s_++) splitpack(af[s_].x, af[s_].y, h_[s_], l_[s_]); \
        *(uint4*)&Ahs[BUF][arow * 8 + sg] = make_uint4(h_[0], h_[1], h_[2], h_[3]); \
        *(uint4*)&Als[BUF][arow * 8 + sg] = make_uint4(l_[0], l_[1], l_[2], l_[3]); \
        _Pragma("unroll") for (int i_ = 0; i_ < 4; i_++) \
            *(uint2*)&Bsm[BUF][2 * (i_ * 256 + tid)] = bf[i_]; \
    } while (0)

    HLD(0);
    HST(0);
    __syncthreads();
    for (int kt = 0; kt < nkt; kt++) {
        int buf = kt & 1;
        if (kt + 1 < nkt) HLD(kt + 1);
        uint2 Uh[2], Vh[2], Ul[2], Vl[2];
#pragma unroll
        for (int mt = 0; mt < 2; mt++) {
            int rb = mw * 32 + mt * 16 + r4;
            Uh[mt] = *(uint2*)&Ahs[buf][rb * 8 + 2 * c4];
            Vh[mt] = *(uint2*)&Ahs[buf][(rb + 8) * 8 + 2 * c4];
            Ul[mt] = *(uint2*)&Als[buf][rb * 8 + 2 * c4];
            Vl[mt] = *(uint2*)&Als[buf][(rb + 8) * 8 + 2 * c4];
        }
#pragma unroll
        for (int nt = 0; nt < 8; nt++) {
            int n = nh * 64 + nt * 8 + r4;
            uint2 Bh = *(uint2*)&Bsm[buf][n * 8 + 2 * c4];
            uint2 Bl = *(uint2*)&Bsm[buf][1024 + n * 8 + 2 * c4];
#pragma unroll
            for (int mt = 0; mt < 2; mt++) {
                mma16816(acc[mt][nt], Uh[mt].x, Vh[mt].x, Uh[mt].y, Vh[mt].y, Bh.x, Bh.y);
                mma16816(acc[mt][nt], Uh[mt].x, Vh[mt].x, Uh[mt].y, Vh[mt].y, Bl.x, Bl.y);
                mma16816(acc[mt][nt], Ul[mt].x, Vl[mt].x, Ul[mt].y, Vl[mt].y, Bh.x, Bh.y);
            }
        }
        if (kt + 1 < nkt) HST(buf ^ 1);
        __syncthreads();
    }
#undef HLD
#undef HST

#pragma unroll
    for (int nt = 0; nt < 8; nt++) {
        int colL = nh * 64 + nt * 8 + 2 * c4;
        float b0 = bias[n0 + colL], b1 = bias[n0 + colL + 1];
#pragma unroll
        for (int mt = 0; mt < 2; mt++) {
            int r = m0 + mw * 32 + mt * 16 + r4;
            float v0 = acc[mt][nt][0] + b0, v1 = acc[mt][nt][1] + b1;
            float v2 = acc[mt][nt][2] + b0, v3 = acc[mt][nt][3] + b1;
            if (ACT == 2) {
                v0 = (v0 > 0.f) ? v0 : expm1f(v0);
                v1 = (v1 > 0.f) ? v1 : expm1f(v1);
                v2 = (v2 > 0.f) ? v2 : expm1f(v2);
                v3 = (v3 > 0.f) ? v3 : expm1f(v3);
                float* dst = (blockIdx.x == 0) ? C : C2;
                *(float2*)(dst + (size_t)r * TAGL + colL)       = make_float2(v0, v1);
                *(float2*)(dst + (size_t)(r + 8) * TAGL + colL) = make_float2(v2, v3);
            } else {
                *(float2*)(C + (size_t)r * N + n0 + colL)       = make_float2(v0, v1);
                *(float2*)(C + (size_t)(r + 8) * N + n0 + colL) = make_float2(v2, v3);
            }
        }
    }
}

// ---------------- HMMA bidirectional masked RNN (8 clusters of 8, 16 batches/CTA) ----------------
#define RAS 200
#define RNN_SMEM ((25600 + 2*16*RAS) * 4)

__global__ void __cluster_dims__(8, 1, 1) __launch_bounds__(256, 1) k_rnn() {
    extern __shared__ unsigned rsm[];
    unsigned* Bs = rsm;             // 25kt x 2split x 64n x 8 = 25600 words
    unsigned* Ah = rsm + 25600;     // 16 x 200
    unsigned* Al = Ah + 16 * RAS;

    int bx = blockIdx.x;
    int cl = bx >> 3, jg = bx & 7;
    int dir = cl >> 2, bg = cl & 3;
    int bbase = bg * 16;
    int tid = threadIdx.x, wid = tid >> 5, lane = tid & 31;
    int ng = wid;                  // each warp owns one 8-col n-tile
    int r4 = lane >> 2, c4 = lane & 3;
    int rlo = r4, rhi = r4 + 8;

    // one-time: B fragments -> smem
    {
        const uint2* bsrc = (const uint2*)(g_Bw + (size_t)(dir * 8 + jg) * 25600);
#pragma unroll
        for (int i = 0; i < 50; i++) {
            int idx = tid + i * 256;
            uint2 v = __ldcg(bsrc + idx);
            *(uint2*)&Bs[2 * idx] = v;
        }
    }
    // zero exactly the words this CTA will write, pp=0
    {
        unsigned* hxp0 = g_HXP + (size_t)(cl * 2 + 0) * 6400;
        for (int idx = tid; idx < 800; idx += 256) {
            int split = idx / 400, rest = idx % 400;
            int b = rest / 25, w = rest % 25;
            int p = word_of_k(jg * 50 + 2 * w);
            __stcg(&hxp0[split * 3200 + b * 200 + p], 0u);
        }
    }
    __syncthreads();
    CLUSTER_SYNC_();

    int jl = ng * 8 + 2 * c4;
    int valid = (jl < 50);
    int wdp = word_of_k(jg * 50 + jl);
    float h[2][2];
#pragma unroll
    for (int a = 0; a < 2; a++) { h[a][0] = 0.f; h[a][1] = 0.f; }

    for (int tv = 0; tv < SL; tv++) {
        int t = dir ? (SL - 1 - tv) : tv;
        int pp = tv & 1;
        const uint2* src = (const uint2*)(g_HXP + (size_t)(cl * 2 + pp) * 6400);
        // stage A fragments: 3200 uint2
        uint2 bp[13];
#pragma unroll
        for (int i = 0; i < 13; i++) {
            int idx = tid + i * 256;
            if (idx < 3200) {
                int split = idx / 1600, rest = idx % 1600;
                int b = rest / 100, wp = rest % 100;
                bp[i] = __ldcg(src + (size_t)split * 1600 + b * 100 + wp);
            }
        }
        float mv[2];
        mv[0] = g_Mf[(bbase + rlo) * SL + t];
        mv[1] = g_Mf[(bbase + rhi) * SL + t];
        float2 pre[2];
#pragma unroll
        for (int rq = 0; rq < 2; rq++) {
            int R = rq ? rhi : rlo;
            pre[rq] = *(const float2*)(g_Pre + (size_t)((bbase + R) * SL + t) * NPRE + dir * HG + jg * 50 + jl);
        }
#pragma unroll
        for (int i = 0; i < 13; i++) {
            int idx = tid + i * 256;
            if (idx < 3200) {
                int split = idx / 1600, rest = idx % 1600;
                int b = rest / 100, wp = rest % 100;
                unsigned* dst = split ? Al : Ah;
                *(uint2*)&dst[b * RAS + wp * 2] = bp[i];
            }
        }
        __syncthreads();

        float acc[4];
#pragma unroll
        for (int z = 0; z < 4; z++) acc[z] = 0.f;
#pragma unroll
        for (int kt = 0; kt < 25; kt++) {
            uint2 UA  = *(uint2*)&Ah[rlo * RAS + kt * 8 + 2 * c4];
            uint2 VA  = *(uint2*)&Ah[rhi * RAS + kt * 8 + 2 * c4];
            uint2 UAl = *(uint2*)&Al[rlo * RAS + kt * 8 + 2 * c4];
            uint2 VAl = *(uint2*)&Al[rhi * RAS + kt * 8 + 2 * c4];
            int n = ng * 8 + r4;
            uint2 Bh = *(uint2*)&Bs[(kt * 2) * 512 + n * 8 + 2 * c4];
            uint2 Bl = *(uint2*)&Bs[(kt * 2 + 1) * 512 + n * 8 + 2 * c4];
            mma16816(acc, UA.x, VA.x, UA.y, VA.y, Bh.x, Bh.y);
            mma16816(acc, UA.x, VA.x, UA.y, VA.y, Bl.x, Bl.y);
            mma16816(acc, UAl.x, VAl.x, UAl.y, VAl.y, Bh.x, Bh.y);
        }
        __syncthreads();

        unsigned* dsth = g_HXP + (size_t)(cl * 2 + (pp ^ 1)) * 6400;
#pragma unroll
        for (int rq = 0; rq < 2; rq++) {
            int R = rq ? rhi : rlo;
            float mt = mv[rq], om = 1.f - mt;
            float u0 = mt * tanhfast(pre[rq].x + acc[rq * 2 + 0]) + om * h[rq][0];
            float u1 = mt * tanhfast(pre[rq].y + acc[rq * 2 + 1]) + om * h[rq][1];
            h[rq][0] = u0; h[rq][1] = u1;
            if (valid) {
                unsigned hi, lo; splitpack(u0, u1, hi, lo);
                __stcg(&dsth[R * 200 + wdp], hi);
                __stcg(&dsth[3200 + R * 200 + wdp], lo);
                *(float2*)(g_GS + (size_t)((bbase + R) * SL + t) * (2 * HG) + dir * HG + jg * 50 + jl)
                    = make_float2(u0 * mt, u1 * mt);
            }
        }
        CLUSTER_SYNC_();
    }
}

// ---------------- tensor-core proj + 20-step estep loop (64 rows/CTA, 2 CTAs/SM) ----------------
#define AST 136
#define ELOOP_WORDS (2*8704 + 8192 + 1024 + 64 + 128)
#define ELOOP_SMEM  (ELOOP_WORDS * 4)

__global__ __launch_bounds__(256, 2) void k_eloop(const float* __restrict__ wie,
                                                  const float* __restrict__ wcls,
                                                  const float* __restrict__ bcls,
                                                  const float* __restrict__ bos,
                                                  const float* __restrict__ bg2e) {
    extern __shared__ unsigned sm_u[];
    unsigned* Ah  = sm_u;
    unsigned* Al  = sm_u + 8704;
    unsigned* Bsm = sm_u + 17408;
    float* sbe = (float*)(sm_u + 25600);
    float* swi = sbe + 256;
    float* swc = sbe + 512;
    float* sbg = sbe + 768;
    float* xs  = sbe + 1024;
    float* lp  = xs + 64;

    int tid = threadIdx.x;
    int wid = tid >> 5, lane = tid & 31;
    int mw = wid & 3, nh = wid >> 2;
    int r4 = lane >> 2, c4 = lane & 3;
    int m0 = blockIdx.x * 64;
    int rlo = mw * 16 + r4, rhi = rlo + 8;

    sbe[tid] = g_biasE[tid & 255];
    swi[tid] = wie[tid & 255];
    swc[tid] = wcls[tid & 255];
    sbg[tid] = bg2e[tid & 255];
    if (tid < 64) xs[tid] = bos[0];
    float bcl = bcls[0];

    float acc[16][4];
    uint2 bp[8];

#define LDCHUNK(gsrc) do { \
        const uint2* s_ = (const uint2*)(gsrc); \
        _Pragma("unroll") for (int i_ = 0; i_ < 8; i_++) bp[i_] = s_[i_ * 256 + tid]; \
    } while (0)
#define STCHUNK(BUF) do { \
        _Pragma("unroll") for (int i_ = 0; i_ < 8; i_++) \
            *(uint2*)&Bsm[(BUF) * 4096 + 2 * (i_ * 256 + tid)] = bp[i_]; \
    } while (0)

    // proj phase
#pragma unroll
    for (int nt = 0; nt < 16; nt++)
#pragma unroll
        for (int q = 0; q < 4; q++) acc[nt][q] = 0.f;

    const float* gsA = g_GS + (size_t)m0 * (2*HG);
    LDCHUNK(g_Bp);
    STCHUNK(0);
    __syncthreads();
    for (int kt = 0; kt < 50; kt++) {
        int buf = kt & 1;
        if (kt + 1 < 50) LDCHUNK(g_Bp + (size_t)(kt + 1) * 4096);
        float2 x0 = *(const float2*)(gsA + (size_t)rlo * 800 + kt * 16 + 2 * c4);
        float2 x2 = *(const float2*)(gsA + (size_t)rlo * 800 + kt * 16 + 2 * c4 + 8);
        float2 x1 = *(const float2*)(gsA + (size_t)rhi * 800 + kt * 16 + 2 * c4);
        float2 x3 = *(const float2*)(gsA + (size_t)rhi * 800 + kt * 16 + 2 * c4 + 8);
        unsigned a0h, a0l, a1h, a1l, a2h, a2l, a3h, a3l;
        splitpack(x0.x, x0.y, a0h, a0l);
        splitpack(x1.x, x1.y, a1h, a1l);
        splitpack(x2.x, x2.y, a2h, a2l);
        splitpack(x3.x, x3.y, a3h, a3l);
        const unsigned* bb = &Bsm[buf * 4096];
#pragma unroll
        for (int nt = 0; nt < 16; nt++) {
            int n = nh * 128 + nt * 8 + r4;
            uint2 Bh = *(const uint2*)&bb[n * 8 + 2 * c4];
            uint2 Bl = *(const uint2*)&bb[2048 + n * 8 + 2 * c4];
            mma16816(acc[nt], a0h, a1h, a2h, a3h, Bh.x, Bh.y);
            mma16816(acc[nt], a0h, a1h, a2h, a3h, Bl.x, Bl.y);
            mma16816(acc[nt], a0l, a1l, a2l, a3l, Bh.x, Bh.y);
        }
        if (kt + 1 < 50) STCHUNK(buf ^ 1);
        __syncthreads();
    }
#pragma unroll
    for (int ntp = 0; ntp < 8; ntp++) {
        int nt = ntp * 2;
        int nb0 = nh * 128 + nt * 8 + 2 * c4;
        int nb1 = nb0 + 8;
        float p00 = acc[nt][0] + sbg[nb0],   p01 = acc[nt][1] + sbg[nb0+1];
        float p10 = acc[nt+1][0] + sbg[nb1], p11 = acc[nt+1][1] + sbg[nb1+1];
        float q00 = acc[nt][2] + sbg[nb0],   q01 = acc[nt][3] + sbg[nb0+1];
        float q10 = acc[nt+1][2] + sbg[nb1], q11 = acc[nt+1][3] + sbg[nb1+1];
        unsigned he0, le0, he1, le1;
        int wlo = rlo * AST + (nh * 8 + ntp) * 8 + 2 * c4;
        int whi = rhi * AST + (nh * 8 + ntp) * 8 + 2 * c4;
        splitpack(p00, p01, he0, le0); splitpack(p10, p11, he1, le1);
        *(uint2*)&Ah[wlo] = make_uint2(he0, he1);
        *(uint2*)&Al[wlo] = make_uint2(le0, le1);
        splitpack(q00, q01, he0, le0); splitpack(q10, q11, he1, le1);
        *(uint2*)&Ah[whi] = make_uint2(he0, he1);
        *(uint2*)&Al[whi] = make_uint2(le0, le1);
    }
    __syncthreads();

    // 20 estep iterations
    for (int st = 0; st < MST; st++) {
#pragma unroll
        for (int nt = 0; nt < 16; nt++)
#pragma unroll
            for (int q = 0; q < 4; q++) acc[nt][q] = 0.f;

        LDCHUNK(g_Be);
        STCHUNK(0);
        __syncthreads();
        for (int kt = 0; kt < 16; kt++) {
            int buf = kt & 1;
            if (kt + 1 < 16) LDCHUNK(g_Be + (size_t)(kt + 1) * 4096);
            uint2 UA  = *(uint2*)&Ah[rlo * AST + kt * 8 + 2 * c4];
            uint2 VA  = *(uint2*)&Ah[rhi * AST + kt * 8 + 2 * c4];
            uint2 UAl = *(uint2*)&Al[rlo * AST + kt * 8 + 2 * c4];
            uint2 VAl = *(uint2*)&Al[rhi * AST + kt * 8 + 2 * c4];
            const unsigned* bb = &Bsm[buf * 4096];
#pragma unroll
            for (int nt = 0; nt < 16; nt++) {
                int n = nh * 128 + nt * 8 + r4;
                uint2 Bh = *(const uint2*)&bb[n * 8 + 2 * c4];
                uint2 Bl = *(const uint2*)&bb[2048 + n * 8 + 2 * c4];
                mma16816(acc[nt], UA.x, VA.x, UA.y, VA.y, Bh.x, Bh.y);
                mma16816(acc[nt], UA.x, VA.x, UA.y, VA.y, Bl.x, Bl.y);
                mma16816(acc[nt], UAl.x, VAl.x, UAl.y, VAl.y, Bh.x, Bh.y);
            }
            if (kt + 1 < 16) STCHUNK(buf ^ 1);
            __syncthreads();
        }

        float xel = xs[rlo], xeh = xs[rhi];
        float pl = 0.f, ph = 0.f;
#pragma unroll
        for (int ntp = 0; ntp < 8; ntp++) {
            int nt = ntp * 2;
            int nb0 = nh * 128 + nt * 8 + 2 * c4;
            int nb1 = nb0 + 8;
            float b00 = sbe[nb0], b01 = sbe[nb0+1], b10 = sbe[nb1], b11 = sbe[nb1+1];
            float w00 = swi[nb0], w01 = swi[nb0+1], w10 = swi[nb1], w11 = swi[nb1+1];
            float h00 = tanhfast(acc[nt][0]   + b00 + xel * w00);
            float h01 = tanhfast(acc[nt][1]   + b01 + xel * w01);
            float h10 = tanhfast(acc[nt+1][0] + b10 + xel * w10);
            float h11 = tanhfast(acc[nt+1][1] + b11 + xel * w11);
            float g00 = tanhfast(acc[nt][2]   + b00 + xeh * w00);
            float g01 = tanhfast(acc[nt][3]   + b01 + xeh * w01);
            float g10 = tanhfast(acc[nt+1][2] + b10 + xeh * w10);
            float g11 = tanhfast(acc[nt+1][3] + b11 + xeh * w11);
            float c00 = swc[nb0], c01 = swc[nb0+1], c10 = swc[nb1], c11 = swc[nb1+1];
            pl += h00 * c00 + h01 * c01 + h10 * c10 + h11 * c11;
            ph += g00 * c00 + g01 * c01 + g10 * c10 + g11 * c11;
            unsigned he0, le0, he1, le1;
            int wlo = rlo * AST + (nh * 8 + ntp) * 8 + 2 * c4;
            int whi = rhi * AST + (nh * 8 + ntp) * 8 + 2 * c4;
            splitpack(h00, h01, he0, le0); splitpack(h10, h11, he1, le1);
            *(uint2*)&Ah[wlo] = make_uint2(he0, he1);
            *(uint2*)&Al[wlo] = make_uint2(le0, le1);
            splitpack(g00, g01, he0, le0); splitpack(g10, g11, he1, le1);
            *(uint2*)&Ah[whi] = make_uint2(he0, he1);
            *(uint2*)&Al[whi] = make_uint2(le0, le1);
        }
        pl += __shfl_xor_sync(0xffffffffu, pl, 1);
        pl += __shfl_xor_sync(0xffffffffu, pl, 2);
        ph += __shfl_xor_sync(0xffffffffu, ph, 1);
        ph += __shfl_xor_sync(0xffffffffu, ph, 2);
        if (c4 == 0) {
            lp[nh * 64 + rlo] = pl;
            lp[nh * 64 + rhi] = ph;
        }
        __syncthreads();
        if (tid < 64) {
            float logit = lp[tid] + lp[64 + tid] + bcl;
            g_Ap[(size_t)(m0 + tid) * MST + st] = logit;
            xs[tid] = logit;
        }
        __syncthreads();
    }
#undef LDCHUNK
#undef STCHUNK
}

// ---------------- arc: zero-fill (early, overlapped) + band fill (tiny, at end) ----------------
__global__ void k_arc_zero(float4* __restrict__ out4) {
    size_t idx = (size_t)blockIdx.x * blockDim.x + threadIdx.x;
    size_t total = (size_t)BB * SL * SL / 4;
    if (idx < total) out4[idx] = make_float4(0.f, 0.f, 0.f, 0.f);
}

__global__ void k_arc_band(float* __restrict__ out) {
    int idx = blockIdx.x * blockDim.x + threadIdx.x;
    if (idx >= MR * MST) return;
    int m = idx / MST, k = idx % MST;
    int b = m / SL, r = m % SL;
    int lim = (r < MST) ? r : MST;
    if (k < lim) {
        int start = r - MST; if (start < 0) start = 0;
        out[(size_t)b * SL * SL + (size_t)r * SL + start + k] = g_Ap[(size_t)m * MST + k];
    }
}

// ---------------- host launcher ----------------
extern "C" void kernel_launch(void* const* d_in, const int* in_sizes, int n_in,
                              void* d_out, int out_size) {
    const float* input  = (const float*)d_in[0];
    const float* tagemb = (const float*)d_in[1];
    const int*   mask   = (const int*)d_in[2];
    const float* sent   = (const float*)d_in[3];
    const float* Wih_f  = (const float*)d_in[4];
    const float* Whh_f  = (const float*)d_in[5];
    const float* bih_f  = (const float*)d_in[6];
    const float* bhh_f  = (const float*)d_in[7];
    const float* Wih_b  = (const float*)d_in[8];
    const float* Whh_b  = (const float*)d_in[9];
    const float* bih_b  = (const float*)d_in[10];
    const float* bhh_b  = (const float*)d_in[11];
    const float* Wg2e   = (const float*)d_in[12];
    const float* bg2e   = (const float*)d_in[13];
    const float* Wih_e  = (const float*)d_in[14];
    const float* Whh_e  = (const float*)d_in[15];
    const float* bih_e  = (const float*)d_in[16];
    const float* bhh_e  = (const float*)d_in[17];
    const float* Wcls   = (const float*)d_in[18];
    const float* bcls   = (const float*)d_in[19];
    const float* bos    = (const float*)d_in[20];
    const float* Wht    = (const float*)d_in[21];
    const float* bht    = (const float*)d_in[22];
    const float* Wdt    = (const float*)d_in[23];
    const float* bdt    = (const float*)d_in[24];
    float* out = (float*)d_out;

    float *pX, *pPre, *pGS, *pbFB, *pbTag;
    unsigned *pBpre, *pBtag;
    cudaGetSymbolAddress((void**)&pX, g_X);
    cudaGetSymbolAddress((void**)&pPre, g_Pre);
    cudaGetSymbolAddress((void**)&pGS, g_GS);
    cudaGetSymbolAddress((void**)&pbFB, g_biasFB);
    cudaGetSymbolAddress((void**)&pbTag, g_biasTag);
    cudaGetSymbolAddress((void**)&pBpre, g_Bpre);
    cudaGetSymbolAddress((void**)&pBtag, g_Btag);

    static cudaStream_t s2 = nullptr;
    static cudaEvent_t evRoot = nullptr, evSide = nullptr, evGS = nullptr, evTags = nullptr;
    static int inited = 0;
    if (!inited) {
        cudaFuncSetAttribute(k_eloop, cudaFuncAttributeMaxDynamicSharedMemorySize, ELOOP_SMEM);
        cudaFuncSetAttribute(k_rnn, cudaFuncAttributeMaxDynamicSharedMemorySize, RNN_SMEM);
        cudaStreamCreateWithFlags(&s2, cudaStreamNonBlocking);
        cudaEventCreateWithFlags(&evRoot, cudaEventDisableTiming);
        cudaEventCreateWithFlags(&evSide, cudaEventDisableTiming);
        cudaEventCreateWithFlags(&evGS, cudaEventDisableTiming);
        cudaEventCreateWithFlags(&evTags, cudaEventDisableTiming);
        inited = 1;
    }

    // fork side stream from origin
    cudaEventRecord(evRoot, 0);
    cudaStreamWaitEvent(s2, evRoot, 0);
    // side: weight prep for rnn/eloop/tags + arc zero-fill
    k_setup_side<<<(TSIDE + 255) / 256, 256, 0, s2>>>(Wg2e, Whh_e, Wht, Wdt, Whh_f, Whh_b,
                                                      bih_e, bhh_e, bht, bdt);
    {
        size_t tot4 = (size_t)BB * SL * SL / 4;
        k_arc_zero<<<(unsigned)((tot4 + 255) / 256), 256, 0, s2>>>(
            (float4*)(out + 2 * (size_t)MR * TAGL));
    }
    cudaEventRecord(evSide, s2);

    // main: input build + Pre weights
    k_setup_main<<<(unsigned)((TMAIN + 255) / 256), 256>>>(Wih_f, Wih_b, bih_f, bhh_f,
                                                           bih_b, bhh_b, input, tagemb,
                                                           sent, mask);
    // Pre GEMM
    {
        dim3 grid(NPRE / 128, MR / 128);
        k_hgemm<0><<<grid, 256>>>(pX, pBpre, pbFB, pPre, nullptr, NPRE, DL, NPRE);
    }
    // join side (g_Bw/Mf needed), then recurrence
    cudaStreamWaitEvent(0, evSide, 0);
    k_rnn<<<64, 256, RNN_SMEM>>>();
    // fork tags (depends only on g_GS)
    cudaEventRecord(evGS, 0);
    cudaStreamWaitEvent(s2, evGS, 0);
    {
        dim3 grid(2, MR / 128);
        k_hgemm<2><<<grid, 256, 0, s2>>>(pGS, pBtag, pbTag, out, out + (size_t)MR * TAGL,
                                         2 * TAGL, 2 * HG, 2 * TAGL);
    }
    cudaEventRecord(evTags, s2);
    // proj + estep chain
    k_eloop<<<MR / 64, 256, ELOOP_SMEM>>>(Wih_e, Wcls, bcls, bos, bg2e);
    // arc band fill
    k_arc_band<<<(MR * MST + 255) / 256, 256>>>(out + 2 * (size_t)MR * TAGL);
    // join
    cudaStreamWaitEvent(0, evTags, 0);
    (void)in_sizes; (void)n_in; (void)out_size;
}

// round 13
// speedup vs baseline: 3.6902x; 1.0343x over previous
#include <cuda_runtime.h>
#include <cuda_bf16.h>
#include <math.h>

#define BB   64
#define TL   383
#define SL   384
#define DL   896
#define HG   400
#define HEH  256
#define TAGL 128
#define MST  20
#define MR   (BB*SL)    // 24576
#define NPRE 896        // padded 2*HG
#define XW   448        // X fragment words per row (K=896)
#define GW   400        // GS fragment words per row (K=800)

// ---------------- scratch (device globals) ----------------
__device__ float g_Mf[MR];
__device__ float g_Pre[(size_t)MR*NPRE];
__device__ float g_Ap[MR*MST];
__device__ float g_biasFB[NPRE];
__device__ float g_biasE[HEH];
__device__ float g_biasTag[2*TAGL];
__device__ unsigned g_Xfh[(size_t)MR*XW];    // X split-bf16 fragments (hi)
__device__ unsigned g_Xfl[(size_t)MR*XW];    // (lo)
__device__ unsigned g_GSfh[(size_t)MR*GW];   // GS fragments (hi)
__device__ unsigned g_GSfl[(size_t)MR*GW];   // (lo)
__device__ unsigned g_Be[16*2*2048];
__device__ unsigned g_Bp[50*2*2048];
__device__ unsigned g_Bpre[56*2*7168];
__device__ unsigned g_Btag[50*2*2048];
__device__ unsigned g_Bw[16*25600];
// H exchange: [cluster 8][pp 2][split 2][b 16][word 200]
__device__ unsigned g_HXP[8*2*2*16*200];

#define CLUSTER_SYNC_() do { \
    asm volatile("barrier.cluster.arrive.aligned;" ::: "memory"); \
    asm volatile("barrier.cluster.wait.aligned;" ::: "memory"); \
} while (0)

// ---------------- helpers ----------------
__device__ __forceinline__ void splitpack(float x0, float x1, unsigned& hi, unsigned& lo) {
    __nv_bfloat16 b0 = __float2bfloat16_rn(x0);
    __nv_bfloat16 b1 = __float2bfloat16_rn(x1);
    float r0 = x0 - __bfloat162float(b0);
    float r1 = x1 - __bfloat162float(b1);
    __nv_bfloat16 c0 = __float2bfloat16_rn(r0);
    __nv_bfloat16 c1 = __float2bfloat16_rn(r1);
    hi = (unsigned)__bfloat16_as_ushort(b0) | ((unsigned)__bfloat16_as_ushort(b1) << 16);
    lo = (unsigned)__bfloat16_as_ushort(c0) | ((unsigned)__bfloat16_as_ushort(c1) << 16);
}

__device__ __forceinline__ void mma16816(float* d, unsigned a0, unsigned a1, unsigned a2,
                                         unsigned a3, unsigned b0, unsigned b1) {
    asm volatile(
        "mma.sync.aligned.m16n8k16.row.col.f32.bf16.bf16.f32 "
        "{%0,%1,%2,%3},{%4,%5,%6,%7},{%8,%9},{%0,%1,%2,%3};"
        : "+f"(d[0]), "+f"(d[1]), "+f"(d[2]), "+f"(d[3])
        : "r"(a0), "r"(a1), "r"(a2), "r"(a3), "r"(b0), "r"(b1));
}

__device__ __forceinline__ float tanhfast(float x) {
    float e = __expf(2.f * x);
    return 1.f - __fdividef(2.f, e + 1.f);
}

__device__ __forceinline__ int word_of_k(int k) {
    int kt = k >> 4, rem = k & 15;
    int s = (rem < 8) ? rem : (rem - 7);
    return kt * 8 + s;
}

// ---------------- setup (split: main / side) ----------------
#define S1 (56*2*7168)   // g_Bpre
#define S6 (NPRE)        // biasFB
#define TXW ((size_t)MR*XW)
#define TMAIN ((size_t)S1 + S6 + TXW + MR)

__global__ void k_setup_main(const float* __restrict__ Wih_f, const float* __restrict__ Wih_b,
                             const float* __restrict__ bih_f, const float* __restrict__ bhh_f,
                             const float* __restrict__ bih_b, const float* __restrict__ bhh_b,
                             const float* __restrict__ inp, const float* __restrict__ tag,
                             const float* __restrict__ sent, const int* __restrict__ mask) {
    size_t gidx = (size_t)blockIdx.x * blockDim.x + threadIdx.x;
    if (gidx < S1) {
        int idx = (int)gidx;
        int kt = idx / 14336, rest = idx % 14336;
        int split = rest / 7168, w = rest % 7168;
        int n = w >> 3, s = w & 7;
        int k = kt * 16 + 2 * (s >> 1) + 8 * (s & 1);
        float x0 = 0.f, x1 = 0.f;
        if (n < HG)          { x0 = Wih_f[(size_t)n * DL + k];        x1 = Wih_f[(size_t)n * DL + k + 1]; }
        else if (n < 2*HG)   { x0 = Wih_b[(size_t)(n-HG) * DL + k];   x1 = Wih_b[(size_t)(n-HG) * DL + k + 1]; }
        unsigned hi, lo; splitpack(x0, x1, hi, lo);
        g_Bpre[idx] = split ? lo : hi; return;
    }
    gidx -= S1;
    if (gidx < S6) {
        int idx = (int)gidx;
        float v = 0.f;
        if (idx < HG) v = bih_f[idx] + bhh_f[idx];
        else if (idx < 2*HG) v = bih_b[idx-HG] + bhh_b[idx-HG];
        g_biasFB[idx] = v; return;
    }
    gidx -= S6;
    if (gidx < TXW) {
        int p = (int)(gidx % XW);
        int r = (int)(gidx / XW);
        int k = (p >> 3) * 16 + 2 * ((p & 7) >> 1) + 8 * ((p & 7) & 1);
        int b = r / SL, s = r % SL;
        float x0, x1;
        if (s == 0) { x0 = sent[k]; x1 = sent[k + 1]; }
        else {
            int t = s - 1;
            if (k < 768) {
                const float* base = inp + (size_t)(b * TL + t) * 768;
                x0 = base[k]; x1 = base[k + 1];
            } else {
                const float* base = tag + (size_t)(b * TL + t) * TAGL;
                x0 = base[k - 768]; x1 = base[k - 767];
            }
        }
        unsigned hi, lo; splitpack(x0, x1, hi, lo);
        g_Xfh[gidx] = hi;
        g_Xfl[gidx] = lo;
        return;
    }
    gidx -= TXW;
    if (gidx < MR) {
        int b = (int)(gidx / SL), s = (int)(gidx % SL);
        g_Mf[gidx] = (s == 0) ? 1.0f : (float)mask[b * TL + s - 1];
    }
}

#define P2 (50*2*2048)   // g_Bp
#define P3 (16*2*2048)   // g_Be
#define P4 (50*2*2048)   // g_Btag
#define P5 (16*25600)    // g_Bw
#define P7 (HEH)
#define P8 (2*TAGL)
#define TSIDE (P2+P3+P4+P5+P7+P8)

__global__ void k_setup_side(const float* __restrict__ Wg2e, const float* __restrict__ Whh_e,
                             const float* __restrict__ Wht,  const float* __restrict__ Wdt,
                             const float* __restrict__ Whh_f, const float* __restrict__ Whh_b,
                             const float* __restrict__ bih_e, const float* __restrict__ bhh_e,
                             const float* __restrict__ bht,   const float* __restrict__ bdt) {
    int idx = blockIdx.x * blockDim.x + threadIdx.x;
    if (idx < P2) {
        int kt = idx >> 12, rest = idx & 4095;
        int split = rest >> 11, w = rest & 2047;
        int n = w >> 3, s = w & 7;
        int k = kt * 16 + 2 * (s >> 1) + 8 * (s & 1);
        float x0 = Wg2e[(size_t)n * (2*HG) + k];
        float x1 = Wg2e[(size_t)n * (2*HG) + k + 1];
        unsigned hi, lo; splitpack(x0, x1, hi, lo);
        g_Bp[idx] = split ? lo : hi; return;
    }
    idx -= P2;
    if (idx < P3) {
        int kt = idx >> 12, rest = idx & 4095;
        int split = rest >> 11, w = rest & 2047;
        int n = w >> 3, s = w & 7;
        int k = kt * 16 + 2 * (s >> 1) + 8 * (s & 1);
        float x0 = Whh_e[(size_t)n * HEH + k];
        float x1 = Whh_e[(size_t)n * HEH + k + 1];
        unsigned hi, lo; splitpack(x0, x1, hi, lo);
        g_Be[idx] = split ? lo : hi; return;
    }
    idx -= P3;
    if (idx < P4) {
        int kt = idx >> 12, rest = idx & 4095;
        int split = rest >> 11, w = rest & 2047;
        int n = w >> 3, s = w & 7;
        int k = kt * 16 + 2 * (s >> 1) + 8 * (s & 1);
        float x0, x1;
        if (n < TAGL) { x0 = Wht[(size_t)n * (2*HG) + k];        x1 = Wht[(size_t)n * (2*HG) + k + 1]; }
        else          { x0 = Wdt[(size_t)(n-TAGL) * (2*HG) + k]; x1 = Wdt[(size_t)(n-TAGL) * (2*HG) + k + 1]; }
        unsigned hi, lo; splitpack(x0, x1, hi, lo);
        g_Btag[idx] = split ? lo : hi; return;
    }
    idx -= P4;
    if (idx < P5) {
        int ctx = idx / 25600, rest = idx % 25600;
        int dir = ctx >> 3, jgx = ctx & 7;
        int kt = rest >> 10, r2 = rest & 1023;
        int split = r2 >> 9, r3 = r2 & 511;
        int n = r3 >> 3, s = r3 & 7;
        int k = kt * 16 + 2 * (s >> 1) + 8 * (s & 1);
        float x0 = 0.f, x1 = 0.f;
        if (n < 50) {
            const float* W = dir ? Whh_b : Whh_f;
            int j = jgx * 50 + n;
            x0 = W[(size_t)j * HG + k];
            x1 = W[(size_t)j * HG + k + 1];
        }
        unsigned hi, lo; splitpack(x0, x1, hi, lo);
        g_Bw[idx] = split ? lo : hi; return;
    }
    idx -= P5;
    if (idx < P7) { g_biasE[idx] = bih_e[idx] + bhh_e[idx]; return; }
    idx -= P7;
    if (idx < P8) g_biasTag[idx] = (idx < TAGL) ? bht[idx] : bdt[idx - TAGL];
}

// ---------------- split-bf16 HMMA GEMM, 128x128 tile (A pre-split fragments) ----------------
template <int ACT>
__global__ __launch_bounds__(256) void k_hgemm(const unsigned* __restrict__ Afh,
                                               const unsigned* __restrict__ Afl,
                                               const unsigned* __restrict__ Bfrag,
                                               const float* __restrict__ bias,
                                               float* __restrict__ C, float* __restrict__ C2,
                                               int N, int nkt, int Kw, int Nfrag) {
    __shared__ __align__(16) unsigned Ahs[2][1024];
    __shared__ __align__(16) unsigned Als[2][1024];
    __shared__ __align__(16) unsigned Bsm[2][2048];
    int m0 = blockIdx.y * 128, n0 = blockIdx.x * 128;
    int tid = threadIdx.x, wid = tid >> 5, lane = tid & 31;
    int mw = wid & 3, nh = wid >> 2;
    int r4 = lane >> 2, c4 = lane & 3;
    int Nw8 = Nfrag * 8;

    int arow = tid >> 1, sg = (tid & 1) * 4;
    const unsigned* Aph = Afh + (size_t)(m0 + arow) * Kw + sg;
    const unsigned* Apl = Afl + (size_t)(m0 + arow) * Kw + sg;

    uint4 afh, afl;
    uint2 bf[4];
    float acc[2][8][4];
#pragma unroll
    for (int mt = 0; mt < 2; mt++)
#pragma unroll
        for (int nt = 0; nt < 8; nt++)
#pragma unroll
            for (int q = 0; q < 4; q++) acc[mt][nt][q] = 0.f;

#define HLD(KT) do { \
        afh = *(const uint4*)(Aph + (size_t)(KT) * 8); \
        afl = *(const uint4*)(Apl + (size_t)(KT) * 8); \
        _Pragma("unroll") for (int i_ = 0; i_ < 4; i_++) { \
            int lw = 2 * (i_ * 256 + tid); \
            int sp = lw >> 10, wq = lw & 1023; \
            bf[i_] = *(const uint2*)(Bfrag + (size_t)(KT) * 2 * Nw8 + (size_t)sp * Nw8 + n0 * 8 + wq); } \
    } while (0)

#define HST(BUF) do { \
        *(uint4*)&Ahs[BUF][arow * 8 + sg] = afh; \
        *(uint4*)&Als[BUF][arow * 8 + sg] = afl; \
        _Pragma("unroll") for (int i_ = 0; i_ < 4; i_++) \
            *(uint2*)&Bsm[BUF][2 * (i_ * 256 + tid)] = bf[i_]; \
    } while (0)

    HLD(0);
    HST(0);
    __syncthreads();
    for (int kt = 0; kt < nkt; kt++) {
        int buf = kt & 1;
        if (kt + 1 < nkt) HLD(kt + 1);
        uint2 Uh[2], Vh[2], Ul[2], Vl[2];
#pragma unroll
        for (int mt = 0; mt < 2; mt++) {
            int rb = mw * 32 + mt * 16 + r4;
            Uh[mt] = *(uint2*)&Ahs[buf][rb * 8 + 2 * c4];
            Vh[mt] = *(uint2*)&Ahs[buf][(rb + 8) * 8 + 2 * c4];
            Ul[mt] = *(uint2*)&Als[buf][rb * 8 + 2 * c4];
            Vl[mt] = *(uint2*)&Als[buf][(rb + 8) * 8 + 2 * c4];
        }
#pragma unroll
        for (int nt = 0; nt < 8; nt++) {
            int n = nh * 64 + nt * 8 + r4;
            uint2 Bh = *(uint2*)&Bsm[buf][n * 8 + 2 * c4];
            uint2 Bl = *(uint2*)&Bsm[buf][1024 + n * 8 + 2 * c4];
#pragma unroll
            for (int mt = 0; mt < 2; mt++) {
                mma16816(acc[mt][nt], Uh[mt].x, Vh[mt].x, Uh[mt].y, Vh[mt].y, Bh.x, Bh.y);
                mma16816(acc[mt][nt], Uh[mt].x, Vh[mt].x, Uh[mt].y, Vh[mt].y, Bl.x, Bl.y);
                mma16816(acc[mt][nt], Ul[mt].x, Vl[mt].x, Ul[mt].y, Vl[mt].y, Bh.x, Bh.y);
            }
        }
        if (kt + 1 < nkt) HST(buf ^ 1);
        __syncthreads();
    }
#undef HLD
#undef HST

#pragma unroll
    for (int nt = 0; nt < 8; nt++) {
        int colL = nh * 64 + nt * 8 + 2 * c4;
        float b0 = bias[n0 + colL], b1 = bias[n0 + colL + 1];
#pragma unroll
        for (int mt = 0; mt < 2; mt++) {
            int r = m0 + mw * 32 + mt * 16 + r4;
            float v0 = acc[mt][nt][0] + b0, v1 = acc[mt][nt][1] + b1;
            float v2 = acc[mt][nt][2] + b0, v3 = acc[mt][nt][3] + b1;
            if (ACT == 2) {
                v0 = (v0 > 0.f) ? v0 : expm1f(v0);
                v1 = (v1 > 0.f) ? v1 : expm1f(v1);
                v2 = (v2 > 0.f) ? v2 : expm1f(v2);
                v3 = (v3 > 0.f) ? v3 : expm1f(v3);
                float* dst = (blockIdx.x == 0) ? C : C2;
                *(float2*)(dst + (size_t)r * TAGL + colL)       = make_float2(v0, v1);
                *(float2*)(dst + (size_t)(r + 8) * TAGL + colL) = make_float2(v2, v3);
            } else {
                *(float2*)(C + (size_t)r * N + n0 + colL)       = make_float2(v0, v1);
                *(float2*)(C + (size_t)(r + 8) * N + n0 + colL) = make_float2(v2, v3);
            }
        }
    }
}

// ---------------- HMMA bidirectional masked RNN (8 clusters of 8, 16 batches/CTA) ----------------
#define RAS 200
#define RNN_SMEM ((25600 + 2*16*RAS) * 4)

__global__ void __cluster_dims__(8, 1, 1) __launch_bounds__(256, 1) k_rnn() {
    extern __shared__ unsigned rsm[];
    unsigned* Bs = rsm;
    unsigned* Ah = rsm + 25600;
    unsigned* Al = Ah + 16 * RAS;

    int bx = blockIdx.x;
    int cl = bx >> 3, jg = bx & 7;
    int dir = cl >> 2, bg = cl & 3;
    int bbase = bg * 16;
    int tid = threadIdx.x, wid = tid >> 5, lane = tid & 31;
    int ng = wid;
    int r4 = lane >> 2, c4 = lane & 3;
    int rlo = r4, rhi = r4 + 8;

    {
        const uint2* bsrc = (const uint2*)(g_Bw + (size_t)(dir * 8 + jg) * 25600);
#pragma unroll
        for (int i = 0; i < 50; i++) {
            int idx = tid + i * 256;
            uint2 v = __ldcg(bsrc + idx);
            *(uint2*)&Bs[2 * idx] = v;
        }
    }
    {
        unsigned* hxp0 = g_HXP + (size_t)(cl * 2 + 0) * 6400;
        for (int idx = tid; idx < 800; idx += 256) {
            int split = idx / 400, rest = idx % 400;
            int b = rest / 25, w = rest % 25;
            int p = word_of_k(jg * 50 + 2 * w);
            __stcg(&hxp0[split * 3200 + b * 200 + p], 0u);
        }
    }
    __syncthreads();
    CLUSTER_SYNC_();

    int jl = ng * 8 + 2 * c4;
    int valid = (jl < 50);
    int wdp = word_of_k(jg * 50 + jl);
    int wdg = word_of_k(dir * 400 + jg * 50 + jl);   // word within 800-wide GS row
    float h[2][2];
#pragma unroll
    for (int a = 0; a < 2; a++) { h[a][0] = 0.f; h[a][1] = 0.f; }

    for (int tv = 0; tv < SL; tv++) {
        int t = dir ? (SL - 1 - tv) : tv;
        int pp = tv & 1;
        const uint2* src = (const uint2*)(g_HXP + (size_t)(cl * 2 + pp) * 6400);
        uint2 bp[13];
#pragma unroll
        for (int i = 0; i < 13; i++) {
            int idx = tid + i * 256;
            if (idx < 3200) {
                int split = idx / 1600, rest = idx % 1600;
                int b = rest / 100, wp = rest % 100;
                bp[i] = __ldcg(src + (size_t)split * 1600 + b * 100 + wp);
            }
        }
        float mv[2];
        mv[0] = g_Mf[(bbase + rlo) * SL + t];
        mv[1] = g_Mf[(bbase + rhi) * SL + t];
        float2 pre[2];
#pragma unroll
        for (int rq = 0; rq < 2; rq++) {
            int R = rq ? rhi : rlo;
            pre[rq] = *(const float2*)(g_Pre + (size_t)((bbase + R) * SL + t) * NPRE + dir * HG + jg * 50 + jl);
        }
#pragma unroll
        for (int i = 0; i < 13; i++) {
            int idx = tid + i * 256;
            if (idx < 3200) {
                int split = idx / 1600, rest = idx % 1600;
                int b = rest / 100, wp = rest % 100;
                unsigned* dst = split ? Al : Ah;
                *(uint2*)&dst[b * RAS + wp * 2] = bp[i];
            }
        }
        __syncthreads();

        // 6 independent accumulator chains (kt parity x 3 split terms)
        float fa[2][3][4];
#pragma unroll
        for (int px = 0; px < 2; px++)
#pragma unroll
            for (int tm = 0; tm < 3; tm++)
#pragma unroll
                for (int z = 0; z < 4; z++) fa[px][tm][z] = 0.f;
#pragma unroll
        for (int kt = 0; kt < 25; kt++) {
            int px = kt & 1;
            uint2 UA  = *(uint2*)&Ah[rlo * RAS + kt * 8 + 2 * c4];
            uint2 VA  = *(uint2*)&Ah[rhi * RAS + kt * 8 + 2 * c4];
            uint2 UAl = *(uint2*)&Al[rlo * RAS + kt * 8 + 2 * c4];
            uint2 VAl = *(uint2*)&Al[rhi * RAS + kt * 8 + 2 * c4];
            int n = ng * 8 + r4;
            uint2 Bh = *(uint2*)&Bs[(kt * 2) * 512 + n * 8 + 2 * c4];
            uint2 Bl = *(uint2*)&Bs[(kt * 2 + 1) * 512 + n * 8 + 2 * c4];
            mma16816(fa[px][0], UA.x, VA.x, UA.y, VA.y, Bh.x, Bh.y);
            mma16816(fa[px][1], UA.x, VA.x, UA.y, VA.y, Bl.x, Bl.y);
            mma16816(fa[px][2], UAl.x, VAl.x, UAl.y, VAl.y, Bh.x, Bh.y);
        }
        float acc[4];
#pragma unroll
        for (int z = 0; z < 4; z++)
            acc[z] = ((fa[0][0][z] + fa[0][1][z]) + (fa[0][2][z] + fa[1][0][z]))
                   + (fa[1][1][z] + fa[1][2][z]);
        __syncthreads();

        unsigned* dsth = g_HXP + (size_t)(cl * 2 + (pp ^ 1)) * 6400;
#pragma unroll
        for (int rq = 0; rq < 2; rq++) {
            int R = rq ? rhi : rlo;
            float mt = mv[rq], om = 1.f - mt;
            float u0 = mt * tanhfast(pre[rq].x + acc[rq * 2 + 0]) + om * h[rq][0];
            float u1 = mt * tanhfast(pre[rq].y + acc[rq * 2 + 1]) + om * h[rq][1];
            h[rq][0] = u0; h[rq][1] = u1;
            if (valid) {
                unsigned hi, lo; splitpack(u0, u1, hi, lo);
                __stcg(&dsth[R * 200 + wdp], hi);
                __stcg(&dsth[3200 + R * 200 + wdp], lo);
                size_t row = (size_t)((bbase + R) * SL + t);
                unsigned gh = (mt != 0.f) ? hi : 0u;
                unsigned gl = (mt != 0.f) ? lo : 0u;
                __stcg(&g_GSfh[row * GW + wdg], gh);
                __stcg(&g_GSfl[row * GW + wdg], gl);
            }
        }
        CLUSTER_SYNC_();
    }
}

// ---------------- tensor-core proj + 20-step estep loop (64 rows/CTA, 2 CTAs/SM) ----------------
#define AST 136
#define ELOOP_WORDS (2*8704 + 8192 + 1024 + 64 + 128)
#define ELOOP_SMEM  (ELOOP_WORDS * 4)

__global__ __launch_bounds__(256, 2) void k_eloop(const float* __restrict__ wie,
                                                  const float* __restrict__ wcls,
                                                  const float* __restrict__ bcls,
                                                  const float* __restrict__ bos,
                                                  const float* __restrict__ bg2e) {
    extern __shared__ unsigned sm_u[];
    unsigned* Ah  = sm_u;
    unsigned* Al  = sm_u + 8704;
    unsigned* Bsm = sm_u + 17408;
    float* sbe = (float*)(sm_u + 25600);
    float* swi = sbe + 256;
    float* swc = sbe + 512;
    float* sbg = sbe + 768;
    float* xs  = sbe + 1024;
    float* lp  = xs + 64;

    int tid = threadIdx.x;
    int wid = tid >> 5, lane = tid & 31;
    int mw = wid & 3, nh = wid >> 2;
    int r4 = lane >> 2, c4 = lane & 3;
    int m0 = blockIdx.x * 64;
    int rlo = mw * 16 + r4, rhi = rlo + 8;

    sbe[tid] = g_biasE[tid & 255];
    swi[tid] = wie[tid & 255];
    swc[tid] = wcls[tid & 255];
    sbg[tid] = bg2e[tid & 255];
    if (tid < 64) xs[tid] = bos[0];
    float bcl = bcls[0];

    float acc[16][4];
    uint2 bp[8];

#define LDCHUNK(gsrc) do { \
        const uint2* s_ = (const uint2*)(gsrc); \
        _Pragma("unroll") for (int i_ = 0; i_ < 8; i_++) bp[i_] = s_[i_ * 256 + tid]; \
    } while (0)
#define STCHUNK(BUF) do { \
        _Pragma("unroll") for (int i_ = 0; i_ < 8; i_++) \
            *(uint2*)&Bsm[(BUF) * 4096 + 2 * (i_ * 256 + tid)] = bp[i_]; \
    } while (0)

    // proj phase (A from pre-split GS fragments)
#pragma unroll
    for (int nt = 0; nt < 16; nt++)
#pragma unroll
        for (int q = 0; q < 4; q++) acc[nt][q] = 0.f;

    LDCHUNK(g_Bp);
    STCHUNK(0);
    __syncthreads();
    for (int kt = 0; kt < 50; kt++) {
        int buf = kt & 1;
        if (kt + 1 < 50) LDCHUNK(g_Bp + (size_t)(kt + 1) * 4096);
        uint2 UA  = *(const uint2*)&g_GSfh[(size_t)(m0 + rlo) * GW + kt * 8 + 2 * c4];
        uint2 VA  = *(const uint2*)&g_GSfh[(size_t)(m0 + rhi) * GW + kt * 8 + 2 * c4];
        uint2 UAl = *(const uint2*)&g_GSfl[(size_t)(m0 + rlo) * GW + kt * 8 + 2 * c4];
        uint2 VAl = *(const uint2*)&g_GSfl[(size_t)(m0 + rhi) * GW + kt * 8 + 2 * c4];
        const unsigned* bb = &Bsm[buf * 4096];
#pragma unroll
        for (int nt = 0; nt < 16; nt++) {
            int n = nh * 128 + nt * 8 + r4;
            uint2 Bh = *(const uint2*)&bb[n * 8 + 2 * c4];
            uint2 Bl = *(const uint2*)&bb[2048 + n * 8 + 2 * c4];
            mma16816(acc[nt], UA.x, VA.x, UA.y, VA.y, Bh.x, Bh.y);
            mma16816(acc[nt], UA.x, VA.x, UA.y, VA.y, Bl.x, Bl.y);
            mma16816(acc[nt], UAl.x, VAl.x, UAl.y, VAl.y, Bh.x, Bh.y);
        }
        if (kt + 1 < 50) STCHUNK(buf ^ 1);
        __syncthreads();
    }
#pragma unroll
    for (int ntp = 0; ntp < 8; ntp++) {
        int nt = ntp * 2;
        int nb0 = nh * 128 + nt * 8 + 2 * c4;
        int nb1 = nb0 + 8;
        float p00 = acc[nt][0] + sbg[nb0],   p01 = acc[nt][1] + sbg[nb0+1];
        float p10 = acc[nt+1][0] + sbg[nb1], p11 = acc[nt+1][1] + sbg[nb1+1];
        float q00 = acc[nt][2] + sbg[nb0],   q01 = acc[nt][3] + sbg[nb0+1];
        float q10 = acc[nt+1][2] + sbg[nb1], q11 = acc[nt+1][3] + sbg[nb1+1];
        unsigned he0, le0, he1, le1;
        int wlo = rlo * AST + (nh * 8 + ntp) * 8 + 2 * c4;
        int whi = rhi * AST + (nh * 8 + ntp) * 8 + 2 * c4;
        splitpack(p00, p01, he0, le0); splitpack(p10, p11, he1, le1);
        *(uint2*)&Ah[wlo] = make_uint2(he0, he1);
        *(uint2*)&Al[wlo] = make_uint2(le0, le1);
        splitpack(q00, q01, he0, le0); splitpack(q10, q11, he1, le1);
        *(uint2*)&Ah[whi] = make_uint2(he0, he1);
        *(uint2*)&Al[whi] = make_uint2(le0, le1);
    }
    __syncthreads();

    // 20 estep iterations
    for (int st = 0; st < MST; st++) {
#pragma unroll
        for (int nt = 0; nt < 16; nt++)
#pragma unroll
            for (int q = 0; q < 4; q++) acc[nt][q] = 0.f;

        LDCHUNK(g_Be);
        STCHUNK(0);
        __syncthreads();
        for (int kt = 0; kt < 16; kt++) {
            int buf = kt & 1;
            if (kt + 1 < 16) LDCHUNK(g_Be + (size_t)(kt + 1) * 4096);
            uint2 UA  = *(uint2*)&Ah[rlo * AST + kt * 8 + 2 * c4];
            uint2 VA  = *(uint2*)&Ah[rhi * AST + kt * 8 + 2 * c4];
            uint2 UAl = *(uint2*)&Al[rlo * AST + kt * 8 + 2 * c4];
            uint2 VAl = *(uint2*)&Al[rhi * AST + kt * 8 + 2 * c4];
            const unsigned* bb = &Bsm[buf * 4096];
#pragma unroll
            for (int nt = 0; nt < 16; nt++) {
                int n = nh * 128 + nt * 8 + r4;
                uint2 Bh = *(const uint2*)&bb[n * 8 + 2 * c4];
                uint2 Bl = *(const uint2*)&bb[2048 + n * 8 + 2 * c4];
                mma16816(acc[nt], UA.x, VA.x, UA.y, VA.y, Bh.x, Bh.y);
                mma16816(acc[nt], UA.x, VA.x, UA.y, VA.y, Bl.x, Bl.y);
                mma16816(acc[nt], UAl.x, VAl.x, UAl.y, VAl.y, Bh.x, Bh.y);
            }
            if (kt + 1 < 16) STCHUNK(buf ^ 1);
            __syncthreads();
        }

        float xel = xs[rlo], xeh = xs[rhi];
        float pl = 0.f, ph = 0.f;
#pragma unroll
        for (int ntp = 0; ntp < 8; ntp++) {
            int nt = ntp * 2;
            int nb0 = nh * 128 + nt * 8 + 2 * c4;
            int nb1 = nb0 + 8;
            float b00 = sbe[nb0], b01 = sbe[nb0+1], b10 = sbe[nb1], b11 = sbe[nb1+1];
            float w00 = swi[nb0], w01 = swi[nb0+1], w10 = swi[nb1], w11 = swi[nb1+1];
            float h00 = tanhfast(acc[nt][0]   + b00 + xel * w00);
            float h01 = tanhfast(acc[nt][1]   + b01 + xel * w01);
            float h10 = tanhfast(acc[nt+1][0] + b10 + xel * w10);
            float h11 = tanhfast(acc[nt+1][1] + b11 + xel * w11);
            float g00 = tanhfast(acc[nt][2]   + b00 + xeh * w00);
            float g01 = tanhfast(acc[nt][3]   + b01 + xeh * w01);
            float g10 = tanhfast(acc[nt+1][2] + b10 + xeh * w10);
            float g11 = tanhfast(acc[nt+1][3] + b11 + xeh * w11);
            float c00 = swc[nb0], c01 = swc[nb0+1], c10 = swc[nb1], c11 = swc[nb1+1];
            pl += h00 * c00 + h01 * c01 + h10 * c10 + h11 * c11;
            ph += g00 * c00 + g01 * c01 + g10 * c10 + g11 * c11;
            unsigned he0, le0, he1, le1;
            int wlo = rlo * AST + (nh * 8 + ntp) * 8 + 2 * c4;
            int whi = rhi * AST + (nh * 8 + ntp) * 8 + 2 * c4;
            splitpack(h00, h01, he0, le0); splitpack(h10, h11, he1, le1);
            *(uint2*)&Ah[wlo] = make_uint2(he0, he1);
            *(uint2*)&Al[wlo] = make_uint2(le0, le1);
            splitpack(g00, g01, he0, le0); splitpack(g10, g11, he1, le1);
            *(uint2*)&Ah[whi] = make_uint2(he0, he1);
            *(uint2*)&Al[whi] = make_uint2(le0, le1);
        }
        pl += __shfl_xor_sync(0xffffffffu, pl, 1);
        pl += __shfl_xor_sync(0xffffffffu, pl, 2);
        ph += __shfl_xor_sync(0xffffffffu, ph, 1);
        ph += __shfl_xor_sync(0xffffffffu, ph, 2);
        if (c4 == 0) {
            lp[nh * 64 + rlo] = pl;
            lp[nh * 64 + rhi] = ph;
        }
        __syncthreads();
        if (tid < 64) {
            float logit = lp[tid] + lp[64 + tid] + bcl;
            g_Ap[(size_t)(m0 + tid) * MST + st] = logit;
            xs[tid] = logit;
        }
        __syncthreads();
    }
#undef LDCHUNK
#undef STCHUNK
}

// ---------------- arc: zero-fill (early, overlapped) + band fill (tiny, at end) ----------------
__global__ void k_arc_zero(float4* __restrict__ out4) {
    size_t idx = (size_t)blockIdx.x * blockDim.x + threadIdx.x;
    size_t total = (size_t)BB * SL * SL / 4;
    if (idx < total) out4[idx] = make_float4(0.f, 0.f, 0.f, 0.f);
}

__global__ void k_arc_band(float* __restrict__ out) {
    int idx = blockIdx.x * blockDim.x + threadIdx.x;
    if (idx >= MR * MST) return;
    int m = idx / MST, k = idx % MST;
    int b = m / SL, r = m % SL;
    int lim = (r < MST) ? r : MST;
    if (k < lim) {
        int start = r - MST; if (start < 0) start = 0;
        out[(size_t)b * SL * SL + (size_t)r * SL + start + k] = g_Ap[(size_t)m * MST + k];
    }
}

// ---------------- host launcher ----------------
extern "C" void kernel_launch(void* const* d_in, const int* in_sizes, int n_in,
                              void* d_out, int out_size) {
    const float* input  = (const float*)d_in[0];
    const float* tagemb = (const float*)d_in[1];
    const int*   mask   = (const int*)d_in[2];
    const float* sent   = (const float*)d_in[3];
    const float* Wih_f  = (const float*)d_in[4];
    const float* Whh_f  = (const float*)d_in[5];
    const float* bih_f  = (const float*)d_in[6];
    const float* bhh_f  = (const float*)d_in[7];
    const float* Wih_b  = (const float*)d_in[8];
    const float* Whh_b  = (const float*)d_in[9];
    const float* bih_b  = (const float*)d_in[10];
    const float* bhh_b  = (const float*)d_in[11];
    const float* Wg2e   = (const float*)d_in[12];
    const float* bg2e   = (const float*)d_in[13];
    const float* Wih_e  = (const float*)d_in[14];
    const float* Whh_e  = (const float*)d_in[15];
    const float* bih_e  = (const float*)d_in[16];
    const float* bhh_e  = (const float*)d_in[17];
    const float* Wcls   = (const float*)d_in[18];
    const float* bcls   = (const float*)d_in[19];
    const float* bos    = (const float*)d_in[20];
    const float* Wht    = (const float*)d_in[21];
    const float* bht    = (const float*)d_in[22];
    const float* Wdt    = (const float*)d_in[23];
    const float* bdt    = (const float*)d_in[24];
    float* out = (float*)d_out;

    float *pPre, *pbFB, *pbTag;
    unsigned *pBpre, *pBtag, *pXfh, *pXfl, *pGSfh, *pGSfl;
    cudaGetSymbolAddress((void**)&pPre, g_Pre);
    cudaGetSymbolAddress((void**)&pbFB, g_biasFB);
    cudaGetSymbolAddress((void**)&pbTag, g_biasTag);
    cudaGetSymbolAddress((void**)&pBpre, g_Bpre);
    cudaGetSymbolAddress((void**)&pBtag, g_Btag);
    cudaGetSymbolAddress((void**)&pXfh, g_Xfh);
    cudaGetSymbolAddress((void**)&pXfl, g_Xfl);
    cudaGetSymbolAddress((void**)&pGSfh, g_GSfh);
    cudaGetSymbolAddress((void**)&pGSfl, g_GSfl);

    static cudaStream_t s2 = nullptr;
    static cudaEvent_t evRoot = nullptr, evSide = nullptr, evGS = nullptr, evTags = nullptr;
    static int inited = 0;
    if (!inited) {
        cudaFuncSetAttribute(k_eloop, cudaFuncAttributeMaxDynamicSharedMemorySize, ELOOP_SMEM);
        cudaFuncSetAttribute(k_rnn, cudaFuncAttributeMaxDynamicSharedMemorySize, RNN_SMEM);
        cudaStreamCreateWithFlags(&s2, cudaStreamNonBlocking);
        cudaEventCreateWithFlags(&evRoot, cudaEventDisableTiming);
        cudaEventCreateWithFlags(&evSide, cudaEventDisableTiming);
        cudaEventCreateWithFlags(&evGS, cudaEventDisableTiming);
        cudaEventCreateWithFlags(&evTags, cudaEventDisableTiming);
        inited = 1;
    }

    // fork side stream from origin
    cudaEventRecord(evRoot, 0);
    cudaStreamWaitEvent(s2, evRoot, 0);
    k_setup_side<<<(TSIDE + 255) / 256, 256, 0, s2>>>(Wg2e, Whh_e, Wht, Wdt, Whh_f, Whh_b,
                                                      bih_e, bhh_e, bht, bdt);
    {
        size_t tot4 = (size_t)BB * SL * SL / 4;
        k_arc_zero<<<(unsigned)((tot4 + 255) / 256), 256, 0, s2>>>(
            (float4*)(out + 2 * (size_t)MR * TAGL));
    }
    cudaEventRecord(evSide, s2);

    // main: X fragments + Pre weights
    k_setup_main<<<(unsigned)((TMAIN + 255) / 256), 256>>>(Wih_f, Wih_b, bih_f, bhh_f,
                                                           bih_b, bhh_b, input, tagemb,
                                                           sent, mask);
    // Pre GEMM (A pre-split fragments)
    {
        dim3 grid(NPRE / 128, MR / 128);
        k_hgemm<0><<<grid, 256>>>(pXfh, pXfl, pBpre, pbFB, pPre, nullptr,
                                  NPRE, DL / 16, XW, NPRE);
    }
    // join side, then recurrence
    cudaStreamWaitEvent(0, evSide, 0);
    k_rnn<<<64, 256, RNN_SMEM>>>();
    // fork tags (depends only on GS fragments)
    cudaEventRecord(evGS, 0);
    cudaStreamWaitEvent(s2, evGS, 0);
    {
        dim3 grid(2, MR / 128);
        k_hgemm<2><<<grid, 256, 0, s2>>>(pGSfh, pGSfl, pBtag, pbTag, out,
                                         out + (size_t)MR * TAGL,
                                         2 * TAGL, (2 * HG) / 16, GW, 2 * TAGL);
    }
    cudaEventRecord(evTags, s2);
    // proj + estep chain
    k_eloop<<<MR / 64, 256, ELOOP_SMEM>>>(Wih_e, Wcls, bcls, bos, bg2e);
    // arc band fill
    k_arc_band<<<(MR * MST + 255) / 256, 256>>>(out + 2 * (size_t)MR * TAGL);
    // join
    cudaStreamWaitEvent(0, evTags, 0);
    (void)in_sizes; (void)n_in; (void)out_size;
}